// round 9
// baseline (speedup 1.0000x reference)
#include <cuda_runtime.h>
#include <cuda_bf16.h>
#include <mma.h>
#include <math.h>
#include <cstdint>

using namespace nvcuda;

#define Bb 4
#define Ss 512
#define Hh 768
#define Dd 24
#define Mm 96
#define OH 768
#define H3 2304
#define NROWS (Bb*Ss)   // 2048

typedef unsigned long long ull;

// ---- scratch ----
__device__ __align__(16) float g_Zj[NROWS*Dd];
__device__ __align__(16) float g_Zi[NROWS*Dd];
__device__ __align__(16) float g_Aj[NROWS*Mm];
__device__ __align__(16) float g_ctx[(long)NROWS*Hh];
// precomputed pair weight matrix W' = [Wc | Wd | Wb | 0]  (96 x 88, hi/lo)
__device__ __align__(16) __nv_bfloat16 g_Wph[96*88];
__device__ __align__(16) __nv_bfloat16 g_Wpl[96*88];
// bf16 hi/lo operands for tensor-core GEMMs
__device__ __align__(16) __nv_bfloat16 g_pbh[(long)Bb*Ss*Ss];
__device__ __align__(16) __nv_bfloat16 g_pbl[(long)Bb*Ss*Ss];
__device__ __align__(16) __nv_bfloat16 g_hih[(long)NROWS*Hh];
__device__ __align__(16) __nv_bfloat16 g_hil[(long)NROWS*Hh];
__device__ __align__(16) __nv_bfloat16 g_m1h[(long)NROWS*H3];
__device__ __align__(16) __nv_bfloat16 g_m1l[(long)NROWS*H3];
__device__ __align__(16) __nv_bfloat16 g_w1h[(long)OH*H3];
__device__ __align__(16) __nv_bfloat16 g_w1l[(long)OH*H3];
__device__ __align__(16) __nv_bfloat16 g_hidh[(long)NROWS*OH];
__device__ __align__(16) __nv_bfloat16 g_hidl[(long)NROWS*OH];
__device__ __align__(16) __nv_bfloat16 g_w2h[(long)Hh*OH];
__device__ __align__(16) __nv_bfloat16 g_w2l[(long)Hh*OH];

// bf16 hi/lo split
__device__ __forceinline__ void bsplit(float v, __nv_bfloat16& h, __nv_bfloat16& l){
    h = __float2bfloat16(v);
    l = __float2bfloat16(v - __bfloat162float(h));
}
__device__ __forceinline__ unsigned packhl(float v0, float v1, unsigned& lo){
    __nv_bfloat16 h0,l0,h1,l1;
    bsplit(v0, h0, l0); bsplit(v1, h1, l1);
    __nv_bfloat162 ph; ph.x = h0; ph.y = h1;
    __nv_bfloat162 pl; pl.x = l0; pl.y = l1;
    lo = *(unsigned*)&pl;
    return *(unsigned*)&ph;
}

// ============================================================
// K0: precompute W' = [Wc | Wd | Wb | 0] (96 x 88) hi/lo
// ============================================================
__global__ __launch_bounds__(256) void wsplit_pair(const float* __restrict__ sw1)
{
    int i = blockIdx.x*256 + threadIdx.x;
    if (i >= 96*88) return;
    int m = i / 88, k = i % 88;
    float wv = 0.f;
    if (k < 24)      wv = sw1[m*96 + 48 + k];
    else if (k < 48) wv = sw1[m*96 + 72 + (k-24)];
    else if (k < 72) wv = sw1[m*96 + 24 + (k-48)];
    __nv_bfloat16 h, l; bsplit(wv, h, l);
    g_Wph[i] = h; g_Wpl[i] = l;
}

// ============================================================
// K1: projections + rank-1 term Aj = Wa @ zj
// ============================================================
__global__ __launch_bounds__(256) void proj_kernel(
    const float* __restrict__ Hj, const float* __restrict__ Hi,
    const float* __restrict__ pjw, const float* __restrict__ piw,
    const float* __restrict__ sw1)
{
    int r = blockIdx.x;
    __shared__ float shj[Hh], shi[Hh], szj[Dd];
    int tid = threadIdx.x;
    for (int i = tid; i < Hh; i += 256){
        shj[i] = Hj[(long)r*Hh + i];
        shi[i] = Hi[(long)r*Hh + i];
    }
    __syncthreads();
    int o = tid >> 3, g = tid & 7;
    if (o < Dd){
        float pj = 0.f, pi = 0.f;
        for (int h = g; h < Hh; h += 8){
            pj += shj[h] * pjw[o*Hh + h];
            pi += shi[h] * piw[o*Hh + h];
        }
        #pragma unroll
        for (int d = 4; d > 0; d >>= 1){
            pj += __shfl_down_sync(0xffffffffu, pj, d, 8);
            pi += __shfl_down_sync(0xffffffffu, pi, d, 8);
        }
        if (g == 0){
            szj[o] = pj;
            g_Zj[r*Dd + o] = pj; g_Zi[r*Dd + o] = pi;
        }
    }
    __syncthreads();
    if (tid < Mm){
        float a = 0.f;
        #pragma unroll
        for (int d = 0; d < Dd; d++)
            a += sw1[tid*96 + d] * szj[d];
        g_Aj[r*Mm + tid] = a;
    }
}

// ============================================================
// K2: pair logits, v4: 512 threads / 16 warps, m-split warps
//  warp = (ttile 0..7, mhalf 0..1): 16 rows x 48 cols, acc[3]
// ============================================================
#define POFF_WH   0
#define POFF_WL   16896
#define POFF_F    33792                   // Fh [128][88] = 22528
#define POFF_FL   56320                   // Fl -> 78848
#define POFF_SCR  POFF_F                  // alias: 16 warps x 16x36 f = 36864
#define POFF_SLOG 78848                   // 2 x 512 floats = 4096
#define POFF_SZJ  82944
#define POFF_SSC  83072
#define POFF_SW2  83456
#define POFF_SRED 83840
#define PAIR_SMEM 83968

__global__ __launch_bounds__(512, 2) void pair_wmma(
    const float* __restrict__ sb1,
    const float* __restrict__ sw2v, const float* __restrict__ sb2,
    const float* __restrict__ mask)
{
    extern __shared__ char ps[];
    __nv_bfloat16* Wh = (__nv_bfloat16*)(ps + POFF_WH);
    __nv_bfloat16* Wl = (__nv_bfloat16*)(ps + POFF_WL);
    __nv_bfloat16* Fh = (__nv_bfloat16*)(ps + POFF_F);
    __nv_bfloat16* Fl = (__nv_bfloat16*)(ps + POFF_FL);
    float* scr  = (float*)(ps + POFF_SCR);
    float* slog = (float*)(ps + POFF_SLOG);
    float* szj  = (float*)(ps + POFF_SZJ);
    float* ssc  = (float*)(ps + POFF_SSC);
    float* sw2s = (float*)(ps + POFF_SW2);
    float* sred = (float*)(ps + POFF_SRED);

    int r = blockIdx.x, b = r >> 9;
    int tid = threadIdx.x, wid = tid >> 5, lane = tid & 31;

    // load precomputed W'
    for (int i = tid; i < 1056; i += 512){
        ((uint4*)Wh)[i] = ((const uint4*)g_Wph)[i];
        ((uint4*)Wl)[i] = ((const uint4*)g_Wpl)[i];
    }
    if (tid < Dd) szj[tid] = g_Zj[r*Dd + tid];
    if (tid < Mm){
        ssc[tid]  = g_Aj[r*Mm + tid] + sb1[tid];
        sw2s[tid] = sw2v[tid];
    }
    __syncthreads();

    int brow = tid & 127;        // F row
    int bqq  = tid >> 7;         // column quarter: 0..3
    int ttile = wid & 7;         // 16-row tile
    int mhalf = wid >> 3;        // 48-col half
    int mb = mhalf * 48;

    #pragma unroll 1
    for (int chunk = 0; chunk < 4; chunk++){
        // ---- build F (each thread: 24-col segment of one row) ----
        if (bqq < 3){
            int t = chunk*128 + brow;
            const float4* zi4 = (const float4*)&g_Zi[(long)(b*Ss + t)*Dd];
            float za[24];
            #pragma unroll
            for (int q = 0; q < 6; q++){
                float4 v4 = __ldg(&zi4[q]);
                za[q*4+0]=v4.x; za[q*4+1]=v4.y; za[q*4+2]=v4.z; za[q*4+3]=v4.w;
            }
            float vals[24];
            if (bqq == 0){
                #pragma unroll
                for (int i = 0; i < 24; i++) vals[i] = szj[i]*za[i];
            } else if (bqq == 1){
                #pragma unroll
                for (int i = 0; i < 24; i++) vals[i] = fabsf(szj[i]-za[i]);
            } else {
                #pragma unroll
                for (int i = 0; i < 24; i++) vals[i] = za[i];
            }
            uint2* dh = (uint2*)&Fh[brow*88 + bqq*24];
            uint2* dl = (uint2*)&Fl[brow*88 + bqq*24];
            #pragma unroll
            for (int q = 0; q < 6; q++){
                unsigned h0, h1, l0, l1;
                h0 = packhl(vals[q*4+0], vals[q*4+1], l0);
                h1 = packhl(vals[q*4+2], vals[q*4+3], l1);
                dh[q] = make_uint2(h0, h1);
                dl[q] = make_uint2(l0, l1);
            }
        } else {
            uint2* dh = (uint2*)&Fh[brow*88 + 72];
            uint2* dl = (uint2*)&Fl[brow*88 + 72];
            uint2 z2 = make_uint2(0u, 0u);
            #pragma unroll
            for (int q = 0; q < 4; q++){ dh[q] = z2; dl[q] = z2; }
        }
        __syncthreads();

        // ---- GEMM: warp = (ttile, mhalf): 16 rows x 48 cols ----
        wmma::fragment<wmma::accumulator,16,16,16,float> acc[3];
        #pragma unroll
        for (int j = 0; j < 3; j++) wmma::fill_fragment(acc[j], 0.f);

        #pragma unroll
        for (int k = 0; k < 5; k++){
            wmma::fragment<wmma::matrix_a,16,16,16,__nv_bfloat16,wmma::row_major> ah, al;
            wmma::load_matrix_sync(ah, &Fh[(ttile*16)*88 + k*16], 88);
            wmma::load_matrix_sync(al, &Fl[(ttile*16)*88 + k*16], 88);
            #pragma unroll
            for (int j = 0; j < 3; j++){
                wmma::fragment<wmma::matrix_b,16,16,16,__nv_bfloat16,wmma::col_major> bh, bl;
                wmma::load_matrix_sync(bh, &Wh[(mb + j*16)*88 + k*16], 88);
                wmma::load_matrix_sync(bl, &Wl[(mb + j*16)*88 + k*16], 88);
                wmma::mma_sync(acc[j], ah, bh, acc[j]);
                wmma::mma_sync(acc[j], ah, bl, acc[j]);
                wmma::mma_sync(acc[j], al, bh, acc[j]);
            }
        }
        __syncthreads();   // F reads done before scr (alias) writes

        // ---- reduce 48 cols to partial logits ----
        float* scrw = scr + wid*576;   // 16 x 36 floats
        int row = lane >> 1, sub = lane & 1;
        float lsum = 0.f;
        // pass A: j0, j1 (32 cols)
        wmma::store_matrix_sync(scrw,      acc[0], 36, wmma::mem_row_major);
        wmma::store_matrix_sync(scrw + 16, acc[1], 36, wmma::mem_row_major);
        __syncwarp();
        {
            const float4* sr4 = (const float4*)(scrw + row*36 + sub*16);
            const float4* sc4 = (const float4*)(ssc + mb + sub*16);
            const float4* sw4 = (const float4*)(sw2s + mb + sub*16);
            #pragma unroll
            for (int q = 0; q < 4; q++){
                float4 hv = sr4[q];
                float4 cv = sc4[q];
                float4 wv = sw4[q];
                lsum += wv.x * fmaxf(hv.x + cv.x, 0.f);
                lsum += wv.y * fmaxf(hv.y + cv.y, 0.f);
                lsum += wv.z * fmaxf(hv.z + cv.z, 0.f);
                lsum += wv.w * fmaxf(hv.w + cv.w, 0.f);
            }
        }
        __syncwarp();
        // pass B: j2 (16 cols)
        wmma::store_matrix_sync(scrw, acc[2], 36, wmma::mem_row_major);
        __syncwarp();
        {
            const float4* sr4 = (const float4*)(scrw + row*36 + sub*8);
            const float4* sc4 = (const float4*)(ssc + mb + 32 + sub*8);
            const float4* sw4 = (const float4*)(sw2s + mb + 32 + sub*8);
            #pragma unroll
            for (int q = 0; q < 2; q++){
                float4 hv = sr4[q];
                float4 cv = sc4[q];
                float4 wv = sw4[q];
                lsum += wv.x * fmaxf(hv.x + cv.x, 0.f);
                lsum += wv.y * fmaxf(hv.y + cv.y, 0.f);
                lsum += wv.z * fmaxf(hv.z + cv.z, 0.f);
                lsum += wv.w * fmaxf(hv.w + cv.w, 0.f);
            }
        }
        lsum += __shfl_xor_sync(0xffffffffu, lsum, 1);
        if (sub == 0) slog[mhalf*512 + chunk*128 + ttile*16 + row] = lsum;
        __syncthreads();
    }

    // ---- masked softmax over 512 logits (one t per thread) ----
    int t = tid;
    float lt = slog[t] + slog[512 + t] + sb2[0]
             + (1.f - mask[b*Ss + t]) * (-3.402823466e38f);

    float mx = lt;
    #pragma unroll
    for (int d = 16; d > 0; d >>= 1)
        mx = fmaxf(mx, __shfl_xor_sync(0xffffffffu, mx, d));
    if (lane == 0) sred[wid] = mx;
    __syncthreads();
    float bmax = sred[0];
    #pragma unroll
    for (int i = 1; i < 16; i++) bmax = fmaxf(bmax, sred[i]);

    float e0 = expf(lt - bmax);
    float sm = e0;
    #pragma unroll
    for (int d = 16; d > 0; d >>= 1)
        sm += __shfl_xor_sync(0xffffffffu, sm, d);
    __syncthreads();
    if (lane == 0) sred[wid] = sm;
    __syncthreads();
    float tot = 0.f;
    #pragma unroll
    for (int i = 0; i < 16; i++) tot += sred[i];
    float inv = 1.f / tot;

    __nv_bfloat16 h, l;
    bsplit(e0 * inv, h, l);
    g_pbh[(long)r*Ss + t] = h; g_pbl[(long)r*Ss + t] = l;
}

// ============================================================
// K3: fp32 -> bf16 hi/lo split (vectorized)
// ============================================================
__global__ __launch_bounds__(256) void conv_split(
    const float* __restrict__ x, __nv_bfloat16* __restrict__ hi,
    __nv_bfloat16* __restrict__ lo, int n4)
{
    int i = blockIdx.x*256 + threadIdx.x;
    if (i >= n4) return;
    float4 v = ((const float4*)x)[i];
    __nv_bfloat16 h0,h1,h2,h3,l0,l1,l2,l3;
    bsplit(v.x,h0,l0); bsplit(v.y,h1,l1); bsplit(v.z,h2,l2); bsplit(v.w,h3,l3);
    __nv_bfloat162 p0, p1;
    p0.x=h0; p0.y=h1; p1.x=h2; p1.y=h3;
    ((__nv_bfloat162*)hi)[2*i]   = p0;
    ((__nv_bfloat162*)hi)[2*i+1] = p1;
    p0.x=l0; p0.y=l1; p1.x=l2; p1.y=l3;
    ((__nv_bfloat162*)lo)[2*i]   = p0;
    ((__nv_bfloat162*)lo)[2*i+1] = p1;
}

// ============================================================
// K4: msg_in = [ctx | Hj | ctx*Hj] -> bf16 hi/lo
// ============================================================
__device__ __forceinline__ void store4(__nv_bfloat16* hp, __nv_bfloat16* lp,
                                       float a, float b, float c, float d)
{
    __nv_bfloat16 h0,h1,h2,h3,l0,l1,l2,l3;
    bsplit(a,h0,l0); bsplit(b,h1,l1); bsplit(c,h2,l2); bsplit(d,h3,l3);
    __nv_bfloat162 p0, p1;
    p0.x=h0; p0.y=h1; p1.x=h2; p1.y=h3;
    ((__nv_bfloat162*)hp)[0] = p0; ((__nv_bfloat162*)hp)[1] = p1;
    p0.x=l0; p0.y=l1; p1.x=l2; p1.y=l3;
    ((__nv_bfloat162*)lp)[0] = p0; ((__nv_bfloat162*)lp)[1] = p1;
}
__global__ __launch_bounds__(256) void msgin_conv(const float* __restrict__ Hj)
{
    int i = blockIdx.x*256 + threadIdx.x;
    if (i >= NROWS*(Hh/4)) return;
    int r = i / (Hh/4);
    int c = (i % (Hh/4)) * 4;
    float4 cv = *(const float4*)&g_ctx[(long)r*Hh + c];
    float4 hv = *(const float4*)&Hj[(long)r*Hh + c];
    long base = (long)r*H3 + c;
    store4(&g_m1h[base],      &g_m1l[base],      cv.x, cv.y, cv.z, cv.w);
    store4(&g_m1h[base+Hh],   &g_m1l[base+Hh],   hv.x, hv.y, hv.z, hv.w);
    store4(&g_m1h[base+2*Hh], &g_m1l[base+2*Hh],
           cv.x*hv.x, cv.y*hv.y, cv.z*hv.z, cv.w*hv.w);
}

// ============================================================
// K5: WMMA GEMM  C[M,N] = A[M,K] @ opB  (bf16 hi/lo, 3-pass)
// ============================================================
template<bool TRANSB, int EPI>
__global__ __launch_bounds__(256) void gemm_wmma(
    const __nv_bfloat16* __restrict__ Ah, const __nv_bfloat16* __restrict__ Al,
    const __nv_bfloat16* __restrict__ Bh, const __nv_bfloat16* __restrict__ Bl,
    float* __restrict__ Cout, int N, int K, int ldA, int ldB,
    long strideA, long strideB, long strideC,
    const float* __restrict__ bias, const float* __restrict__ alpha_p)
{
    __shared__ __nv_bfloat16 As[2][128][40];
    __shared__ __nv_bfloat16 Bs[2][5120];   // NT: [n][40] ; NN: [k][136]

    int tid = threadIdx.x;
    int wid = tid >> 5, lane = tid & 31;
    int wr = wid & 3, wc = wid >> 2;        // 4x2 warps, warp tile 32x64
    long row0 = (long)blockIdx.y * 128;
    long col0 = (long)blockIdx.x * 128;

    const __nv_bfloat16* APh = Ah + (long)blockIdx.z * strideA;
    const __nv_bfloat16* APl = Al + (long)blockIdx.z * strideA;
    const __nv_bfloat16* BPh = Bh + (long)blockIdx.z * strideB;
    const __nv_bfloat16* BPl = Bl + (long)blockIdx.z * strideB;
    float* Cb = Cout ? (Cout + (long)blockIdx.z * strideC) : nullptr;

    wmma::fragment<wmma::accumulator,16,16,16,float> acc[2][4];
    #pragma unroll
    for (int i = 0; i < 2; i++)
        #pragma unroll
        for (int j = 0; j < 4; j++) wmma::fill_fragment(acc[i][j], 0.f);

    #pragma unroll 1
    for (int kc = 0; kc < K; kc += 32){
        #pragma unroll
        for (int t = tid; t < 512; t += 256){
            int r = t >> 2, seg = t & 3;
            long off = (row0 + r)*(long)ldA + kc + seg*8;
            *(float4*)&As[0][r][seg*8] = *(const float4*)(APh + off);
            *(float4*)&As[1][r][seg*8] = *(const float4*)(APl + off);
        }
        if (TRANSB){
            #pragma unroll
            for (int t = tid; t < 512; t += 256){
                int r = t >> 2, seg = t & 3;
                long off = (col0 + r)*(long)ldB + kc + seg*8;
                *(float4*)&Bs[0][r*40 + seg*8] = *(const float4*)(BPh + off);
                *(float4*)&Bs[1][r*40 + seg*8] = *(const float4*)(BPl + off);
            }
        } else {
            #pragma unroll
            for (int t = tid; t < 512; t += 256){
                int r = t >> 4, seg = t & 15;
                long off = (long)(kc + r)*ldB + col0 + seg*8;
                *(float4*)&Bs[0][r*136 + seg*8] = *(const float4*)(BPh + off);
                *(float4*)&Bs[1][r*136 + seg*8] = *(const float4*)(BPl + off);
            }
        }
        __syncthreads();

        #pragma unroll
        for (int ks = 0; ks < 2; ks++){
            wmma::fragment<wmma::matrix_a,16,16,16,__nv_bfloat16,wmma::row_major> afh[2], afl[2];
            #pragma unroll
            for (int i = 0; i < 2; i++){
                wmma::load_matrix_sync(afh[i], &As[0][wr*32 + i*16][ks*16], 40);
                wmma::load_matrix_sync(afl[i], &As[1][wr*32 + i*16][ks*16], 40);
            }
            if (TRANSB){
                #pragma unroll
                for (int j = 0; j < 4; j++){
                    wmma::fragment<wmma::matrix_b,16,16,16,__nv_bfloat16,wmma::col_major> bfh, bfl;
                    int nb = wc*64 + j*16;
                    wmma::load_matrix_sync(bfh, &Bs[0][nb*40 + ks*16], 40);
                    wmma::load_matrix_sync(bfl, &Bs[1][nb*40 + ks*16], 40);
                    #pragma unroll
                    for (int i = 0; i < 2; i++){
                        wmma::mma_sync(acc[i][j], afh[i], bfh, acc[i][j]);
                        wmma::mma_sync(acc[i][j], afh[i], bfl, acc[i][j]);
                        wmma::mma_sync(acc[i][j], afl[i], bfh, acc[i][j]);
                    }
                }
            } else {
                #pragma unroll
                for (int j = 0; j < 4; j++){
                    wmma::fragment<wmma::matrix_b,16,16,16,__nv_bfloat16,wmma::row_major> bfh, bfl;
                    int nb = wc*64 + j*16;
                    wmma::load_matrix_sync(bfh, &Bs[0][(ks*16)*136 + nb], 136);
                    wmma::load_matrix_sync(bfl, &Bs[1][(ks*16)*136 + nb], 136);
                    #pragma unroll
                    for (int i = 0; i < 2; i++){
                        wmma::mma_sync(acc[i][j], afh[i], bfh, acc[i][j]);
                        wmma::mma_sync(acc[i][j], afh[i], bfl, acc[i][j]);
                        wmma::mma_sync(acc[i][j], afl[i], bfh, acc[i][j]);
                    }
                }
            }
        }
        __syncthreads();
    }

    if (EPI == 2){
        #pragma unroll
        for (int i = 0; i < 2; i++)
            #pragma unroll
            for (int j = 0; j < 4; j++){
                float* cp = Cb + (row0 + wr*32 + i*16)*(long)N + col0 + wc*64 + j*16;
                wmma::store_matrix_sync(cp, acc[i][j], N, wmma::mem_row_major);
            }
        return;
    }

    float* scr = ((float*)Bs) + wid*320;   // 16x20 per warp
    float alpha = (EPI == 1) ? __ldg(alpha_p) : 1.f;
    #pragma unroll
    for (int i = 0; i < 2; i++){
        #pragma unroll
        for (int j = 0; j < 4; j++){
            wmma::store_matrix_sync(scr, acc[i][j], 20, wmma::mem_row_major);
            __syncwarp();
            #pragma unroll
            for (int e = lane; e < 256; e += 32){
                int r = e >> 4, c = e & 15;
                long grow = row0 + wr*32 + i*16 + r;
                long gcol = col0 + wc*64 + j*16 + c;
                float v = scr[r*20 + c] + bias[gcol];
                if (EPI == 0){
                    v = fmaxf(v, 0.f);
                    __nv_bfloat16 h, l;
                    bsplit(v, h, l);
                    g_hidh[grow*OH + gcol] = h;
                    g_hidl[grow*OH + gcol] = l;
                } else {
                    Cb[grow*(long)N + gcol] = v * alpha;
                }
            }
            __syncwarp();
        }
    }
}

// ============================================================
extern "C" void kernel_launch(void* const* d_in, const int* in_sizes, int n_in,
                              void* d_out, int out_size)
{
    const float* Hj   = (const float*)d_in[0];
    const float* Hi   = (const float*)d_in[1];
    const float* mask = (const float*)d_in[2];
    const float* pjw  = (const float*)d_in[3];
    const float* piw  = (const float*)d_in[4];
    const float* sw1  = (const float*)d_in[5];
    const float* sb1  = (const float*)d_in[6];
    const float* sw2  = (const float*)d_in[7];
    const float* sb2  = (const float*)d_in[8];
    const float* vw1  = (const float*)d_in[9];
    const float* vb1  = (const float*)d_in[10];
    const float* vw2  = (const float*)d_in[11];
    const float* vb2  = (const float*)d_in[12];
    const float* alpha= (const float*)d_in[13];
    float* out = (float*)d_out;

    void *pctx, *ppbh, *ppbl, *phih, *phil, *pm1h, *pm1l;
    void *pw1h, *pw1l, *phdh, *phdl, *pw2h, *pw2l;
    cudaGetSymbolAddress(&pctx, g_ctx);
    cudaGetSymbolAddress(&ppbh, g_pbh);  cudaGetSymbolAddress(&ppbl, g_pbl);
    cudaGetSymbolAddress(&phih, g_hih);  cudaGetSymbolAddress(&phil, g_hil);
    cudaGetSymbolAddress(&pm1h, g_m1h);  cudaGetSymbolAddress(&pm1l, g_m1l);
    cudaGetSymbolAddress(&pw1h, g_w1h);  cudaGetSymbolAddress(&pw1l, g_w1l);
    cudaGetSymbolAddress(&phdh, g_hidh); cudaGetSymbolAddress(&phdl, g_hidl);
    cudaGetSymbolAddress(&pw2h, g_w2h);  cudaGetSymbolAddress(&pw2l, g_w2l);

    cudaFuncSetAttribute(pair_wmma, cudaFuncAttributeMaxDynamicSharedMemorySize, PAIR_SMEM);

    // 0: proj
    proj_kernel<<<NROWS, 256>>>(Hj, Hi, pjw, piw, sw1);
    // 1: W' precompute
    wsplit_pair<<<(96*88 + 255)/256, 256>>>(sw1);
    // 2: Hi -> bf16 hi/lo
    conv_split<<<(NROWS*Hh/4 + 255)/256, 256>>>(Hi, (__nv_bfloat16*)phih,
                                                (__nv_bfloat16*)phil, NROWS*Hh/4);
    // 3: pair (profiled slot)
    pair_wmma<<<NROWS, 512, PAIR_SMEM>>>(sb1, sw2, sb2, mask);
    // 4: ctx = probs @ Hi  [NN, batched, EPI2 raw fp32]
    {
        dim3 g(Hh/128, Ss/128, Bb);
        gemm_wmma<false,2><<<g, 256>>>(
            (const __nv_bfloat16*)ppbh, (const __nv_bfloat16*)ppbl,
            (const __nv_bfloat16*)phih, (const __nv_bfloat16*)phil,
            (float*)pctx, Hh, Ss, Ss, Hh,
            (long)Ss*Ss, (long)Ss*Hh, (long)Ss*Hh, nullptr, nullptr);
    }
    // 5: msg_in -> bf16 hi/lo
    msgin_conv<<<(NROWS*(Hh/4) + 255)/256, 256>>>(Hj);
    // 6: vw1 -> bf16 hi/lo
    conv_split<<<(OH*H3/4 + 255)/256, 256>>>(vw1, (__nv_bfloat16*)pw1h,
                                             (__nv_bfloat16*)pw1l, OH*H3/4);
    // 7: hid = relu(msg_in @ vw1^T + vb1)  [NT, EPI0]
    {
        dim3 g(OH/128, NROWS/128, 1);
        gemm_wmma<true,0><<<g, 256>>>(
            (const __nv_bfloat16*)pm1h, (const __nv_bfloat16*)pm1l,
            (const __nv_bfloat16*)pw1h, (const __nv_bfloat16*)pw1l,
            nullptr, OH, H3, H3, H3,
            0, 0, 0, vb1, nullptr);
    }
    // 8: vw2 -> bf16 hi/lo
    conv_split<<<(Hh*OH/4 + 255)/256, 256>>>(vw2, (__nv_bfloat16*)pw2h,
                                             (__nv_bfloat16*)pw2l, Hh*OH/4);
    // 9: out = alpha * (hid @ vw2^T + vb2)  [NT, EPI1]
    {
        dim3 g(Hh/128, NROWS/128, 1);
        gemm_wmma<true,1><<<g, 256>>>(
            (const __nv_bfloat16*)phdh, (const __nv_bfloat16*)phdl,
            (const __nv_bfloat16*)pw2h, (const __nv_bfloat16*)pw2l,
            out, Hh, OH, OH, OH,
            0, 0, 0, vb2, alpha);
    }
    (void)in_sizes; (void)n_in; (void)out_size;
}

// round 10
// speedup vs baseline: 1.2259x; 1.2259x over previous
#include <cuda_runtime.h>
#include <cuda_bf16.h>
#include <mma.h>
#include <math.h>
#include <cstdint>

using namespace nvcuda;

#define Bb 4
#define Ss 512
#define Hh 768
#define Dd 24
#define Mm 96
#define OH 768
#define H3 2304
#define NROWS (Bb*Ss)   // 2048

typedef unsigned long long ull;

// ---- scratch ----
__device__ __align__(16) float g_Zj[NROWS*Dd];
__device__ __align__(16) float g_Zi[NROWS*Dd];
__device__ __align__(16) float g_Aj[NROWS*Mm];
__device__ __align__(16) float g_ctx[(long)NROWS*Hh];
// precomputed pair weight matrix W' = [Wc | Wd | Wb | 0]  (96 x 88, bf16)
__device__ __align__(16) __nv_bfloat16 g_Wph[96*88];
// bf16 hi/lo operands for tensor-core GEMMs
__device__ __align__(16) __nv_bfloat16 g_pbh[(long)Bb*Ss*Ss];
__device__ __align__(16) __nv_bfloat16 g_pbl[(long)Bb*Ss*Ss];
__device__ __align__(16) __nv_bfloat16 g_hih[(long)NROWS*Hh];
__device__ __align__(16) __nv_bfloat16 g_hil[(long)NROWS*Hh];
__device__ __align__(16) __nv_bfloat16 g_m1h[(long)NROWS*H3];
__device__ __align__(16) __nv_bfloat16 g_m1l[(long)NROWS*H3];
__device__ __align__(16) __nv_bfloat16 g_w1h[(long)OH*H3];
__device__ __align__(16) __nv_bfloat16 g_w1l[(long)OH*H3];
__device__ __align__(16) __nv_bfloat16 g_hidh[(long)NROWS*OH];
__device__ __align__(16) __nv_bfloat16 g_hidl[(long)NROWS*OH];
__device__ __align__(16) __nv_bfloat16 g_w2h[(long)Hh*OH];
__device__ __align__(16) __nv_bfloat16 g_w2l[(long)Hh*OH];

// bf16 hi/lo split
__device__ __forceinline__ void bsplit(float v, __nv_bfloat16& h, __nv_bfloat16& l){
    h = __float2bfloat16(v);
    l = __float2bfloat16(v - __bfloat162float(h));
}
// pack two floats to bf16x2 (hi only)
__device__ __forceinline__ unsigned packh(float a, float b){
    __nv_bfloat162 p;
    p.x = __float2bfloat16(a);
    p.y = __float2bfloat16(b);
    return *(unsigned*)&p;
}

// ============================================================
// K0: precompute W' = [Wc | Wd | Wb | 0] (96 x 88) bf16
// ============================================================
__global__ __launch_bounds__(256) void wsplit_pair(const float* __restrict__ sw1)
{
    int i = blockIdx.x*256 + threadIdx.x;
    if (i >= 96*88) return;
    int m = i / 88, k = i % 88;
    float wv = 0.f;
    if (k < 24)      wv = sw1[m*96 + 48 + k];
    else if (k < 48) wv = sw1[m*96 + 72 + (k-24)];
    else if (k < 72) wv = sw1[m*96 + 24 + (k-48)];
    g_Wph[i] = __float2bfloat16(wv);
}

// ============================================================
// K1: projections + rank-1 term Aj = Wa @ zj
// ============================================================
__global__ __launch_bounds__(256) void proj_kernel(
    const float* __restrict__ Hj, const float* __restrict__ Hi,
    const float* __restrict__ pjw, const float* __restrict__ piw,
    const float* __restrict__ sw1)
{
    int r = blockIdx.x;
    __shared__ float shj[Hh], shi[Hh], szj[Dd];
    int tid = threadIdx.x;
    for (int i = tid; i < Hh; i += 256){
        shj[i] = Hj[(long)r*Hh + i];
        shi[i] = Hi[(long)r*Hh + i];
    }
    __syncthreads();
    int o = tid >> 3, g = tid & 7;
    if (o < Dd){
        float pj = 0.f, pi = 0.f;
        for (int h = g; h < Hh; h += 8){
            pj += shj[h] * pjw[o*Hh + h];
            pi += shi[h] * piw[o*Hh + h];
        }
        #pragma unroll
        for (int d = 4; d > 0; d >>= 1){
            pj += __shfl_down_sync(0xffffffffu, pj, d, 8);
            pi += __shfl_down_sync(0xffffffffu, pi, d, 8);
        }
        if (g == 0){
            szj[o] = pj;
            g_Zj[r*Dd + o] = pj; g_Zi[r*Dd + o] = pi;
        }
    }
    __syncthreads();
    if (tid < Mm){
        float a = 0.f;
        #pragma unroll
        for (int d = 0; d < Dd; d++)
            a += sw1[tid*96 + d] * szj[d];
        g_Aj[r*Mm + tid] = a;
    }
}

// ============================================================
// K2: pair logits, v5: single-pass bf16 (round-8 structure)
//  256 threads / 8 warps, warp owns 16-row t-tile x 96 cols.
//  Softmax converts bf16's absolute logit error (~1e-4) into
//  ~1e-4 relative prob error: safe at 1e-3 gate.
// ============================================================
#define POFF_WH   0                       // 96*88*2 = 16896
#define POFF_F    16896                   // [128][88]*2 = 22528 -> 39424
#define POFF_SCR  39424                   // 8 warps x 16x52 f = 26624 -> 66048
#define POFF_SLOG 66048                   // 512 f -> 68096
#define POFF_SZJ  68096
#define POFF_SSC  68224
#define POFF_SW2  68608
#define POFF_SRED 68992
#define PAIR_SMEM 69120

// column value: [u(24) | v(24) | zi(24) | 0(16)]
#define FCOLV(c) ((c) < 24 ? szj[(c)]*za[(c)] : \
                  (c) < 48 ? fabsf(szj[(c)-24]-za[(c)-24]) : \
                  (c) < 72 ? za[(c)-48] : 0.f)

__global__ __launch_bounds__(256) void pair_wmma(
    const float* __restrict__ sb1,
    const float* __restrict__ sw2v, const float* __restrict__ sb2,
    const float* __restrict__ mask)
{
    extern __shared__ char ps[];
    __nv_bfloat16* Wh = (__nv_bfloat16*)(ps + POFF_WH);
    __nv_bfloat16* Fh = (__nv_bfloat16*)(ps + POFF_F);
    float* scr  = (float*)(ps + POFF_SCR);
    float* slog = (float*)(ps + POFF_SLOG);
    float* szj  = (float*)(ps + POFF_SZJ);
    float* ssc  = (float*)(ps + POFF_SSC);
    float* sw2s = (float*)(ps + POFF_SW2);
    float* sred = (float*)(ps + POFF_SRED);

    int r = blockIdx.x, b = r >> 9;
    int tid = threadIdx.x, wid = tid >> 5, lane = tid & 31;

    // load precomputed W' (1056 uint4)
    for (int i = tid; i < 1056; i += 256)
        ((uint4*)Wh)[i] = ((const uint4*)g_Wph)[i];
    if (tid < Dd) szj[tid] = g_Zj[r*Dd + tid];
    if (tid < Mm){
        ssc[tid]  = g_Aj[r*Mm + tid] + sb1[tid];
        sw2s[tid] = sw2v[tid];
    }
    __syncthreads();

    int bhalf = tid >> 7;        // 0: cols 0..39, 1: cols 40..87
    int brow  = tid & 127;

    #pragma unroll 1
    for (int chunk = 0; chunk < 4; chunk++){
        // ---- build F (bf16, vectorized STS.128) ----
        {
            int t = chunk*128 + brow;
            const float4* zi4 = (const float4*)&g_Zi[(long)(b*Ss + t)*Dd];
            float za[24];
            #pragma unroll
            for (int q = 0; q < 6; q++){
                float4 v4 = __ldg(&zi4[q]);
                za[q*4+0]=v4.x; za[q*4+1]=v4.y; za[q*4+2]=v4.z; za[q*4+3]=v4.w;
            }
            if (bhalf == 0){
                uint4* dh = (uint4*)&Fh[brow*88];
                #pragma unroll
                for (int q = 0; q < 5; q++){
                    unsigned h4[4];
                    #pragma unroll
                    for (int e = 0; e < 4; e++){
                        int c = q*8 + e*2;
                        h4[e] = packh(FCOLV(c), FCOLV(c+1));
                    }
                    dh[q] = make_uint4(h4[0],h4[1],h4[2],h4[3]);
                }
            } else {
                uint4* dh = (uint4*)&Fh[brow*88 + 40];
                #pragma unroll
                for (int q = 0; q < 6; q++){
                    unsigned h4[4];
                    #pragma unroll
                    for (int e = 0; e < 4; e++){
                        int c = 40 + q*8 + e*2;
                        h4[e] = packh(FCOLV(c), FCOLV(c+1));
                    }
                    dh[q] = make_uint4(h4[0],h4[1],h4[2],h4[3]);
                }
            }
        }
        __syncthreads();

        // ---- GEMM: warp owns 16-row t-tile; single bf16 pass ----
        wmma::fragment<wmma::accumulator,16,16,16,float> acc[6];
        #pragma unroll
        for (int j = 0; j < 6; j++) wmma::fill_fragment(acc[j], 0.f);

        #pragma unroll
        for (int k = 0; k < 5; k++){
            wmma::fragment<wmma::matrix_a,16,16,16,__nv_bfloat16,wmma::row_major> ah;
            wmma::load_matrix_sync(ah, &Fh[(wid*16)*88 + k*16], 88);
            #pragma unroll
            for (int j = 0; j < 6; j++){
                wmma::fragment<wmma::matrix_b,16,16,16,__nv_bfloat16,wmma::col_major> bh;
                wmma::load_matrix_sync(bh, &Wh[(j*16)*88 + k*16], 88);
                wmma::mma_sync(acc[j], ah, bh, acc[j]);
            }
        }

        // ---- reduce to logits, two 48-col passes ----
        float* scrw = scr + wid*832;   // 16 x 52 floats
        int row = lane >> 1, sub = lane & 1;
        float lsum = 0.f;
        #pragma unroll
        for (int g = 0; g < 2; g++){
            #pragma unroll
            for (int j = 0; j < 3; j++)
                wmma::store_matrix_sync(scrw + j*16, acc[g*3 + j], 52, wmma::mem_row_major);
            __syncwarp();
            const float4* sr4 = (const float4*)(scrw + row*52 + sub*24);
            const float4* sc4 = (const float4*)(ssc + g*48 + sub*24);
            const float4* sw4 = (const float4*)(sw2s + g*48 + sub*24);
            #pragma unroll
            for (int q = 0; q < 6; q++){
                float4 hv = sr4[q];
                float4 cv = sc4[q];
                float4 wv = sw4[q];
                lsum += wv.x * fmaxf(hv.x + cv.x, 0.f);
                lsum += wv.y * fmaxf(hv.y + cv.y, 0.f);
                lsum += wv.z * fmaxf(hv.z + cv.z, 0.f);
                lsum += wv.w * fmaxf(hv.w + cv.w, 0.f);
            }
            __syncwarp();
        }
        lsum += __shfl_xor_sync(0xffffffffu, lsum, 1);
        if (sub == 0) slog[chunk*128 + wid*16 + row] = lsum;
        __syncthreads();
    }

    // ---- masked softmax over slog[512] ----
    int t0 = tid, t1 = tid + 256;
    float lt0 = slog[t0] + sb2[0] + (1.f - mask[b*Ss + t0]) * (-3.402823466e38f);
    float lt1 = slog[t1] + sb2[0] + (1.f - mask[b*Ss + t1]) * (-3.402823466e38f);

    float mx = fmaxf(lt0, lt1);
    #pragma unroll
    for (int d = 16; d > 0; d >>= 1)
        mx = fmaxf(mx, __shfl_xor_sync(0xffffffffu, mx, d));
    if (lane == 0) sred[wid] = mx;
    __syncthreads();
    float bmax = sred[0];
    #pragma unroll
    for (int i = 1; i < 8; i++) bmax = fmaxf(bmax, sred[i]);

    float e0 = expf(lt0 - bmax);
    float e1 = expf(lt1 - bmax);
    float sm = e0 + e1;
    #pragma unroll
    for (int d = 16; d > 0; d >>= 1)
        sm += __shfl_xor_sync(0xffffffffu, sm, d);
    __syncthreads();
    if (lane == 0) sred[wid] = sm;
    __syncthreads();
    float tot = 0.f;
    #pragma unroll
    for (int i = 0; i < 8; i++) tot += sred[i];
    float inv = 1.f / tot;

    __nv_bfloat16 h, l;
    bsplit(e0 * inv, h, l);
    g_pbh[(long)r*Ss + t0] = h; g_pbl[(long)r*Ss + t0] = l;
    bsplit(e1 * inv, h, l);
    g_pbh[(long)r*Ss + t1] = h; g_pbl[(long)r*Ss + t1] = l;
}

// ============================================================
// K3: fp32 -> bf16 hi/lo split (vectorized)
// ============================================================
__global__ __launch_bounds__(256) void conv_split(
    const float* __restrict__ x, __nv_bfloat16* __restrict__ hi,
    __nv_bfloat16* __restrict__ lo, int n4)
{
    int i = blockIdx.x*256 + threadIdx.x;
    if (i >= n4) return;
    float4 v = ((const float4*)x)[i];
    __nv_bfloat16 h0,h1,h2,h3,l0,l1,l2,l3;
    bsplit(v.x,h0,l0); bsplit(v.y,h1,l1); bsplit(v.z,h2,l2); bsplit(v.w,h3,l3);
    __nv_bfloat162 p0, p1;
    p0.x=h0; p0.y=h1; p1.x=h2; p1.y=h3;
    ((__nv_bfloat162*)hi)[2*i]   = p0;
    ((__nv_bfloat162*)hi)[2*i+1] = p1;
    p0.x=l0; p0.y=l1; p1.x=l2; p1.y=l3;
    ((__nv_bfloat162*)lo)[2*i]   = p0;
    ((__nv_bfloat162*)lo)[2*i+1] = p1;
}

// ============================================================
// K4: msg_in = [ctx | Hj | ctx*Hj] -> bf16 hi/lo
// ============================================================
__device__ __forceinline__ void store4(__nv_bfloat16* hp, __nv_bfloat16* lp,
                                       float a, float b, float c, float d)
{
    __nv_bfloat16 h0,h1,h2,h3,l0,l1,l2,l3;
    bsplit(a,h0,l0); bsplit(b,h1,l1); bsplit(c,h2,l2); bsplit(d,h3,l3);
    __nv_bfloat162 p0, p1;
    p0.x=h0; p0.y=h1; p1.x=h2; p1.y=h3;
    ((__nv_bfloat162*)hp)[0] = p0; ((__nv_bfloat162*)hp)[1] = p1;
    p0.x=l0; p0.y=l1; p1.x=l2; p1.y=l3;
    ((__nv_bfloat162*)lp)[0] = p0; ((__nv_bfloat162*)lp)[1] = p1;
}
__global__ __launch_bounds__(256) void msgin_conv(const float* __restrict__ Hj)
{
    int i = blockIdx.x*256 + threadIdx.x;
    if (i >= NROWS*(Hh/4)) return;
    int r = i / (Hh/4);
    int c = (i % (Hh/4)) * 4;
    float4 cv = *(const float4*)&g_ctx[(long)r*Hh + c];
    float4 hv = *(const float4*)&Hj[(long)r*Hh + c];
    long base = (long)r*H3 + c;
    store4(&g_m1h[base],      &g_m1l[base],      cv.x, cv.y, cv.z, cv.w);
    store4(&g_m1h[base+Hh],   &g_m1l[base+Hh],   hv.x, hv.y, hv.z, hv.w);
    store4(&g_m1h[base+2*Hh], &g_m1l[base+2*Hh],
           cv.x*hv.x, cv.y*hv.y, cv.z*hv.z, cv.w*hv.w);
}

// ============================================================
// K5: WMMA GEMM  C[M,N] = A[M,K] @ opB  (bf16 hi/lo, 3-pass)
// ============================================================
template<bool TRANSB, int EPI>
__global__ __launch_bounds__(256) void gemm_wmma(
    const __nv_bfloat16* __restrict__ Ah, const __nv_bfloat16* __restrict__ Al,
    const __nv_bfloat16* __restrict__ Bh, const __nv_bfloat16* __restrict__ Bl,
    float* __restrict__ Cout, int N, int K, int ldA, int ldB,
    long strideA, long strideB, long strideC,
    const float* __restrict__ bias, const float* __restrict__ alpha_p)
{
    __shared__ __nv_bfloat16 As[2][128][40];
    __shared__ __nv_bfloat16 Bs[2][5120];   // NT: [n][40] ; NN: [k][136]

    int tid = threadIdx.x;
    int wid = tid >> 5, lane = tid & 31;
    int wr = wid & 3, wc = wid >> 2;        // 4x2 warps, warp tile 32x64
    long row0 = (long)blockIdx.y * 128;
    long col0 = (long)blockIdx.x * 128;

    const __nv_bfloat16* APh = Ah + (long)blockIdx.z * strideA;
    const __nv_bfloat16* APl = Al + (long)blockIdx.z * strideA;
    const __nv_bfloat16* BPh = Bh + (long)blockIdx.z * strideB;
    const __nv_bfloat16* BPl = Bl + (long)blockIdx.z * strideB;
    float* Cb = Cout ? (Cout + (long)blockIdx.z * strideC) : nullptr;

    wmma::fragment<wmma::accumulator,16,16,16,float> acc[2][4];
    #pragma unroll
    for (int i = 0; i < 2; i++)
        #pragma unroll
        for (int j = 0; j < 4; j++) wmma::fill_fragment(acc[i][j], 0.f);

    #pragma unroll 1
    for (int kc = 0; kc < K; kc += 32){
        #pragma unroll
        for (int t = tid; t < 512; t += 256){
            int r = t >> 2, seg = t & 3;
            long off = (row0 + r)*(long)ldA + kc + seg*8;
            *(float4*)&As[0][r][seg*8] = *(const float4*)(APh + off);
            *(float4*)&As[1][r][seg*8] = *(const float4*)(APl + off);
        }
        if (TRANSB){
            #pragma unroll
            for (int t = tid; t < 512; t += 256){
                int r = t >> 2, seg = t & 3;
                long off = (col0 + r)*(long)ldB + kc + seg*8;
                *(float4*)&Bs[0][r*40 + seg*8] = *(const float4*)(BPh + off);
                *(float4*)&Bs[1][r*40 + seg*8] = *(const float4*)(BPl + off);
            }
        } else {
            #pragma unroll
            for (int t = tid; t < 512; t += 256){
                int r = t >> 4, seg = t & 15;
                long off = (long)(kc + r)*ldB + col0 + seg*8;
                *(float4*)&Bs[0][r*136 + seg*8] = *(const float4*)(BPh + off);
                *(float4*)&Bs[1][r*136 + seg*8] = *(const float4*)(BPl + off);
            }
        }
        __syncthreads();

        #pragma unroll
        for (int ks = 0; ks < 2; ks++){
            wmma::fragment<wmma::matrix_a,16,16,16,__nv_bfloat16,wmma::row_major> afh[2], afl[2];
            #pragma unroll
            for (int i = 0; i < 2; i++){
                wmma::load_matrix_sync(afh[i], &As[0][wr*32 + i*16][ks*16], 40);
                wmma::load_matrix_sync(afl[i], &As[1][wr*32 + i*16][ks*16], 40);
            }
            if (TRANSB){
                #pragma unroll
                for (int j = 0; j < 4; j++){
                    wmma::fragment<wmma::matrix_b,16,16,16,__nv_bfloat16,wmma::col_major> bfh, bfl;
                    int nb = wc*64 + j*16;
                    wmma::load_matrix_sync(bfh, &Bs[0][nb*40 + ks*16], 40);
                    wmma::load_matrix_sync(bfl, &Bs[1][nb*40 + ks*16], 40);
                    #pragma unroll
                    for (int i = 0; i < 2; i++){
                        wmma::mma_sync(acc[i][j], afh[i], bfh, acc[i][j]);
                        wmma::mma_sync(acc[i][j], afh[i], bfl, acc[i][j]);
                        wmma::mma_sync(acc[i][j], afl[i], bfh, acc[i][j]);
                    }
                }
            } else {
                #pragma unroll
                for (int j = 0; j < 4; j++){
                    wmma::fragment<wmma::matrix_b,16,16,16,__nv_bfloat16,wmma::row_major> bfh, bfl;
                    int nb = wc*64 + j*16;
                    wmma::load_matrix_sync(bfh, &Bs[0][(ks*16)*136 + nb], 136);
                    wmma::load_matrix_sync(bfl, &Bs[1][(ks*16)*136 + nb], 136);
                    #pragma unroll
                    for (int i = 0; i < 2; i++){
                        wmma::mma_sync(acc[i][j], afh[i], bfh, acc[i][j]);
                        wmma::mma_sync(acc[i][j], afh[i], bfl, acc[i][j]);
                        wmma::mma_sync(acc[i][j], afl[i], bfh, acc[i][j]);
                    }
                }
            }
        }
        __syncthreads();
    }

    if (EPI == 2){
        #pragma unroll
        for (int i = 0; i < 2; i++)
            #pragma unroll
            for (int j = 0; j < 4; j++){
                float* cp = Cb + (row0 + wr*32 + i*16)*(long)N + col0 + wc*64 + j*16;
                wmma::store_matrix_sync(cp, acc[i][j], N, wmma::mem_row_major);
            }
        return;
    }

    float* scr = ((float*)Bs) + wid*320;   // 16x20 per warp
    float alpha = (EPI == 1) ? __ldg(alpha_p) : 1.f;
    #pragma unroll
    for (int i = 0; i < 2; i++){
        #pragma unroll
        for (int j = 0; j < 4; j++){
            wmma::store_matrix_sync(scr, acc[i][j], 20, wmma::mem_row_major);
            __syncwarp();
            #pragma unroll
            for (int e = lane; e < 256; e += 32){
                int r = e >> 4, c = e & 15;
                long grow = row0 + wr*32 + i*16 + r;
                long gcol = col0 + wc*64 + j*16 + c;
                float v = scr[r*20 + c] + bias[gcol];
                if (EPI == 0){
                    v = fmaxf(v, 0.f);
                    __nv_bfloat16 h, l;
                    bsplit(v, h, l);
                    g_hidh[grow*OH + gcol] = h;
                    g_hidl[grow*OH + gcol] = l;
                } else {
                    Cb[grow*(long)N + gcol] = v * alpha;
                }
            }
            __syncwarp();
        }
    }
}

// ============================================================
extern "C" void kernel_launch(void* const* d_in, const int* in_sizes, int n_in,
                              void* d_out, int out_size)
{
    const float* Hj   = (const float*)d_in[0];
    const float* Hi   = (const float*)d_in[1];
    const float* mask = (const float*)d_in[2];
    const float* pjw  = (const float*)d_in[3];
    const float* piw  = (const float*)d_in[4];
    const float* sw1  = (const float*)d_in[5];
    const float* sb1  = (const float*)d_in[6];
    const float* sw2  = (const float*)d_in[7];
    const float* sb2  = (const float*)d_in[8];
    const float* vw1  = (const float*)d_in[9];
    const float* vb1  = (const float*)d_in[10];
    const float* vw2  = (const float*)d_in[11];
    const float* vb2  = (const float*)d_in[12];
    const float* alpha= (const float*)d_in[13];
    float* out = (float*)d_out;

    void *pctx, *ppbh, *ppbl, *phih, *phil, *pm1h, *pm1l;
    void *pw1h, *pw1l, *phdh, *phdl, *pw2h, *pw2l;
    cudaGetSymbolAddress(&pctx, g_ctx);
    cudaGetSymbolAddress(&ppbh, g_pbh);  cudaGetSymbolAddress(&ppbl, g_pbl);
    cudaGetSymbolAddress(&phih, g_hih);  cudaGetSymbolAddress(&phil, g_hil);
    cudaGetSymbolAddress(&pm1h, g_m1h);  cudaGetSymbolAddress(&pm1l, g_m1l);
    cudaGetSymbolAddress(&pw1h, g_w1h);  cudaGetSymbolAddress(&pw1l, g_w1l);
    cudaGetSymbolAddress(&phdh, g_hidh); cudaGetSymbolAddress(&phdl, g_hidl);
    cudaGetSymbolAddress(&pw2h, g_w2h);  cudaGetSymbolAddress(&pw2l, g_w2l);

    cudaFuncSetAttribute(pair_wmma, cudaFuncAttributeMaxDynamicSharedMemorySize, PAIR_SMEM);

    // 0: proj
    proj_kernel<<<NROWS, 256>>>(Hj, Hi, pjw, piw, sw1);
    // 1: W' precompute
    wsplit_pair<<<(96*88 + 255)/256, 256>>>(sw1);
    // 2: Hi -> bf16 hi/lo
    conv_split<<<(NROWS*Hh/4 + 255)/256, 256>>>(Hi, (__nv_bfloat16*)phih,
                                                (__nv_bfloat16*)phil, NROWS*Hh/4);
    // 3: pair (profiled slot)
    pair_wmma<<<NROWS, 256, PAIR_SMEM>>>(sb1, sw2, sb2, mask);
    // 4: ctx = probs @ Hi  [NN, batched, EPI2 raw fp32]
    {
        dim3 g(Hh/128, Ss/128, Bb);
        gemm_wmma<false,2><<<g, 256>>>(
            (const __nv_bfloat16*)ppbh, (const __nv_bfloat16*)ppbl,
            (const __nv_bfloat16*)phih, (const __nv_bfloat16*)phil,
            (float*)pctx, Hh, Ss, Ss, Hh,
            (long)Ss*Ss, (long)Ss*Hh, (long)Ss*Hh, nullptr, nullptr);
    }
    // 5: msg_in -> bf16 hi/lo
    msgin_conv<<<(NROWS*(Hh/4) + 255)/256, 256>>>(Hj);
    // 6: vw1 -> bf16 hi/lo
    conv_split<<<(OH*H3/4 + 255)/256, 256>>>(vw1, (__nv_bfloat16*)pw1h,
                                             (__nv_bfloat16*)pw1l, OH*H3/4);
    // 7: hid = relu(msg_in @ vw1^T + vb1)  [NT, EPI0]
    {
        dim3 g(OH/128, NROWS/128, 1);
        gemm_wmma<true,0><<<g, 256>>>(
            (const __nv_bfloat16*)pm1h, (const __nv_bfloat16*)pm1l,
            (const __nv_bfloat16*)pw1h, (const __nv_bfloat16*)pw1l,
            nullptr, OH, H3, H3, H3,
            0, 0, 0, vb1, nullptr);
    }
    // 8: vw2 -> bf16 hi/lo
    conv_split<<<(Hh*OH/4 + 255)/256, 256>>>(vw2, (__nv_bfloat16*)pw2h,
                                             (__nv_bfloat16*)pw2l, Hh*OH/4);
    // 9: out = alpha * (hid @ vw2^T + vb2)  [NT, EPI1]
    {
        dim3 g(Hh/128, NROWS/128, 1);
        gemm_wmma<true,1><<<g, 256>>>(
            (const __nv_bfloat16*)phdh, (const __nv_bfloat16*)phdl,
            (const __nv_bfloat16*)pw2h, (const __nv_bfloat16*)pw2l,
            out, Hh, OH, OH, OH,
            0, 0, 0, vb2, alpha);
    }
    (void)in_sizes; (void)n_in; (void)out_size;
}

// round 11
// speedup vs baseline: 1.3723x; 1.1194x over previous
#include <cuda_runtime.h>
#include <cuda_bf16.h>
#include <mma.h>
#include <math.h>
#include <cstdint>

using namespace nvcuda;

#define Bb 4
#define Ss 512
#define Hh 768
#define Dd 24
#define Mm 96
#define OH 768
#define H3 2304
#define NROWS (Bb*Ss)   // 2048

typedef unsigned long long ull;

// ---- scratch ----
__device__ __align__(16) float g_Zj[NROWS*Dd];
__device__ __align__(16) float g_Zi[NROWS*Dd];
__device__ __align__(16) float g_Aj[NROWS*Mm];
__device__ __align__(16) float g_ctx[(long)NROWS*Hh];
__device__ __align__(16) __nv_bfloat16 g_Wph[96*88];
// bf16 hi/lo operands for tensor-core GEMMs
__device__ __align__(16) __nv_bfloat16 g_pbh[(long)Bb*Ss*Ss];
__device__ __align__(16) __nv_bfloat16 g_pbl[(long)Bb*Ss*Ss];
__device__ __align__(16) __nv_bfloat16 g_hih[(long)NROWS*Hh];
__device__ __align__(16) __nv_bfloat16 g_hil[(long)NROWS*Hh];
__device__ __align__(16) __nv_bfloat16 g_m1h[(long)NROWS*H3];
__device__ __align__(16) __nv_bfloat16 g_m1l[(long)NROWS*H3];
__device__ __align__(16) __nv_bfloat16 g_w1h[(long)OH*H3];
__device__ __align__(16) __nv_bfloat16 g_w1l[(long)OH*H3];
__device__ __align__(16) __nv_bfloat16 g_hidh[(long)NROWS*OH];
__device__ __align__(16) __nv_bfloat16 g_hidl[(long)NROWS*OH];
__device__ __align__(16) __nv_bfloat16 g_w2h[(long)Hh*OH];
__device__ __align__(16) __nv_bfloat16 g_w2l[(long)Hh*OH];
// split-K partial buffers (fp32)
__device__ __align__(16) float g_partc[4L*Bb*Ss*Hh];
__device__ __align__(16) float g_part1[3L*NROWS*OH];
__device__ __align__(16) float g_part2[3L*NROWS*Hh];

// bf16 hi/lo split
__device__ __forceinline__ void bsplit(float v, __nv_bfloat16& h, __nv_bfloat16& l){
    h = __float2bfloat16(v);
    l = __float2bfloat16(v - __bfloat162float(h));
}
__device__ __forceinline__ unsigned packh(float a, float b){
    __nv_bfloat162 p;
    p.x = __float2bfloat16(a);
    p.y = __float2bfloat16(b);
    return *(unsigned*)&p;
}

// ============================================================
// K0: precompute W' = [Wc | Wd | Wb | 0] (96 x 88) bf16
// ============================================================
__global__ __launch_bounds__(256) void wsplit_pair(const float* __restrict__ sw1)
{
    int i = blockIdx.x*256 + threadIdx.x;
    if (i >= 96*88) return;
    int m = i / 88, k = i % 88;
    float wv = 0.f;
    if (k < 24)      wv = sw1[m*96 + 48 + k];
    else if (k < 48) wv = sw1[m*96 + 72 + (k-24)];
    else if (k < 72) wv = sw1[m*96 + 24 + (k-48)];
    g_Wph[i] = __float2bfloat16(wv);
}

// ============================================================
// K1: projections + rank-1 term Aj = Wa @ zj
// ============================================================
__global__ __launch_bounds__(256) void proj_kernel(
    const float* __restrict__ Hj, const float* __restrict__ Hi,
    const float* __restrict__ pjw, const float* __restrict__ piw,
    const float* __restrict__ sw1)
{
    int r = blockIdx.x;
    __shared__ float shj[Hh], shi[Hh], szj[Dd];
    int tid = threadIdx.x;
    for (int i = tid; i < Hh; i += 256){
        shj[i] = Hj[(long)r*Hh + i];
        shi[i] = Hi[(long)r*Hh + i];
    }
    __syncthreads();
    int o = tid >> 3, g = tid & 7;
    if (o < Dd){
        float pj = 0.f, pi = 0.f;
        for (int h = g; h < Hh; h += 8){
            pj += shj[h] * pjw[o*Hh + h];
            pi += shi[h] * piw[o*Hh + h];
        }
        #pragma unroll
        for (int d = 4; d > 0; d >>= 1){
            pj += __shfl_down_sync(0xffffffffu, pj, d, 8);
            pi += __shfl_down_sync(0xffffffffu, pi, d, 8);
        }
        if (g == 0){
            szj[o] = pj;
            g_Zj[r*Dd + o] = pj; g_Zi[r*Dd + o] = pi;
        }
    }
    __syncthreads();
    if (tid < Mm){
        float a = 0.f;
        #pragma unroll
        for (int d = 0; d < Dd; d++)
            a += sw1[tid*96 + d] * szj[d];
        g_Aj[r*Mm + tid] = a;
    }
}

// ============================================================
// K2: pair logits (single-pass bf16 WMMA + fused softmax)
// ============================================================
#define POFF_WH   0
#define POFF_F    16896
#define POFF_SCR  39424
#define POFF_SLOG 66048
#define POFF_SZJ  68096
#define POFF_SSC  68224
#define POFF_SW2  68608
#define POFF_SRED 68992
#define PAIR_SMEM 69120

#define FCOLV(c) ((c) < 24 ? szj[(c)]*za[(c)] : \
                  (c) < 48 ? fabsf(szj[(c)-24]-za[(c)-24]) : \
                  (c) < 72 ? za[(c)-48] : 0.f)

__global__ __launch_bounds__(256) void pair_wmma(
    const float* __restrict__ sb1,
    const float* __restrict__ sw2v, const float* __restrict__ sb2,
    const float* __restrict__ mask)
{
    extern __shared__ char ps[];
    __nv_bfloat16* Wh = (__nv_bfloat16*)(ps + POFF_WH);
    __nv_bfloat16* Fh = (__nv_bfloat16*)(ps + POFF_F);
    float* scr  = (float*)(ps + POFF_SCR);
    float* slog = (float*)(ps + POFF_SLOG);
    float* szj  = (float*)(ps + POFF_SZJ);
    float* ssc  = (float*)(ps + POFF_SSC);
    float* sw2s = (float*)(ps + POFF_SW2);
    float* sred = (float*)(ps + POFF_SRED);

    int r = blockIdx.x, b = r >> 9;
    int tid = threadIdx.x, wid = tid >> 5, lane = tid & 31;

    for (int i = tid; i < 1056; i += 256)
        ((uint4*)Wh)[i] = ((const uint4*)g_Wph)[i];
    if (tid < Dd) szj[tid] = g_Zj[r*Dd + tid];
    if (tid < Mm){
        ssc[tid]  = g_Aj[r*Mm + tid] + sb1[tid];
        sw2s[tid] = sw2v[tid];
    }
    __syncthreads();

    int bhalf = tid >> 7;
    int brow  = tid & 127;

    #pragma unroll 1
    for (int chunk = 0; chunk < 4; chunk++){
        {
            int t = chunk*128 + brow;
            const float4* zi4 = (const float4*)&g_Zi[(long)(b*Ss + t)*Dd];
            float za[24];
            #pragma unroll
            for (int q = 0; q < 6; q++){
                float4 v4 = __ldg(&zi4[q]);
                za[q*4+0]=v4.x; za[q*4+1]=v4.y; za[q*4+2]=v4.z; za[q*4+3]=v4.w;
            }
            if (bhalf == 0){
                uint4* dh = (uint4*)&Fh[brow*88];
                #pragma unroll
                for (int q = 0; q < 5; q++){
                    unsigned h4[4];
                    #pragma unroll
                    for (int e = 0; e < 4; e++){
                        int c = q*8 + e*2;
                        h4[e] = packh(FCOLV(c), FCOLV(c+1));
                    }
                    dh[q] = make_uint4(h4[0],h4[1],h4[2],h4[3]);
                }
            } else {
                uint4* dh = (uint4*)&Fh[brow*88 + 40];
                #pragma unroll
                for (int q = 0; q < 6; q++){
                    unsigned h4[4];
                    #pragma unroll
                    for (int e = 0; e < 4; e++){
                        int c = 40 + q*8 + e*2;
                        h4[e] = packh(FCOLV(c), FCOLV(c+1));
                    }
                    dh[q] = make_uint4(h4[0],h4[1],h4[2],h4[3]);
                }
            }
        }
        __syncthreads();

        wmma::fragment<wmma::accumulator,16,16,16,float> acc[6];
        #pragma unroll
        for (int j = 0; j < 6; j++) wmma::fill_fragment(acc[j], 0.f);

        #pragma unroll
        for (int k = 0; k < 5; k++){
            wmma::fragment<wmma::matrix_a,16,16,16,__nv_bfloat16,wmma::row_major> ah;
            wmma::load_matrix_sync(ah, &Fh[(wid*16)*88 + k*16], 88);
            #pragma unroll
            for (int j = 0; j < 6; j++){
                wmma::fragment<wmma::matrix_b,16,16,16,__nv_bfloat16,wmma::col_major> bh;
                wmma::load_matrix_sync(bh, &Wh[(j*16)*88 + k*16], 88);
                wmma::mma_sync(acc[j], ah, bh, acc[j]);
            }
        }

        float* scrw = scr + wid*832;
        int row = lane >> 1, sub = lane & 1;
        float lsum = 0.f;
        #pragma unroll
        for (int g = 0; g < 2; g++){
            #pragma unroll
            for (int j = 0; j < 3; j++)
                wmma::store_matrix_sync(scrw + j*16, acc[g*3 + j], 52, wmma::mem_row_major);
            __syncwarp();
            const float4* sr4 = (const float4*)(scrw + row*52 + sub*24);
            const float4* sc4 = (const float4*)(ssc + g*48 + sub*24);
            const float4* sw4 = (const float4*)(sw2s + g*48 + sub*24);
            #pragma unroll
            for (int q = 0; q < 6; q++){
                float4 hv = sr4[q];
                float4 cv = sc4[q];
                float4 wv = sw4[q];
                lsum += wv.x * fmaxf(hv.x + cv.x, 0.f);
                lsum += wv.y * fmaxf(hv.y + cv.y, 0.f);
                lsum += wv.z * fmaxf(hv.z + cv.z, 0.f);
                lsum += wv.w * fmaxf(hv.w + cv.w, 0.f);
            }
            __syncwarp();
        }
        lsum += __shfl_xor_sync(0xffffffffu, lsum, 1);
        if (sub == 0) slog[chunk*128 + wid*16 + row] = lsum;
        __syncthreads();
    }

    int t0 = tid, t1 = tid + 256;
    float lt0 = slog[t0] + sb2[0] + (1.f - mask[b*Ss + t0]) * (-3.402823466e38f);
    float lt1 = slog[t1] + sb2[0] + (1.f - mask[b*Ss + t1]) * (-3.402823466e38f);

    float mx = fmaxf(lt0, lt1);
    #pragma unroll
    for (int d = 16; d > 0; d >>= 1)
        mx = fmaxf(mx, __shfl_xor_sync(0xffffffffu, mx, d));
    if (lane == 0) sred[wid] = mx;
    __syncthreads();
    float bmax = sred[0];
    #pragma unroll
    for (int i = 1; i < 8; i++) bmax = fmaxf(bmax, sred[i]);

    float e0 = expf(lt0 - bmax);
    float e1 = expf(lt1 - bmax);
    float sm = e0 + e1;
    #pragma unroll
    for (int d = 16; d > 0; d >>= 1)
        sm += __shfl_xor_sync(0xffffffffu, sm, d);
    __syncthreads();
    if (lane == 0) sred[wid] = sm;
    __syncthreads();
    float tot = 0.f;
    #pragma unroll
    for (int i = 0; i < 8; i++) tot += sred[i];
    float inv = 1.f / tot;

    __nv_bfloat16 h, l;
    bsplit(e0 * inv, h, l);
    g_pbh[(long)r*Ss + t0] = h; g_pbl[(long)r*Ss + t0] = l;
    bsplit(e1 * inv, h, l);
    g_pbh[(long)r*Ss + t1] = h; g_pbl[(long)r*Ss + t1] = l;
}

// ============================================================
// K3: fp32 -> bf16 hi/lo split (vectorized)
// ============================================================
__global__ __launch_bounds__(256) void conv_split(
    const float* __restrict__ x, __nv_bfloat16* __restrict__ hi,
    __nv_bfloat16* __restrict__ lo, int n4)
{
    int i = blockIdx.x*256 + threadIdx.x;
    if (i >= n4) return;
    float4 v = ((const float4*)x)[i];
    __nv_bfloat16 h0,h1,h2,h3,l0,l1,l2,l3;
    bsplit(v.x,h0,l0); bsplit(v.y,h1,l1); bsplit(v.z,h2,l2); bsplit(v.w,h3,l3);
    __nv_bfloat162 p0, p1;
    p0.x=h0; p0.y=h1; p1.x=h2; p1.y=h3;
    ((__nv_bfloat162*)hi)[2*i]   = p0;
    ((__nv_bfloat162*)hi)[2*i+1] = p1;
    p0.x=l0; p0.y=l1; p1.x=l2; p1.y=l3;
    ((__nv_bfloat162*)lo)[2*i]   = p0;
    ((__nv_bfloat162*)lo)[2*i+1] = p1;
}

// ============================================================
// K4: msg_in = [ctx | Hj | ctx*Hj] -> bf16 hi/lo
// ============================================================
__device__ __forceinline__ void store4(__nv_bfloat16* hp, __nv_bfloat16* lp,
                                       float a, float b, float c, float d)
{
    __nv_bfloat16 h0,h1,h2,h3,l0,l1,l2,l3;
    bsplit(a,h0,l0); bsplit(b,h1,l1); bsplit(c,h2,l2); bsplit(d,h3,l3);
    __nv_bfloat162 p0, p1;
    p0.x=h0; p0.y=h1; p1.x=h2; p1.y=h3;
    ((__nv_bfloat162*)hp)[0] = p0; ((__nv_bfloat162*)hp)[1] = p1;
    p0.x=l0; p0.y=l1; p1.x=l2; p1.y=l3;
    ((__nv_bfloat162*)lp)[0] = p0; ((__nv_bfloat162*)lp)[1] = p1;
}
__global__ __launch_bounds__(256) void msgin_conv(const float* __restrict__ Hj)
{
    int i = blockIdx.x*256 + threadIdx.x;
    if (i >= NROWS*(Hh/4)) return;
    int r = i / (Hh/4);
    int c = (i % (Hh/4)) * 4;
    float4 cv = *(const float4*)&g_ctx[(long)r*Hh + c];
    float4 hv = *(const float4*)&Hj[(long)r*Hh + c];
    long base = (long)r*H3 + c;
    store4(&g_m1h[base],      &g_m1l[base],      cv.x, cv.y, cv.z, cv.w);
    store4(&g_m1h[base+Hh],   &g_m1l[base+Hh],   hv.x, hv.y, hv.z, hv.w);
    store4(&g_m1h[base+2*Hh], &g_m1l[base+2*Hh],
           cv.x*hv.x, cv.y*hv.y, cv.z*hv.z, cv.w*hv.w);
}

// ============================================================
// K5: WMMA GEMM, split-K, raw fp32 partial store.
//  z = batch*KSPLIT + kslice.
// ============================================================
template<bool TRANSB, int KSPLIT>
__global__ __launch_bounds__(256) void gemm_wmma(
    const __nv_bfloat16* __restrict__ Ah, const __nv_bfloat16* __restrict__ Al,
    const __nv_bfloat16* __restrict__ Bh, const __nv_bfloat16* __restrict__ Bl,
    float* __restrict__ Cpart, int N, int K, int ldA, int ldB,
    long strideA, long strideB, long strideC, long partStride)
{
    __shared__ __nv_bfloat16 As[2][128][40];
    __shared__ __nv_bfloat16 Bs[2][5120];   // NT: [n][40] ; NN: [k][136]

    int tid = threadIdx.x;
    int wid = tid >> 5;
    int wr = wid & 3, wc = wid >> 2;
    long row0 = (long)blockIdx.y * 128;
    long col0 = (long)blockIdx.x * 128;

    int zb = blockIdx.z / KSPLIT, zk = blockIdx.z % KSPLIT;
    int kcnt = K / KSPLIT, k0 = zk * kcnt;

    const __nv_bfloat16* APh = Ah + (long)zb * strideA;
    const __nv_bfloat16* APl = Al + (long)zb * strideA;
    const __nv_bfloat16* BPh = Bh + (long)zb * strideB;
    const __nv_bfloat16* BPl = Bl + (long)zb * strideB;
    float* Cb = Cpart + (long)zk * partStride + (long)zb * strideC;

    wmma::fragment<wmma::accumulator,16,16,16,float> acc[2][4];
    #pragma unroll
    for (int i = 0; i < 2; i++)
        #pragma unroll
        for (int j = 0; j < 4; j++) wmma::fill_fragment(acc[i][j], 0.f);

    #pragma unroll 1
    for (int kc = k0; kc < k0 + kcnt; kc += 32){
        #pragma unroll
        for (int t = tid; t < 512; t += 256){
            int r = t >> 2, seg = t & 3;
            long off = (row0 + r)*(long)ldA + kc + seg*8;
            *(float4*)&As[0][r][seg*8] = *(const float4*)(APh + off);
            *(float4*)&As[1][r][seg*8] = *(const float4*)(APl + off);
        }
        if (TRANSB){
            #pragma unroll
            for (int t = tid; t < 512; t += 256){
                int r = t >> 2, seg = t & 3;
                long off = (col0 + r)*(long)ldB + kc + seg*8;
                *(float4*)&Bs[0][r*40 + seg*8] = *(const float4*)(BPh + off);
                *(float4*)&Bs[1][r*40 + seg*8] = *(const float4*)(BPl + off);
            }
        } else {
            #pragma unroll
            for (int t = tid; t < 512; t += 256){
                int r = t >> 4, seg = t & 15;
                long off = (long)(kc + r)*ldB + col0 + seg*8;
                *(float4*)&Bs[0][r*136 + seg*8] = *(const float4*)(BPh + off);
                *(float4*)&Bs[1][r*136 + seg*8] = *(const float4*)(BPl + off);
            }
        }
        __syncthreads();

        #pragma unroll
        for (int ks = 0; ks < 2; ks++){
            wmma::fragment<wmma::matrix_a,16,16,16,__nv_bfloat16,wmma::row_major> afh[2], afl[2];
            #pragma unroll
            for (int i = 0; i < 2; i++){
                wmma::load_matrix_sync(afh[i], &As[0][wr*32 + i*16][ks*16], 40);
                wmma::load_matrix_sync(afl[i], &As[1][wr*32 + i*16][ks*16], 40);
            }
            if (TRANSB){
                #pragma unroll
                for (int j = 0; j < 4; j++){
                    wmma::fragment<wmma::matrix_b,16,16,16,__nv_bfloat16,wmma::col_major> bfh, bfl;
                    int nb = wc*64 + j*16;
                    wmma::load_matrix_sync(bfh, &Bs[0][nb*40 + ks*16], 40);
                    wmma::load_matrix_sync(bfl, &Bs[1][nb*40 + ks*16], 40);
                    #pragma unroll
                    for (int i = 0; i < 2; i++){
                        wmma::mma_sync(acc[i][j], afh[i], bfh, acc[i][j]);
                        wmma::mma_sync(acc[i][j], afh[i], bfl, acc[i][j]);
                        wmma::mma_sync(acc[i][j], afl[i], bfh, acc[i][j]);
                    }
                }
            } else {
                #pragma unroll
                for (int j = 0; j < 4; j++){
                    wmma::fragment<wmma::matrix_b,16,16,16,__nv_bfloat16,wmma::row_major> bfh, bfl;
                    int nb = wc*64 + j*16;
                    wmma::load_matrix_sync(bfh, &Bs[0][(ks*16)*136 + nb], 136);
                    wmma::load_matrix_sync(bfl, &Bs[1][(ks*16)*136 + nb], 136);
                    #pragma unroll
                    for (int i = 0; i < 2; i++){
                        wmma::mma_sync(acc[i][j], afh[i], bfh, acc[i][j]);
                        wmma::mma_sync(acc[i][j], afh[i], bfl, acc[i][j]);
                        wmma::mma_sync(acc[i][j], afl[i], bfh, acc[i][j]);
                    }
                }
            }
        }
        __syncthreads();
    }

    // raw fp32 partial store
    #pragma unroll
    for (int i = 0; i < 2; i++)
        #pragma unroll
        for (int j = 0; j < 4; j++){
            float* cp = Cb + (row0 + wr*32 + i*16)*(long)N + col0 + wc*64 + j*16;
            wmma::store_matrix_sync(cp, acc[i][j], N, wmma::mem_row_major);
        }
}

// ============================================================
// K6: split-K reduce + epilogues
//  MODE 0: raw sum -> fp32 (ctx)
//  MODE 1: relu(sum + bias) -> bf16 hi/lo (hid)
//  MODE 2: (sum + bias) * alpha -> fp32 (out)
// ============================================================
template<int NS, int MODE>
__global__ __launch_bounds__(256) void reduce_ns(
    const float* __restrict__ p, long partStride,
    float* __restrict__ outf,
    __nv_bfloat16* __restrict__ oh, __nv_bfloat16* __restrict__ ol,
    const float* __restrict__ bias, const float* __restrict__ alpha_p,
    int N, long total)
{
    long i4 = ((long)blockIdx.x * 256 + threadIdx.x) * 4;
    if (i4 >= total) return;
    float4 s = *(const float4*)&p[i4];
    #pragma unroll
    for (int n = 1; n < NS; n++){
        float4 v = *(const float4*)&p[n*partStride + i4];
        s.x += v.x; s.y += v.y; s.z += v.z; s.w += v.w;
    }
    if (MODE >= 1){
        int col = (int)(i4 % N);
        float4 bi = *(const float4*)&bias[col];
        s.x += bi.x; s.y += bi.y; s.z += bi.z; s.w += bi.w;
    }
    if (MODE == 1){
        s.x = fmaxf(s.x, 0.f); s.y = fmaxf(s.y, 0.f);
        s.z = fmaxf(s.z, 0.f); s.w = fmaxf(s.w, 0.f);
        __nv_bfloat16 h0,h1,h2,h3,l0,l1,l2,l3;
        bsplit(s.x,h0,l0); bsplit(s.y,h1,l1); bsplit(s.z,h2,l2); bsplit(s.w,h3,l3);
        __nv_bfloat162 ph0, ph1, pl0, pl1;
        ph0.x=h0; ph0.y=h1; ph1.x=h2; ph1.y=h3;
        pl0.x=l0; pl0.y=l1; pl1.x=l2; pl1.y=l3;
        *(__nv_bfloat162*)&oh[i4]   = ph0;
        *(__nv_bfloat162*)&oh[i4+2] = ph1;
        *(__nv_bfloat162*)&ol[i4]   = pl0;
        *(__nv_bfloat162*)&ol[i4+2] = pl1;
    } else {
        if (MODE == 2){
            float a = __ldg(alpha_p);
            s.x *= a; s.y *= a; s.z *= a; s.w *= a;
        }
        *(float4*)&outf[i4] = s;
    }
}

// ============================================================
extern "C" void kernel_launch(void* const* d_in, const int* in_sizes, int n_in,
                              void* d_out, int out_size)
{
    const float* Hj   = (const float*)d_in[0];
    const float* Hi   = (const float*)d_in[1];
    const float* mask = (const float*)d_in[2];
    const float* pjw  = (const float*)d_in[3];
    const float* piw  = (const float*)d_in[4];
    const float* sw1  = (const float*)d_in[5];
    const float* sb1  = (const float*)d_in[6];
    const float* sw2  = (const float*)d_in[7];
    const float* sb2  = (const float*)d_in[8];
    const float* vw1  = (const float*)d_in[9];
    const float* vb1  = (const float*)d_in[10];
    const float* vw2  = (const float*)d_in[11];
    const float* vb2  = (const float*)d_in[12];
    const float* alpha= (const float*)d_in[13];
    float* out = (float*)d_out;

    void *pctx, *ppbh, *ppbl, *phih, *phil, *pm1h, *pm1l;
    void *pw1h, *pw1l, *phdh, *phdl, *pw2h, *pw2l;
    void *ppc, *pp1, *pp2;
    cudaGetSymbolAddress(&pctx, g_ctx);
    cudaGetSymbolAddress(&ppbh, g_pbh);  cudaGetSymbolAddress(&ppbl, g_pbl);
    cudaGetSymbolAddress(&phih, g_hih);  cudaGetSymbolAddress(&phil, g_hil);
    cudaGetSymbolAddress(&pm1h, g_m1h);  cudaGetSymbolAddress(&pm1l, g_m1l);
    cudaGetSymbolAddress(&pw1h, g_w1h);  cudaGetSymbolAddress(&pw1l, g_w1l);
    cudaGetSymbolAddress(&phdh, g_hidh); cudaGetSymbolAddress(&phdl, g_hidl);
    cudaGetSymbolAddress(&pw2h, g_w2h);  cudaGetSymbolAddress(&pw2l, g_w2l);
    cudaGetSymbolAddress(&ppc, g_partc);
    cudaGetSymbolAddress(&pp1, g_part1);
    cudaGetSymbolAddress(&pp2, g_part2);

    cudaFuncSetAttribute(pair_wmma, cudaFuncAttributeMaxDynamicSharedMemorySize, PAIR_SMEM);

    // 0: proj
    proj_kernel<<<NROWS, 256>>>(Hj, Hi, pjw, piw, sw1);
    // 1: W' precompute
    wsplit_pair<<<(96*88 + 255)/256, 256>>>(sw1);
    // 2: Hi -> bf16 hi/lo
    conv_split<<<(NROWS*Hh/4 + 255)/256, 256>>>(Hi, (__nv_bfloat16*)phih,
                                                (__nv_bfloat16*)phil, NROWS*Hh/4);
    // 3: pair (profiled slot)
    pair_wmma<<<NROWS, 256, PAIR_SMEM>>>(sb1, sw2, sb2, mask);
    // 4: ctx partials = probs @ Hi  [NN, batched, split-K=4]
    {
        dim3 g(Hh/128, Ss/128, Bb*4);
        gemm_wmma<false,4><<<g, 256>>>(
            (const __nv_bfloat16*)ppbh, (const __nv_bfloat16*)ppbl,
            (const __nv_bfloat16*)phih, (const __nv_bfloat16*)phil,
            (float*)ppc, Hh, Ss, Ss, Hh,
            (long)Ss*Ss, (long)Ss*Hh, (long)Ss*Hh, 4L*Ss*Hh);
    }
    // 5: ctx reduce
    {
        long total = (long)NROWS*Hh;
        reduce_ns<4,0><<<(int)((total/4 + 255)/256), 256>>>(
            (const float*)ppc, 4L*Ss*Hh, (float*)pctx,
            nullptr, nullptr, nullptr, nullptr, Hh, total);
    }
    // 6: msg_in -> bf16 hi/lo
    msgin_conv<<<(NROWS*(Hh/4) + 255)/256, 256>>>(Hj);
    // 7: vw1 -> bf16 hi/lo
    conv_split<<<(OH*H3/4 + 255)/256, 256>>>(vw1, (__nv_bfloat16*)pw1h,
                                             (__nv_bfloat16*)pw1l, OH*H3/4);
    // 8: gemm1 partials  [NT, split-K=3]
    {
        dim3 g(OH/128, NROWS/128, 3);
        gemm_wmma<true,3><<<g, 256>>>(
            (const __nv_bfloat16*)pm1h, (const __nv_bfloat16*)pm1l,
            (const __nv_bfloat16*)pw1h, (const __nv_bfloat16*)pw1l,
            (float*)pp1, OH, H3, H3, H3,
            0, 0, 0, (long)NROWS*OH);
    }
    // 9: hid reduce (bias+relu -> bf16 split)
    {
        long total = (long)NROWS*OH;
        reduce_ns<3,1><<<(int)((total/4 + 255)/256), 256>>>(
            (const float*)pp1, (long)NROWS*OH, nullptr,
            (__nv_bfloat16*)phdh, (__nv_bfloat16*)phdl, vb1, nullptr, OH, total);
    }
    // 10: vw2 -> bf16 hi/lo
    conv_split<<<(Hh*OH/4 + 255)/256, 256>>>(vw2, (__nv_bfloat16*)pw2h,
                                             (__nv_bfloat16*)pw2l, Hh*OH/4);
    // 11: gemm2 partials  [NT, split-K=3]
    {
        dim3 g(Hh/128, NROWS/128, 3);
        gemm_wmma<true,3><<<g, 256>>>(
            (const __nv_bfloat16*)phdh, (const __nv_bfloat16*)phdl,
            (const __nv_bfloat16*)pw2h, (const __nv_bfloat16*)pw2l,
            (float*)pp2, Hh, OH, OH, OH,
            0, 0, 0, (long)NROWS*Hh);
    }
    // 12: out reduce (bias, alpha)
    {
        long total = (long)NROWS*Hh;
        reduce_ns<3,2><<<(int)((total/4 + 255)/256), 256>>>(
            (const float*)pp2, (long)NROWS*Hh, out,
            nullptr, nullptr, vb2, alpha, Hh, total);
    }
    (void)in_sizes; (void)n_in; (void)out_size;
}

// round 12
// speedup vs baseline: 1.6041x; 1.1689x over previous
#include <cuda_runtime.h>
#include <cuda_bf16.h>
#include <mma.h>
#include <math.h>
#include <cstdint>

using namespace nvcuda;

#define Bb 4
#define Ss 512
#define Hh 768
#define Dd 24
#define Mm 96
#define OH 768
#define H3 2304
#define NROWS (Bb*Ss)   // 2048

typedef unsigned long long ull;

// ---- scratch ----
__device__ __align__(16) float g_Zj[NROWS*Dd];
__device__ __align__(16) float g_Zi[NROWS*Dd];
__device__ __align__(16) float g_Aj[NROWS*Mm];
__device__ __align__(16) float g_ctx[(long)NROWS*Hh];
__device__ __align__(16) __nv_bfloat16 g_Wph[96*88];
// bf16 hi/lo operands for tensor-core GEMMs
__device__ __align__(16) __nv_bfloat16 g_pbh[(long)Bb*Ss*Ss];
__device__ __align__(16) __nv_bfloat16 g_pbl[(long)Bb*Ss*Ss];
__device__ __align__(16) __nv_bfloat16 g_hih[(long)NROWS*Hh];
__device__ __align__(16) __nv_bfloat16 g_hil[(long)NROWS*Hh];
__device__ __align__(16) __nv_bfloat16 g_m1h[(long)NROWS*H3];
__device__ __align__(16) __nv_bfloat16 g_m1l[(long)NROWS*H3];
__device__ __align__(16) __nv_bfloat16 g_w1h[(long)OH*H3];
__device__ __align__(16) __nv_bfloat16 g_w1l[(long)OH*H3];
__device__ __align__(16) __nv_bfloat16 g_hidh[(long)NROWS*OH];
__device__ __align__(16) __nv_bfloat16 g_hidl[(long)NROWS*OH];
__device__ __align__(16) __nv_bfloat16 g_w2h[(long)Hh*OH];
__device__ __align__(16) __nv_bfloat16 g_w2l[(long)Hh*OH];
// split-K partial buffers (fp32)
__device__ __align__(16) float g_partc[4L*Bb*Ss*Hh];
__device__ __align__(16) float g_part1[3L*NROWS*OH];
__device__ __align__(16) float g_part2[3L*NROWS*Hh];

// bf16 hi/lo split
__device__ __forceinline__ void bsplit(float v, __nv_bfloat16& h, __nv_bfloat16& l){
    h = __float2bfloat16(v);
    l = __float2bfloat16(v - __bfloat162float(h));
}
__device__ __forceinline__ unsigned packh(float a, float b){
    __nv_bfloat162 p;
    p.x = __float2bfloat16(a);
    p.y = __float2bfloat16(b);
    return *(unsigned*)&p;
}

// ---- PTX mma helpers (base ISA, sm_80+) ----
__device__ __forceinline__ unsigned smem_cast(const void* p){
    return (unsigned)__cvta_generic_to_shared(p);
}
__device__ __forceinline__ void ldsm_x4(unsigned addr, unsigned& r0, unsigned& r1,
                                        unsigned& r2, unsigned& r3){
    asm volatile("ldmatrix.sync.aligned.m8n8.x4.shared.b16 {%0,%1,%2,%3}, [%4];"
        : "=r"(r0), "=r"(r1), "=r"(r2), "=r"(r3) : "r"(addr));
}
__device__ __forceinline__ void mma16816(float* d, const unsigned* a,
                                         unsigned b0, unsigned b1){
    asm volatile(
        "mma.sync.aligned.m16n8k16.row.col.f32.bf16.bf16.f32 "
        "{%0,%1,%2,%3}, {%4,%5,%6,%7}, {%8,%9}, {%0,%1,%2,%3};"
        : "+f"(d[0]), "+f"(d[1]), "+f"(d[2]), "+f"(d[3])
        : "r"(a[0]), "r"(a[1]), "r"(a[2]), "r"(a[3]), "r"(b0), "r"(b1));
}

// ============================================================
// K0: precompute W' = [Wc | Wd | Wb | 0] (96 x 88) bf16
// ============================================================
__global__ __launch_bounds__(256) void wsplit_pair(const float* __restrict__ sw1)
{
    int i = blockIdx.x*256 + threadIdx.x;
    if (i >= 96*88) return;
    int m = i / 88, k = i % 88;
    float wv = 0.f;
    if (k < 24)      wv = sw1[m*96 + 48 + k];
    else if (k < 48) wv = sw1[m*96 + 72 + (k-24)];
    else if (k < 72) wv = sw1[m*96 + 24 + (k-48)];
    g_Wph[i] = __float2bfloat16(wv);
}

// ============================================================
// K1: projections + rank-1 term Aj = Wa @ zj
// ============================================================
__global__ __launch_bounds__(256) void proj_kernel(
    const float* __restrict__ Hj, const float* __restrict__ Hi,
    const float* __restrict__ pjw, const float* __restrict__ piw,
    const float* __restrict__ sw1)
{
    int r = blockIdx.x;
    __shared__ float shj[Hh], shi[Hh], szj[Dd];
    int tid = threadIdx.x;
    for (int i = tid; i < Hh; i += 256){
        shj[i] = Hj[(long)r*Hh + i];
        shi[i] = Hi[(long)r*Hh + i];
    }
    __syncthreads();
    int o = tid >> 3, g = tid & 7;
    if (o < Dd){
        float pj = 0.f, pi = 0.f;
        for (int h = g; h < Hh; h += 8){
            pj += shj[h] * pjw[o*Hh + h];
            pi += shi[h] * piw[o*Hh + h];
        }
        #pragma unroll
        for (int d = 4; d > 0; d >>= 1){
            pj += __shfl_down_sync(0xffffffffu, pj, d, 8);
            pi += __shfl_down_sync(0xffffffffu, pi, d, 8);
        }
        if (g == 0){
            szj[o] = pj;
            g_Zj[r*Dd + o] = pj; g_Zi[r*Dd + o] = pi;
        }
    }
    __syncthreads();
    if (tid < Mm){
        float a = 0.f;
        #pragma unroll
        for (int d = 0; d < Dd; d++)
            a += sw1[tid*96 + d] * szj[d];
        g_Aj[r*Mm + tid] = a;
    }
}

// ============================================================
// K2: pair logits v6 — PTX mma.m16n8k16, in-register reduce.
//  256 threads / 8 warps; warp owns a 16-row t-tile per chunk.
//  acc[12] n-frags of 8 cols; epilogue entirely in registers.
// ============================================================
#define POFF_WH   0                       // 96*88*2 = 16896
#define POFF_F    16896                   // 128*88*2 = 22528 -> 39424
#define POFF_SLOG 39424                   // 512*4 -> 41472
#define POFF_SZJ  41472                   // -> 41600 (padded)
#define POFF_SCW  41600                   // 96 float2 = 768 -> 42368
#define POFF_SRED 42368                   // 8*4 -> 42400
#define PAIR_SMEM 42496

#define FCOLV(c) ((c) < 24 ? szj[(c)]*za[(c)] : \
                  (c) < 48 ? fabsf(szj[(c)-24]-za[(c)-24]) : \
                  (c) < 72 ? za[(c)-48] : 0.f)

__global__ __launch_bounds__(256) void pair_wmma(
    const float* __restrict__ sb1,
    const float* __restrict__ sw2v, const float* __restrict__ sb2,
    const float* __restrict__ mask)
{
    extern __shared__ char ps[];
    __nv_bfloat16* Wh = (__nv_bfloat16*)(ps + POFF_WH);
    __nv_bfloat16* Fh = (__nv_bfloat16*)(ps + POFF_F);
    float*  slog = (float*)(ps + POFF_SLOG);
    float*  szj  = (float*)(ps + POFF_SZJ);
    float2* scw  = (float2*)(ps + POFF_SCW);    // (ssc, w2) interleaved
    float*  sred = (float*)(ps + POFF_SRED);

    int r = blockIdx.x, b = r >> 9;
    int tid = threadIdx.x, wid = tid >> 5, lane = tid & 31;

    // load precomputed W' (1056 uint4)
    for (int i = tid; i < 1056; i += 256)
        ((uint4*)Wh)[i] = ((const uint4*)g_Wph)[i];
    if (tid < Dd) szj[tid] = g_Zj[r*Dd + tid];
    if (tid < Mm)
        scw[tid] = make_float2(g_Aj[r*Mm + tid] + sb1[tid], sw2v[tid]);
    __syncthreads();

    // per-lane epilogue coefficients: cols m = jf*8 + (lane&3)*2 + {0,1}
    float4 cw[12];
    {
        int c0 = (lane & 3) * 2;
        #pragma unroll
        for (int jf = 0; jf < 12; jf++)
            cw[jf] = *(const float4*)&scw[jf*8 + c0];
    }

    unsigned sF = smem_cast(Fh);
    unsigned sW = smem_cast(Wh);
    int bhalf = tid >> 7;
    int brow  = tid & 127;
    int l16   = lane & 15;
    int lhi8  = (lane >> 4) * 8;

    #pragma unroll 1
    for (int chunk = 0; chunk < 4; chunk++){
        // ---- build F (bf16, vectorized STS.128) ----
        {
            int t = chunk*128 + brow;
            const float4* zi4 = (const float4*)&g_Zi[(long)(b*Ss + t)*Dd];
            float za[24];
            #pragma unroll
            for (int q = 0; q < 6; q++){
                float4 v4 = __ldg(&zi4[q]);
                za[q*4+0]=v4.x; za[q*4+1]=v4.y; za[q*4+2]=v4.z; za[q*4+3]=v4.w;
            }
            if (bhalf == 0){
                uint4* dh = (uint4*)&Fh[brow*88];
                #pragma unroll
                for (int q = 0; q < 5; q++){
                    unsigned h4[4];
                    #pragma unroll
                    for (int e = 0; e < 4; e++){
                        int c = q*8 + e*2;
                        h4[e] = packh(FCOLV(c), FCOLV(c+1));
                    }
                    dh[q] = make_uint4(h4[0],h4[1],h4[2],h4[3]);
                }
            } else {
                uint4* dh = (uint4*)&Fh[brow*88 + 40];
                #pragma unroll
                for (int q = 0; q < 6; q++){
                    unsigned h4[4];
                    #pragma unroll
                    for (int e = 0; e < 4; e++){
                        int c = 40 + q*8 + e*2;
                        h4[e] = packh(FCOLV(c), FCOLV(c+1));
                    }
                    dh[q] = make_uint4(h4[0],h4[1],h4[2],h4[3]);
                }
            }
        }
        __syncthreads();

        // ---- MMA: 12 n-frags x 5 k-steps, acc in registers ----
        float acc[12][4];
        #pragma unroll
        for (int jf = 0; jf < 12; jf++)
            #pragma unroll
            for (int e = 0; e < 4; e++) acc[jf][e] = 0.f;

        int rowbase = wid * 16;
        #pragma unroll
        for (int k = 0; k < 5; k++){
            unsigned a[4];
            unsigned aaddr = sF + (unsigned)(((rowbase + l16)*88 + k*16 + lhi8) * 2);
            ldsm_x4(aaddr, a[0], a[1], a[2], a[3]);
            #pragma unroll
            for (int j2 = 0; j2 < 6; j2++){
                unsigned bq[4];
                unsigned baddr = sW + (unsigned)(((j2*16 + l16)*88 + k*16 + lhi8) * 2);
                ldsm_x4(baddr, bq[0], bq[1], bq[2], bq[3]);
                mma16816(acc[2*j2],     a, bq[0], bq[2]);
                mma16816(acc[2*j2 + 1], a, bq[1], bq[3]);
            }
        }

        // ---- in-register reduce: logit rows (lane>>2) and +8 ----
        float s0 = 0.f, s1 = 0.f;
        #pragma unroll
        for (int jf = 0; jf < 12; jf++){
            float4 c = cw[jf];
            s0 += c.y * fmaxf(acc[jf][0] + c.x, 0.f)
                + c.w * fmaxf(acc[jf][1] + c.z, 0.f);
            s1 += c.y * fmaxf(acc[jf][2] + c.x, 0.f)
                + c.w * fmaxf(acc[jf][3] + c.z, 0.f);
        }
        s0 += __shfl_xor_sync(0xffffffffu, s0, 1);
        s0 += __shfl_xor_sync(0xffffffffu, s0, 2);
        s1 += __shfl_xor_sync(0xffffffffu, s1, 1);
        s1 += __shfl_xor_sync(0xffffffffu, s1, 2);
        if ((lane & 3) == 0){
            int row = lane >> 2;
            slog[chunk*128 + wid*16 + row]     = s0;
            slog[chunk*128 + wid*16 + 8 + row] = s1;
        }
        __syncthreads();   // F reads done before next chunk's build
    }

    // ---- masked softmax over slog[512] ----
    int t0 = tid, t1 = tid + 256;
    float lt0 = slog[t0] + sb2[0] + (1.f - mask[b*Ss + t0]) * (-3.402823466e38f);
    float lt1 = slog[t1] + sb2[0] + (1.f - mask[b*Ss + t1]) * (-3.402823466e38f);

    float mx = fmaxf(lt0, lt1);
    #pragma unroll
    for (int d = 16; d > 0; d >>= 1)
        mx = fmaxf(mx, __shfl_xor_sync(0xffffffffu, mx, d));
    if (lane == 0) sred[wid] = mx;
    __syncthreads();
    float bmax = sred[0];
    #pragma unroll
    for (int i = 1; i < 8; i++) bmax = fmaxf(bmax, sred[i]);

    float e0 = expf(lt0 - bmax);
    float e1 = expf(lt1 - bmax);
    float sm = e0 + e1;
    #pragma unroll
    for (int d = 16; d > 0; d >>= 1)
        sm += __shfl_xor_sync(0xffffffffu, sm, d);
    __syncthreads();
    if (lane == 0) sred[wid] = sm;
    __syncthreads();
    float tot = 0.f;
    #pragma unroll
    for (int i = 0; i < 8; i++) tot += sred[i];
    float inv = 1.f / tot;

    __nv_bfloat16 h, l;
    bsplit(e0 * inv, h, l);
    g_pbh[(long)r*Ss + t0] = h; g_pbl[(long)r*Ss + t0] = l;
    bsplit(e1 * inv, h, l);
    g_pbh[(long)r*Ss + t1] = h; g_pbl[(long)r*Ss + t1] = l;
}

// ============================================================
// K3: fp32 -> bf16 hi/lo split (vectorized)
// ============================================================
__global__ __launch_bounds__(256) void conv_split(
    const float* __restrict__ x, __nv_bfloat16* __restrict__ hi,
    __nv_bfloat16* __restrict__ lo, int n4)
{
    int i = blockIdx.x*256 + threadIdx.x;
    if (i >= n4) return;
    float4 v = ((const float4*)x)[i];
    __nv_bfloat16 h0,h1,h2,h3,l0,l1,l2,l3;
    bsplit(v.x,h0,l0); bsplit(v.y,h1,l1); bsplit(v.z,h2,l2); bsplit(v.w,h3,l3);
    __nv_bfloat162 p0, p1;
    p0.x=h0; p0.y=h1; p1.x=h2; p1.y=h3;
    ((__nv_bfloat162*)hi)[2*i]   = p0;
    ((__nv_bfloat162*)hi)[2*i+1] = p1;
    p0.x=l0; p0.y=l1; p1.x=l2; p1.y=l3;
    ((__nv_bfloat162*)lo)[2*i]   = p0;
    ((__nv_bfloat162*)lo)[2*i+1] = p1;
}

// ============================================================
// K4: msg_in = [ctx | Hj | ctx*Hj] -> bf16 hi/lo
// ============================================================
__device__ __forceinline__ void store4(__nv_bfloat16* hp, __nv_bfloat16* lp,
                                       float a, float b, float c, float d)
{
    __nv_bfloat16 h0,h1,h2,h3,l0,l1,l2,l3;
    bsplit(a,h0,l0); bsplit(b,h1,l1); bsplit(c,h2,l2); bsplit(d,h3,l3);
    __nv_bfloat162 p0, p1;
    p0.x=h0; p0.y=h1; p1.x=h2; p1.y=h3;
    ((__nv_bfloat162*)hp)[0] = p0; ((__nv_bfloat162*)hp)[1] = p1;
    p0.x=l0; p0.y=l1; p1.x=l2; p1.y=l3;
    ((__nv_bfloat162*)lp)[0] = p0; ((__nv_bfloat162*)lp)[1] = p1;
}
__global__ __launch_bounds__(256) void msgin_conv(const float* __restrict__ Hj)
{
    int i = blockIdx.x*256 + threadIdx.x;
    if (i >= NROWS*(Hh/4)) return;
    int r = i / (Hh/4);
    int c = (i % (Hh/4)) * 4;
    float4 cv = *(const float4*)&g_ctx[(long)r*Hh + c];
    float4 hv = *(const float4*)&Hj[(long)r*Hh + c];
    long base = (long)r*H3 + c;
    store4(&g_m1h[base],      &g_m1l[base],      cv.x, cv.y, cv.z, cv.w);
    store4(&g_m1h[base+Hh],   &g_m1l[base+Hh],   hv.x, hv.y, hv.z, hv.w);
    store4(&g_m1h[base+2*Hh], &g_m1l[base+2*Hh],
           cv.x*hv.x, cv.y*hv.y, cv.z*hv.z, cv.w*hv.w);
}

// ============================================================
// K5: WMMA GEMM, split-K, raw fp32 partial store.
// ============================================================
template<bool TRANSB, int KSPLIT>
__global__ __launch_bounds__(256) void gemm_wmma(
    const __nv_bfloat16* __restrict__ Ah, const __nv_bfloat16* __restrict__ Al,
    const __nv_bfloat16* __restrict__ Bh, const __nv_bfloat16* __restrict__ Bl,
    float* __restrict__ Cpart, int N, int K, int ldA, int ldB,
    long strideA, long strideB, long strideC, long partStride)
{
    __shared__ __nv_bfloat16 As[2][128][40];
    __shared__ __nv_bfloat16 Bs[2][5120];   // NT: [n][40] ; NN: [k][136]

    int tid = threadIdx.x;
    int wid = tid >> 5;
    int wr = wid & 3, wc = wid >> 2;
    long row0 = (long)blockIdx.y * 128;
    long col0 = (long)blockIdx.x * 128;

    int zb = blockIdx.z / KSPLIT, zk = blockIdx.z % KSPLIT;
    int kcnt = K / KSPLIT, k0 = zk * kcnt;

    const __nv_bfloat16* APh = Ah + (long)zb * strideA;
    const __nv_bfloat16* APl = Al + (long)zb * strideA;
    const __nv_bfloat16* BPh = Bh + (long)zb * strideB;
    const __nv_bfloat16* BPl = Bl + (long)zb * strideB;
    float* Cb = Cpart + (long)zk * partStride + (long)zb * strideC;

    wmma::fragment<wmma::accumulator,16,16,16,float> acc[2][4];
    #pragma unroll
    for (int i = 0; i < 2; i++)
        #pragma unroll
        for (int j = 0; j < 4; j++) wmma::fill_fragment(acc[i][j], 0.f);

    #pragma unroll 1
    for (int kc = k0; kc < k0 + kcnt; kc += 32){
        #pragma unroll
        for (int t = tid; t < 512; t += 256){
            int r = t >> 2, seg = t & 3;
            long off = (row0 + r)*(long)ldA + kc + seg*8;
            *(float4*)&As[0][r][seg*8] = *(const float4*)(APh + off);
            *(float4*)&As[1][r][seg*8] = *(const float4*)(APl + off);
        }
        if (TRANSB){
            #pragma unroll
            for (int t = tid; t < 512; t += 256){
                int r = t >> 2, seg = t & 3;
                long off = (col0 + r)*(long)ldB + kc + seg*8;
                *(float4*)&Bs[0][r*40 + seg*8] = *(const float4*)(BPh + off);
                *(float4*)&Bs[1][r*40 + seg*8] = *(const float4*)(BPl + off);
            }
        } else {
            #pragma unroll
            for (int t = tid; t < 512; t += 256){
                int r = t >> 4, seg = t & 15;
                long off = (long)(kc + r)*ldB + col0 + seg*8;
                *(float4*)&Bs[0][r*136 + seg*8] = *(const float4*)(BPh + off);
                *(float4*)&Bs[1][r*136 + seg*8] = *(const float4*)(BPl + off);
            }
        }
        __syncthreads();

        #pragma unroll
        for (int ks = 0; ks < 2; ks++){
            wmma::fragment<wmma::matrix_a,16,16,16,__nv_bfloat16,wmma::row_major> afh[2], afl[2];
            #pragma unroll
            for (int i = 0; i < 2; i++){
                wmma::load_matrix_sync(afh[i], &As[0][wr*32 + i*16][ks*16], 40);
                wmma::load_matrix_sync(afl[i], &As[1][wr*32 + i*16][ks*16], 40);
            }
            if (TRANSB){
                #pragma unroll
                for (int j = 0; j < 4; j++){
                    wmma::fragment<wmma::matrix_b,16,16,16,__nv_bfloat16,wmma::col_major> bfh, bfl;
                    int nb = wc*64 + j*16;
                    wmma::load_matrix_sync(bfh, &Bs[0][nb*40 + ks*16], 40);
                    wmma::load_matrix_sync(bfl, &Bs[1][nb*40 + ks*16], 40);
                    #pragma unroll
                    for (int i = 0; i < 2; i++){
                        wmma::mma_sync(acc[i][j], afh[i], bfh, acc[i][j]);
                        wmma::mma_sync(acc[i][j], afh[i], bfl, acc[i][j]);
                        wmma::mma_sync(acc[i][j], afl[i], bfh, acc[i][j]);
                    }
                }
            } else {
                #pragma unroll
                for (int j = 0; j < 4; j++){
                    wmma::fragment<wmma::matrix_b,16,16,16,__nv_bfloat16,wmma::row_major> bfh, bfl;
                    int nb = wc*64 + j*16;
                    wmma::load_matrix_sync(bfh, &Bs[0][(ks*16)*136 + nb], 136);
                    wmma::load_matrix_sync(bfl, &Bs[1][(ks*16)*136 + nb], 136);
                    #pragma unroll
                    for (int i = 0; i < 2; i++){
                        wmma::mma_sync(acc[i][j], afh[i], bfh, acc[i][j]);
                        wmma::mma_sync(acc[i][j], afh[i], bfl, acc[i][j]);
                        wmma::mma_sync(acc[i][j], afl[i], bfh, acc[i][j]);
                    }
                }
            }
        }
        __syncthreads();
    }

    #pragma unroll
    for (int i = 0; i < 2; i++)
        #pragma unroll
        for (int j = 0; j < 4; j++){
            float* cp = Cb + (row0 + wr*32 + i*16)*(long)N + col0 + wc*64 + j*16;
            wmma::store_matrix_sync(cp, acc[i][j], N, wmma::mem_row_major);
        }
}

// ============================================================
// K6: split-K reduce + epilogues
// ============================================================
template<int NS, int MODE>
__global__ __launch_bounds__(256) void reduce_ns(
    const float* __restrict__ p, long partStride,
    float* __restrict__ outf,
    __nv_bfloat16* __restrict__ oh, __nv_bfloat16* __restrict__ ol,
    const float* __restrict__ bias, const float* __restrict__ alpha_p,
    int N, long total)
{
    long i4 = ((long)blockIdx.x * 256 + threadIdx.x) * 4;
    if (i4 >= total) return;
    float4 s = *(const float4*)&p[i4];
    #pragma unroll
    for (int n = 1; n < NS; n++){
        float4 v = *(const float4*)&p[n*partStride + i4];
        s.x += v.x; s.y += v.y; s.z += v.z; s.w += v.w;
    }
    if (MODE >= 1){
        int col = (int)(i4 % N);
        float4 bi = *(const float4*)&bias[col];
        s.x += bi.x; s.y += bi.y; s.z += bi.z; s.w += bi.w;
    }
    if (MODE == 1){
        s.x = fmaxf(s.x, 0.f); s.y = fmaxf(s.y, 0.f);
        s.z = fmaxf(s.z, 0.f); s.w = fmaxf(s.w, 0.f);
        __nv_bfloat16 h0,h1,h2,h3,l0,l1,l2,l3;
        bsplit(s.x,h0,l0); bsplit(s.y,h1,l1); bsplit(s.z,h2,l2); bsplit(s.w,h3,l3);
        __nv_bfloat162 ph0, ph1, pl0, pl1;
        ph0.x=h0; ph0.y=h1; ph1.x=h2; ph1.y=h3;
        pl0.x=l0; pl0.y=l1; pl1.x=l2; pl1.y=l3;
        *(__nv_bfloat162*)&oh[i4]   = ph0;
        *(__nv_bfloat162*)&oh[i4+2] = ph1;
        *(__nv_bfloat162*)&ol[i4]   = pl0;
        *(__nv_bfloat162*)&ol[i4+2] = pl1;
    } else {
        if (MODE == 2){
            float a = __ldg(alpha_p);
            s.x *= a; s.y *= a; s.z *= a; s.w *= a;
        }
        *(float4*)&outf[i4] = s;
    }
}

// ============================================================
extern "C" void kernel_launch(void* const* d_in, const int* in_sizes, int n_in,
                              void* d_out, int out_size)
{
    const float* Hj   = (const float*)d_in[0];
    const float* Hi   = (const float*)d_in[1];
    const float* mask = (const float*)d_in[2];
    const float* pjw  = (const float*)d_in[3];
    const float* piw  = (const float*)d_in[4];
    const float* sw1  = (const float*)d_in[5];
    const float* sb1  = (const float*)d_in[6];
    const float* sw2  = (const float*)d_in[7];
    const float* sb2  = (const float*)d_in[8];
    const float* vw1  = (const float*)d_in[9];
    const float* vb1  = (const float*)d_in[10];
    const float* vw2  = (const float*)d_in[11];
    const float* vb2  = (const float*)d_in[12];
    const float* alpha= (const float*)d_in[13];
    float* out = (float*)d_out;

    void *pctx, *ppbh, *ppbl, *phih, *phil, *pm1h, *pm1l;
    void *pw1h, *pw1l, *phdh, *phdl, *pw2h, *pw2l;
    void *ppc, *pp1, *pp2;
    cudaGetSymbolAddress(&pctx, g_ctx);
    cudaGetSymbolAddress(&ppbh, g_pbh);  cudaGetSymbolAddress(&ppbl, g_pbl);
    cudaGetSymbolAddress(&phih, g_hih);  cudaGetSymbolAddress(&phil, g_hil);
    cudaGetSymbolAddress(&pm1h, g_m1h);  cudaGetSymbolAddress(&pm1l, g_m1l);
    cudaGetSymbolAddress(&pw1h, g_w1h);  cudaGetSymbolAddress(&pw1l, g_w1l);
    cudaGetSymbolAddress(&phdh, g_hidh); cudaGetSymbolAddress(&phdl, g_hidl);
    cudaGetSymbolAddress(&pw2h, g_w2h);  cudaGetSymbolAddress(&pw2l, g_w2l);
    cudaGetSymbolAddress(&ppc, g_partc);
    cudaGetSymbolAddress(&pp1, g_part1);
    cudaGetSymbolAddress(&pp2, g_part2);

    cudaFuncSetAttribute(pair_wmma, cudaFuncAttributeMaxDynamicSharedMemorySize, PAIR_SMEM);

    // 0: proj
    proj_kernel<<<NROWS, 256>>>(Hj, Hi, pjw, piw, sw1);
    // 1: W' precompute
    wsplit_pair<<<(96*88 + 255)/256, 256>>>(sw1);
    // 2: Hi -> bf16 hi/lo
    conv_split<<<(NROWS*Hh/4 + 255)/256, 256>>>(Hi, (__nv_bfloat16*)phih,
                                                (__nv_bfloat16*)phil, NROWS*Hh/4);
    // 3: pair (profiled slot)
    pair_wmma<<<NROWS, 256, PAIR_SMEM>>>(sb1, sw2, sb2, mask);
    // 4: ctx partials = probs @ Hi  [NN, batched, split-K=4]
    {
        dim3 g(Hh/128, Ss/128, Bb*4);
        gemm_wmma<false,4><<<g, 256>>>(
            (const __nv_bfloat16*)ppbh, (const __nv_bfloat16*)ppbl,
            (const __nv_bfloat16*)phih, (const __nv_bfloat16*)phil,
            (float*)ppc, Hh, Ss, Ss, Hh,
            (long)Ss*Ss, (long)Ss*Hh, (long)Ss*Hh, 4L*Ss*Hh);
    }
    // 5: ctx reduce
    {
        long total = (long)NROWS*Hh;
        reduce_ns<4,0><<<(int)((total/4 + 255)/256), 256>>>(
            (const float*)ppc, 4L*Ss*Hh, (float*)pctx,
            nullptr, nullptr, nullptr, nullptr, Hh, total);
    }
    // 6: msg_in -> bf16 hi/lo
    msgin_conv<<<(NROWS*(Hh/4) + 255)/256, 256>>>(Hj);
    // 7: vw1 -> bf16 hi/lo
    conv_split<<<(OH*H3/4 + 255)/256, 256>>>(vw1, (__nv_bfloat16*)pw1h,
                                             (__nv_bfloat16*)pw1l, OH*H3/4);
    // 8: gemm1 partials  [NT, split-K=3]
    {
        dim3 g(OH/128, NROWS/128, 3);
        gemm_wmma<true,3><<<g, 256>>>(
            (const __nv_bfloat16*)pm1h, (const __nv_bfloat16*)pm1l,
            (const __nv_bfloat16*)pw1h, (const __nv_bfloat16*)pw1l,
            (float*)pp1, OH, H3, H3, H3,
            0, 0, 0, (long)NROWS*OH);
    }
    // 9: hid reduce (bias+relu -> bf16 split)
    {
        long total = (long)NROWS*OH;
        reduce_ns<3,1><<<(int)((total/4 + 255)/256), 256>>>(
            (const float*)pp1, (long)NROWS*OH, nullptr,
            (__nv_bfloat16*)phdh, (__nv_bfloat16*)phdl, vb1, nullptr, OH, total);
    }
    // 10: vw2 -> bf16 hi/lo
    conv_split<<<(Hh*OH/4 + 255)/256, 256>>>(vw2, (__nv_bfloat16*)pw2h,
                                             (__nv_bfloat16*)pw2l, Hh*OH/4);
    // 11: gemm2 partials  [NT, split-K=3]
    {
        dim3 g(Hh/128, NROWS/128, 3);
        gemm_wmma<true,3><<<g, 256>>>(
            (const __nv_bfloat16*)phdh, (const __nv_bfloat16*)phdl,
            (const __nv_bfloat16*)pw2h, (const __nv_bfloat16*)pw2l,
            (float*)pp2, Hh, OH, OH, OH,
            0, 0, 0, (long)NROWS*Hh);
    }
    // 12: out reduce (bias, alpha)
    {
        long total = (long)NROWS*Hh;
        reduce_ns<3,2><<<(int)((total/4 + 255)/256), 256>>>(
            (const float*)pp2, (long)NROWS*Hh, out,
            nullptr, nullptr, vb2, alpha, Hh, total);
    }
    (void)in_sizes; (void)n_in; (void)out_size;
}

// round 13
// speedup vs baseline: 1.7873x; 1.1142x over previous
#include <cuda_runtime.h>
#include <cuda_bf16.h>
#include <mma.h>
#include <math.h>
#include <cstdint>

using namespace nvcuda;

#define Bb 4
#define Ss 512
#define Hh 768
#define Dd 24
#define Mm 96
#define OH 768
#define H3 2304
#define NROWS (Bb*Ss)   // 2048

typedef unsigned long long ull;

// ---- scratch ----
__device__ __align__(16) float g_Zj[NROWS*Dd];
__device__ __align__(16) float g_Zi[NROWS*Dd];
__device__ __align__(16) float g_Aj[NROWS*Mm];
__device__ __align__(16) float g_ctx[(long)NROWS*Hh];
__device__ __align__(16) __nv_bfloat16 g_Wph[96*88];
// bf16 hi/lo operands for tensor-core GEMMs
__device__ __align__(16) __nv_bfloat16 g_pbh[(long)Bb*Ss*Ss];
__device__ __align__(16) __nv_bfloat16 g_pbl[(long)Bb*Ss*Ss];
__device__ __align__(16) __nv_bfloat16 g_hih[(long)NROWS*Hh];
__device__ __align__(16) __nv_bfloat16 g_hil[(long)NROWS*Hh];
__device__ __align__(16) __nv_bfloat16 g_m1h[(long)NROWS*H3];
__device__ __align__(16) __nv_bfloat16 g_m1l[(long)NROWS*H3];
__device__ __align__(16) __nv_bfloat16 g_w1h[(long)OH*H3];
__device__ __align__(16) __nv_bfloat16 g_w1l[(long)OH*H3];
__device__ __align__(16) __nv_bfloat16 g_hidh[(long)NROWS*OH];
__device__ __align__(16) __nv_bfloat16 g_hidl[(long)NROWS*OH];
__device__ __align__(16) __nv_bfloat16 g_w2h[(long)Hh*OH];
__device__ __align__(16) __nv_bfloat16 g_w2l[(long)Hh*OH];
// split-K partial buffers (fp32)
__device__ __align__(16) float g_partc[4L*Bb*Ss*Hh];
__device__ __align__(16) float g_part1[3L*NROWS*OH];
__device__ __align__(16) float g_part2[3L*NROWS*Hh];

// bf16 hi/lo split
__device__ __forceinline__ void bsplit(float v, __nv_bfloat16& h, __nv_bfloat16& l){
    h = __float2bfloat16(v);
    l = __float2bfloat16(v - __bfloat162float(h));
}
__device__ __forceinline__ unsigned packh(float a, float b){
    __nv_bfloat162 p;
    p.x = __float2bfloat16(a);
    p.y = __float2bfloat16(b);
    return *(unsigned*)&p;
}

// ---- PTX mma helpers (base ISA, sm_80+) ----
__device__ __forceinline__ unsigned smem_cast(const void* p){
    return (unsigned)__cvta_generic_to_shared(p);
}
__device__ __forceinline__ void ldsm_x4(unsigned addr, unsigned& r0, unsigned& r1,
                                        unsigned& r2, unsigned& r3){
    asm volatile("ldmatrix.sync.aligned.m8n8.x4.shared.b16 {%0,%1,%2,%3}, [%4];"
        : "=r"(r0), "=r"(r1), "=r"(r2), "=r"(r3) : "r"(addr));
}
__device__ __forceinline__ void mma16816(float* d, const unsigned* a,
                                         unsigned b0, unsigned b1){
    asm volatile(
        "mma.sync.aligned.m16n8k16.row.col.f32.bf16.bf16.f32 "
        "{%0,%1,%2,%3}, {%4,%5,%6,%7}, {%8,%9}, {%0,%1,%2,%3};"
        : "+f"(d[0]), "+f"(d[1]), "+f"(d[2]), "+f"(d[3])
        : "r"(a[0]), "r"(a[1]), "r"(a[2]), "r"(a[3]), "r"(b0), "r"(b1));
}

// ============================================================
// K0: precompute W' = [Wc | Wd | Wb | 0] (96 x 88) bf16
// ============================================================
__global__ __launch_bounds__(256) void wsplit_pair(const float* __restrict__ sw1)
{
    int i = blockIdx.x*256 + threadIdx.x;
    if (i >= 96*88) return;
    int m = i / 88, k = i % 88;
    float wv = 0.f;
    if (k < 24)      wv = sw1[m*96 + 48 + k];
    else if (k < 48) wv = sw1[m*96 + 72 + (k-24)];
    else if (k < 72) wv = sw1[m*96 + 24 + (k-48)];
    g_Wph[i] = __float2bfloat16(wv);
}

// ============================================================
// K1: proj v2 — 8 rows per CTA; weights L1-resident after row 0.
// ============================================================
#define PROJ_ROWS 8
#define PROJ_SMEM (PROJ_ROWS*Hh*2*4 + PROJ_ROWS*Dd*4 + 128)
__global__ __launch_bounds__(256) void proj_kernel(
    const float* __restrict__ Hj, const float* __restrict__ Hi,
    const float* __restrict__ pjw, const float* __restrict__ piw,
    const float* __restrict__ sw1)
{
    extern __shared__ float psm[];
    float* shj = psm;                      // [8][768]
    float* shi = psm + PROJ_ROWS*Hh;       // [8][768]
    float* szj = psm + 2*PROJ_ROWS*Hh;     // [8][24]
    long r0 = (long)blockIdx.x * PROJ_ROWS;
    int tid = threadIdx.x;

    const float4* Hj4 = (const float4*)(Hj + r0*Hh);
    const float4* Hi4 = (const float4*)(Hi + r0*Hh);
    float4* shj4 = (float4*)shj;
    float4* shi4 = (float4*)shi;
    #pragma unroll 4
    for (int i = tid; i < PROJ_ROWS*Hh/4; i += 256){
        shj4[i] = Hj4[i];
        shi4[i] = Hi4[i];
    }
    __syncthreads();

    int o = tid >> 3, g = tid & 7;
    if (o < Dd){
        const float4* wj4 = (const float4*)(pjw + o*Hh);
        const float4* wi4 = (const float4*)(piw + o*Hh);
        #pragma unroll 1
        for (int rr = 0; rr < PROJ_ROWS; rr++){
            const float4* hj4 = (const float4*)(shj + rr*Hh);
            const float4* hs4 = (const float4*)(shi + rr*Hh);
            float pj = 0.f, pi = 0.f;
            #pragma unroll 6
            for (int it = g; it < Hh/4; it += 8){
                float4 wj = __ldg(&wj4[it]);
                float4 wi = __ldg(&wi4[it]);
                float4 hj = hj4[it];
                float4 hs = hs4[it];
                pj += wj.x*hj.x + wj.y*hj.y + wj.z*hj.z + wj.w*hj.w;
                pi += wi.x*hs.x + wi.y*hs.y + wi.z*hs.z + wi.w*hs.w;
            }
            #pragma unroll
            for (int d = 4; d > 0; d >>= 1){
                pj += __shfl_down_sync(0xffffffffu, pj, d, 8);
                pi += __shfl_down_sync(0xffffffffu, pi, d, 8);
            }
            if (g == 0){
                szj[rr*Dd + o] = pj;
                g_Zj[(r0+rr)*Dd + o] = pj;
                g_Zi[(r0+rr)*Dd + o] = pi;
            }
        }
    }
    __syncthreads();
    if (tid < Mm){
        #pragma unroll 1
        for (int rr = 0; rr < PROJ_ROWS; rr++){
            float a = 0.f;
            #pragma unroll
            for (int d = 0; d < Dd; d++)
                a += sw1[tid*96 + d] * szj[rr*Dd + d];
            g_Aj[(r0+rr)*Mm + tid] = a;
        }
    }
}

// ============================================================
// K2: pair logits v7 — PTX mma, in-register reduce, smem coeffs,
//  one-time zero pad, 3 CTAs/SM target.
// ============================================================
#define POFF_WH   0                       // 96*88*2 = 16896
#define POFF_F    16896                   // 128*88*2 = 22528 -> 39424
#define POFF_SLOG 39424                   // 512*4 -> 41472
#define POFF_SZJ  41472                   // -> 41600 (padded)
#define POFF_SCW  41600                   // 96 float2 = 768 -> 42368
#define POFF_SRED 42368                   // 8*4 -> 42400
#define PAIR_SMEM 42496

#define FCOLV(c) ((c) < 24 ? szj[(c)]*za[(c)] : \
                  (c) < 48 ? fabsf(szj[(c)-24]-za[(c)-24]) : \
                  (c) < 72 ? za[(c)-48] : 0.f)

__global__ __launch_bounds__(256, 3) void pair_wmma(
    const float* __restrict__ sb1,
    const float* __restrict__ sw2v, const float* __restrict__ sb2,
    const float* __restrict__ mask)
{
    extern __shared__ char ps[];
    __nv_bfloat16* Wh = (__nv_bfloat16*)(ps + POFF_WH);
    __nv_bfloat16* Fh = (__nv_bfloat16*)(ps + POFF_F);
    float*  slog = (float*)(ps + POFF_SLOG);
    float*  szj  = (float*)(ps + POFF_SZJ);
    float2* scw  = (float2*)(ps + POFF_SCW);    // (ssc, w2) interleaved
    float*  sred = (float*)(ps + POFF_SRED);

    int r = blockIdx.x, b = r >> 9;
    int tid = threadIdx.x, wid = tid >> 5, lane = tid & 31;

    // load precomputed W' (1056 uint4)
    for (int i = tid; i < 1056; i += 256)
        ((uint4*)Wh)[i] = ((const uint4*)g_Wph)[i];
    if (tid < Dd) szj[tid] = g_Zj[r*Dd + tid];
    if (tid < Mm)
        scw[tid] = make_float2(g_Aj[r*Mm + tid] + sb1[tid], sw2v[tid]);
    // one-time zero pad of F cols 72..87 (never rewritten)
    if (tid < 128){
        uint4 z = make_uint4(0u,0u,0u,0u);
        uint4* zp = (uint4*)&Fh[tid*88 + 72];
        zp[0] = z; zp[1] = z;
    }
    __syncthreads();

    unsigned sF = smem_cast(Fh);
    unsigned sW = smem_cast(Wh);
    int bhalf = tid >> 7;
    int brow  = tid & 127;
    int l16   = lane & 15;
    int lhi8  = (lane >> 4) * 8;
    int c0    = (lane & 3) * 2;

    #pragma unroll 1
    for (int chunk = 0; chunk < 4; chunk++){
        // ---- build F cols 0..71 (bf16, vectorized STS.128) ----
        {
            int t = chunk*128 + brow;
            const float4* zi4 = (const float4*)&g_Zi[(long)(b*Ss + t)*Dd];
            float za[24];
            #pragma unroll
            for (int q = 0; q < 6; q++){
                float4 v4 = __ldg(&zi4[q]);
                za[q*4+0]=v4.x; za[q*4+1]=v4.y; za[q*4+2]=v4.z; za[q*4+3]=v4.w;
            }
            if (bhalf == 0){
                uint4* dh = (uint4*)&Fh[brow*88];
                #pragma unroll
                for (int q = 0; q < 5; q++){
                    unsigned h4[4];
                    #pragma unroll
                    for (int e = 0; e < 4; e++){
                        int c = q*8 + e*2;
                        h4[e] = packh(FCOLV(c), FCOLV(c+1));
                    }
                    dh[q] = make_uint4(h4[0],h4[1],h4[2],h4[3]);
                }
            } else {
                uint4* dh = (uint4*)&Fh[brow*88 + 40];
                #pragma unroll
                for (int q = 0; q < 4; q++){
                    unsigned h4[4];
                    #pragma unroll
                    for (int e = 0; e < 4; e++){
                        int c = 40 + q*8 + e*2;
                        h4[e] = packh(FCOLV(c), FCOLV(c+1));
                    }
                    dh[q] = make_uint4(h4[0],h4[1],h4[2],h4[3]);
                }
            }
        }
        __syncthreads();

        // ---- MMA: 12 n-frags x 5 k-steps, acc in registers ----
        float acc[12][4];
        #pragma unroll
        for (int jf = 0; jf < 12; jf++)
            #pragma unroll
            for (int e = 0; e < 4; e++) acc[jf][e] = 0.f;

        int rowbase = wid * 16;
        #pragma unroll
        for (int k = 0; k < 5; k++){
            unsigned a[4];
            unsigned aaddr = sF + (unsigned)(((rowbase + l16)*88 + k*16 + lhi8) * 2);
            ldsm_x4(aaddr, a[0], a[1], a[2], a[3]);
            #pragma unroll
            for (int j2 = 0; j2 < 6; j2++){
                unsigned bq[4];
                unsigned baddr = sW + (unsigned)(((j2*16 + l16)*88 + k*16 + lhi8) * 2);
                ldsm_x4(baddr, bq[0], bq[1], bq[2], bq[3]);
                mma16816(acc[2*j2],     a, bq[0], bq[2]);
                mma16816(acc[2*j2 + 1], a, bq[1], bq[3]);
            }
        }

        // ---- in-register reduce (coeffs from SMEM) ----
        float s0 = 0.f, s1 = 0.f;
        #pragma unroll
        for (int jf = 0; jf < 12; jf++){
            float4 c = *(const float4*)&scw[jf*8 + c0];
            s0 += c.y * fmaxf(acc[jf][0] + c.x, 0.f)
                + c.w * fmaxf(acc[jf][1] + c.z, 0.f);
            s1 += c.y * fmaxf(acc[jf][2] + c.x, 0.f)
                + c.w * fmaxf(acc[jf][3] + c.z, 0.f);
        }
        s0 += __shfl_xor_sync(0xffffffffu, s0, 1);
        s0 += __shfl_xor_sync(0xffffffffu, s0, 2);
        s1 += __shfl_xor_sync(0xffffffffu, s1, 1);
        s1 += __shfl_xor_sync(0xffffffffu, s1, 2);
        if ((lane & 3) == 0){
            int row = lane >> 2;
            slog[chunk*128 + wid*16 + row]     = s0;
            slog[chunk*128 + wid*16 + 8 + row] = s1;
        }
        __syncthreads();   // F reads done before next chunk's build
    }

    // ---- masked softmax over slog[512] ----
    int t0 = tid, t1 = tid + 256;
    float lt0 = slog[t0] + sb2[0] + (1.f - mask[b*Ss + t0]) * (-3.402823466e38f);
    float lt1 = slog[t1] + sb2[0] + (1.f - mask[b*Ss + t1]) * (-3.402823466e38f);

    float mx = fmaxf(lt0, lt1);
    #pragma unroll
    for (int d = 16; d > 0; d >>= 1)
        mx = fmaxf(mx, __shfl_xor_sync(0xffffffffu, mx, d));
    if (lane == 0) sred[wid] = mx;
    __syncthreads();
    float bmax = sred[0];
    #pragma unroll
    for (int i = 1; i < 8; i++) bmax = fmaxf(bmax, sred[i]);

    float e0 = expf(lt0 - bmax);
    float e1 = expf(lt1 - bmax);
    float sm = e0 + e1;
    #pragma unroll
    for (int d = 16; d > 0; d >>= 1)
        sm += __shfl_xor_sync(0xffffffffu, sm, d);
    __syncthreads();
    if (lane == 0) sred[wid] = sm;
    __syncthreads();
    float tot = 0.f;
    #pragma unroll
    for (int i = 0; i < 8; i++) tot += sred[i];
    float inv = 1.f / tot;

    __nv_bfloat16 h, l;
    bsplit(e0 * inv, h, l);
    g_pbh[(long)r*Ss + t0] = h; g_pbl[(long)r*Ss + t0] = l;
    bsplit(e1 * inv, h, l);
    g_pbh[(long)r*Ss + t1] = h; g_pbl[(long)r*Ss + t1] = l;
}

// ============================================================
// K3: fp32 -> bf16 hi/lo split (vectorized)
// ============================================================
__global__ __launch_bounds__(256) void conv_split(
    const float* __restrict__ x, __nv_bfloat16* __restrict__ hi,
    __nv_bfloat16* __restrict__ lo, int n4)
{
    int i = blockIdx.x*256 + threadIdx.x;
    if (i >= n4) return;
    float4 v = ((const float4*)x)[i];
    __nv_bfloat16 h0,h1,h2,h3,l0,l1,l2,l3;
    bsplit(v.x,h0,l0); bsplit(v.y,h1,l1); bsplit(v.z,h2,l2); bsplit(v.w,h3,l3);
    __nv_bfloat162 p0, p1;
    p0.x=h0; p0.y=h1; p1.x=h2; p1.y=h3;
    ((__nv_bfloat162*)hi)[2*i]   = p0;
    ((__nv_bfloat162*)hi)[2*i+1] = p1;
    p0.x=l0; p0.y=l1; p1.x=l2; p1.y=l3;
    ((__nv_bfloat162*)lo)[2*i]   = p0;
    ((__nv_bfloat162*)lo)[2*i+1] = p1;
}

// ============================================================
// K4: msg_in = [ctx | Hj | ctx*Hj] -> bf16 hi/lo
// ============================================================
__device__ __forceinline__ void store4(__nv_bfloat16* hp, __nv_bfloat16* lp,
                                       float a, float b, float c, float d)
{
    __nv_bfloat16 h0,h1,h2,h3,l0,l1,l2,l3;
    bsplit(a,h0,l0); bsplit(b,h1,l1); bsplit(c,h2,l2); bsplit(d,h3,l3);
    __nv_bfloat162 p0, p1;
    p0.x=h0; p0.y=h1; p1.x=h2; p1.y=h3;
    ((__nv_bfloat162*)hp)[0] = p0; ((__nv_bfloat162*)hp)[1] = p1;
    p0.x=l0; p0.y=l1; p1.x=l2; p1.y=l3;
    ((__nv_bfloat162*)lp)[0] = p0; ((__nv_bfloat162*)lp)[1] = p1;
}
__global__ __launch_bounds__(256) void msgin_conv(const float* __restrict__ Hj)
{
    int i = blockIdx.x*256 + threadIdx.x;
    if (i >= NROWS*(Hh/4)) return;
    int r = i / (Hh/4);
    int c = (i % (Hh/4)) * 4;
    float4 cv = *(const float4*)&g_ctx[(long)r*Hh + c];
    float4 hv = *(const float4*)&Hj[(long)r*Hh + c];
    long base = (long)r*H3 + c;
    store4(&g_m1h[base],      &g_m1l[base],      cv.x, cv.y, cv.z, cv.w);
    store4(&g_m1h[base+Hh],   &g_m1l[base+Hh],   hv.x, hv.y, hv.z, hv.w);
    store4(&g_m1h[base+2*Hh], &g_m1l[base+2*Hh],
           cv.x*hv.x, cv.y*hv.y, cv.z*hv.z, cv.w*hv.w);
}

// ============================================================
// K5: WMMA GEMM, split-K, raw fp32 partial store.
// ============================================================
template<bool TRANSB, int KSPLIT>
__global__ __launch_bounds__(256) void gemm_wmma(
    const __nv_bfloat16* __restrict__ Ah, const __nv_bfloat16* __restrict__ Al,
    const __nv_bfloat16* __restrict__ Bh, const __nv_bfloat16* __restrict__ Bl,
    float* __restrict__ Cpart, int N, int K, int ldA, int ldB,
    long strideA, long strideB, long strideC, long partStride)
{
    __shared__ __nv_bfloat16 As[2][128][40];
    __shared__ __nv_bfloat16 Bs[2][5120];   // NT: [n][40] ; NN: [k][136]

    int tid = threadIdx.x;
    int wid = tid >> 5;
    int wr = wid & 3, wc = wid >> 2;
    long row0 = (long)blockIdx.y * 128;
    long col0 = (long)blockIdx.x * 128;

    int zb = blockIdx.z / KSPLIT, zk = blockIdx.z % KSPLIT;
    int kcnt = K / KSPLIT, k0 = zk * kcnt;

    const __nv_bfloat16* APh = Ah + (long)zb * strideA;
    const __nv_bfloat16* APl = Al + (long)zb * strideA;
    const __nv_bfloat16* BPh = Bh + (long)zb * strideB;
    const __nv_bfloat16* BPl = Bl + (long)zb * strideB;
    float* Cb = Cpart + (long)zk * partStride + (long)zb * strideC;

    wmma::fragment<wmma::accumulator,16,16,16,float> acc[2][4];
    #pragma unroll
    for (int i = 0; i < 2; i++)
        #pragma unroll
        for (int j = 0; j < 4; j++) wmma::fill_fragment(acc[i][j], 0.f);

    #pragma unroll 1
    for (int kc = k0; kc < k0 + kcnt; kc += 32){
        #pragma unroll
        for (int t = tid; t < 512; t += 256){
            int r = t >> 2, seg = t & 3;
            long off = (row0 + r)*(long)ldA + kc + seg*8;
            *(float4*)&As[0][r][seg*8] = *(const float4*)(APh + off);
            *(float4*)&As[1][r][seg*8] = *(const float4*)(APl + off);
        }
        if (TRANSB){
            #pragma unroll
            for (int t = tid; t < 512; t += 256){
                int r = t >> 2, seg = t & 3;
                long off = (col0 + r)*(long)ldB + kc + seg*8;
                *(float4*)&Bs[0][r*40 + seg*8] = *(const float4*)(BPh + off);
                *(float4*)&Bs[1][r*40 + seg*8] = *(const float4*)(BPl + off);
            }
        } else {
            #pragma unroll
            for (int t = tid; t < 512; t += 256){
                int r = t >> 4, seg = t & 15;
                long off = (long)(kc + r)*ldB + col0 + seg*8;
                *(float4*)&Bs[0][r*136 + seg*8] = *(const float4*)(BPh + off);
                *(float4*)&Bs[1][r*136 + seg*8] = *(const float4*)(BPl + off);
            }
        }
        __syncthreads();

        #pragma unroll
        for (int ks = 0; ks < 2; ks++){
            wmma::fragment<wmma::matrix_a,16,16,16,__nv_bfloat16,wmma::row_major> afh[2], afl[2];
            #pragma unroll
            for (int i = 0; i < 2; i++){
                wmma::load_matrix_sync(afh[i], &As[0][wr*32 + i*16][ks*16], 40);
                wmma::load_matrix_sync(afl[i], &As[1][wr*32 + i*16][ks*16], 40);
            }
            if (TRANSB){
                #pragma unroll
                for (int j = 0; j < 4; j++){
                    wmma::fragment<wmma::matrix_b,16,16,16,__nv_bfloat16,wmma::col_major> bfh, bfl;
                    int nb = wc*64 + j*16;
                    wmma::load_matrix_sync(bfh, &Bs[0][nb*40 + ks*16], 40);
                    wmma::load_matrix_sync(bfl, &Bs[1][nb*40 + ks*16], 40);
                    #pragma unroll
                    for (int i = 0; i < 2; i++){
                        wmma::mma_sync(acc[i][j], afh[i], bfh, acc[i][j]);
                        wmma::mma_sync(acc[i][j], afh[i], bfl, acc[i][j]);
                        wmma::mma_sync(acc[i][j], afl[i], bfh, acc[i][j]);
                    }
                }
            } else {
                #pragma unroll
                for (int j = 0; j < 4; j++){
                    wmma::fragment<wmma::matrix_b,16,16,16,__nv_bfloat16,wmma::row_major> bfh, bfl;
                    int nb = wc*64 + j*16;
                    wmma::load_matrix_sync(bfh, &Bs[0][(ks*16)*136 + nb], 136);
                    wmma::load_matrix_sync(bfl, &Bs[1][(ks*16)*136 + nb], 136);
                    #pragma unroll
                    for (int i = 0; i < 2; i++){
                        wmma::mma_sync(acc[i][j], afh[i], bfh, acc[i][j]);
                        wmma::mma_sync(acc[i][j], afh[i], bfl, acc[i][j]);
                        wmma::mma_sync(acc[i][j], afl[i], bfh, acc[i][j]);
                    }
                }
            }
        }
        __syncthreads();
    }

    #pragma unroll
    for (int i = 0; i < 2; i++)
        #pragma unroll
        for (int j = 0; j < 4; j++){
            float* cp = Cb + (row0 + wr*32 + i*16)*(long)N + col0 + wc*64 + j*16;
            wmma::store_matrix_sync(cp, acc[i][j], N, wmma::mem_row_major);
        }
}

// ============================================================
// K6: split-K reduce + epilogues
// ============================================================
template<int NS, int MODE>
__global__ __launch_bounds__(256) void reduce_ns(
    const float* __restrict__ p, long partStride,
    float* __restrict__ outf,
    __nv_bfloat16* __restrict__ oh, __nv_bfloat16* __restrict__ ol,
    const float* __restrict__ bias, const float* __restrict__ alpha_p,
    int N, long total)
{
    long i4 = ((long)blockIdx.x * 256 + threadIdx.x) * 4;
    if (i4 >= total) return;
    float4 s = *(const float4*)&p[i4];
    #pragma unroll
    for (int n = 1; n < NS; n++){
        float4 v = *(const float4*)&p[n*partStride + i4];
        s.x += v.x; s.y += v.y; s.z += v.z; s.w += v.w;
    }
    if (MODE >= 1){
        int col = (int)(i4 % N);
        float4 bi = *(const float4*)&bias[col];
        s.x += bi.x; s.y += bi.y; s.z += bi.z; s.w += bi.w;
    }
    if (MODE == 1){
        s.x = fmaxf(s.x, 0.f); s.y = fmaxf(s.y, 0.f);
        s.z = fmaxf(s.z, 0.f); s.w = fmaxf(s.w, 0.f);
        __nv_bfloat16 h0,h1,h2,h3,l0,l1,l2,l3;
        bsplit(s.x,h0,l0); bsplit(s.y,h1,l1); bsplit(s.z,h2,l2); bsplit(s.w,h3,l3);
        __nv_bfloat162 ph0, ph1, pl0, pl1;
        ph0.x=h0; ph0.y=h1; ph1.x=h2; ph1.y=h3;
        pl0.x=l0; pl0.y=l1; pl1.x=l2; pl1.y=l3;
        *(__nv_bfloat162*)&oh[i4]   = ph0;
        *(__nv_bfloat162*)&oh[i4+2] = ph1;
        *(__nv_bfloat162*)&ol[i4]   = pl0;
        *(__nv_bfloat162*)&ol[i4+2] = pl1;
    } else {
        if (MODE == 2){
            float a = __ldg(alpha_p);
            s.x *= a; s.y *= a; s.z *= a; s.w *= a;
        }
        *(float4*)&outf[i4] = s;
    }
}

// ============================================================
extern "C" void kernel_launch(void* const* d_in, const int* in_sizes, int n_in,
                              void* d_out, int out_size)
{
    const float* Hj   = (const float*)d_in[0];
    const float* Hi   = (const float*)d_in[1];
    const float* mask = (const float*)d_in[2];
    const float* pjw  = (const float*)d_in[3];
    const float* piw  = (const float*)d_in[4];
    const float* sw1  = (const float*)d_in[5];
    const float* sb1  = (const float*)d_in[6];
    const float* sw2  = (const float*)d_in[7];
    const float* sb2  = (const float*)d_in[8];
    const float* vw1  = (const float*)d_in[9];
    const float* vb1  = (const float*)d_in[10];
    const float* vw2  = (const float*)d_in[11];
    const float* vb2  = (const float*)d_in[12];
    const float* alpha= (const float*)d_in[13];
    float* out = (float*)d_out;

    void *pctx, *ppbh, *ppbl, *phih, *phil, *pm1h, *pm1l;
    void *pw1h, *pw1l, *phdh, *phdl, *pw2h, *pw2l;
    void *ppc, *pp1, *pp2;
    cudaGetSymbolAddress(&pctx, g_ctx);
    cudaGetSymbolAddress(&ppbh, g_pbh);  cudaGetSymbolAddress(&ppbl, g_pbl);
    cudaGetSymbolAddress(&phih, g_hih);  cudaGetSymbolAddress(&phil, g_hil);
    cudaGetSymbolAddress(&pm1h, g_m1h);  cudaGetSymbolAddress(&pm1l, g_m1l);
    cudaGetSymbolAddress(&pw1h, g_w1h);  cudaGetSymbolAddress(&pw1l, g_w1l);
    cudaGetSymbolAddress(&phdh, g_hidh); cudaGetSymbolAddress(&phdl, g_hidl);
    cudaGetSymbolAddress(&pw2h, g_w2h);  cudaGetSymbolAddress(&pw2l, g_w2l);
    cudaGetSymbolAddress(&ppc, g_partc);
    cudaGetSymbolAddress(&pp1, g_part1);
    cudaGetSymbolAddress(&pp2, g_part2);

    cudaFuncSetAttribute(pair_wmma, cudaFuncAttributeMaxDynamicSharedMemorySize, PAIR_SMEM);
    cudaFuncSetAttribute(proj_kernel, cudaFuncAttributeMaxDynamicSharedMemorySize, PROJ_SMEM);

    // 0: proj (8 rows/CTA)
    proj_kernel<<<NROWS/PROJ_ROWS, 256, PROJ_SMEM>>>(Hj, Hi, pjw, piw, sw1);
    // 1: W' precompute
    wsplit_pair<<<(96*88 + 255)/256, 256>>>(sw1);
    // 2: Hi -> bf16 hi/lo
    conv_split<<<(NROWS*Hh/4 + 255)/256, 256>>>(Hi, (__nv_bfloat16*)phih,
                                                (__nv_bfloat16*)phil, NROWS*Hh/4);
    // 3: pair
    pair_wmma<<<NROWS, 256, PAIR_SMEM>>>(sb1, sw2, sb2, mask);
    // 4: ctx partials = probs @ Hi  [NN, batched, split-K=4]
    {
        dim3 g(Hh/128, Ss/128, Bb*4);
        gemm_wmma<false,4><<<g, 256>>>(
            (const __nv_bfloat16*)ppbh, (const __nv_bfloat16*)ppbl,
            (const __nv_bfloat16*)phih, (const __nv_bfloat16*)phil,
            (float*)ppc, Hh, Ss, Ss, Hh,
            (long)Ss*Ss, (long)Ss*Hh, (long)Ss*Hh, 4L*Ss*Hh);
    }
    // 5: ctx reduce
    {
        long total = (long)NROWS*Hh;
        reduce_ns<4,0><<<(int)((total/4 + 255)/256), 256>>>(
            (const float*)ppc, 4L*Ss*Hh, (float*)pctx,
            nullptr, nullptr, nullptr, nullptr, Hh, total);
    }
    // 6: msg_in -> bf16 hi/lo
    msgin_conv<<<(NROWS*(Hh/4) + 255)/256, 256>>>(Hj);
    // 7: vw1 -> bf16 hi/lo
    conv_split<<<(OH*H3/4 + 255)/256, 256>>>(vw1, (__nv_bfloat16*)pw1h,
                                             (__nv_bfloat16*)pw1l, OH*H3/4);
    // 8: gemm1 partials  [NT, split-K=3]
    {
        dim3 g(OH/128, NROWS/128, 3);
        gemm_wmma<true,3><<<g, 256>>>(
            (const __nv_bfloat16*)pm1h, (const __nv_bfloat16*)pm1l,
            (const __nv_bfloat16*)pw1h, (const __nv_bfloat16*)pw1l,
            (float*)pp1, OH, H3, H3, H3,
            0, 0, 0, (long)NROWS*OH);
    }
    // 9: hid reduce (bias+relu -> bf16 split)
    {
        long total = (long)NROWS*OH;
        reduce_ns<3,1><<<(int)((total/4 + 255)/256), 256>>>(
            (const float*)pp1, (long)NROWS*OH, nullptr,
            (__nv_bfloat16*)phdh, (__nv_bfloat16*)phdl, vb1, nullptr, OH, total);
    }
    // 10: vw2 -> bf16 hi/lo
    conv_split<<<(Hh*OH/4 + 255)/256, 256>>>(vw2, (__nv_bfloat16*)pw2h,
                                             (__nv_bfloat16*)pw2l, Hh*OH/4);
    // 11: gemm2 partials  [NT, split-K=3]
    {
        dim3 g(Hh/128, NROWS/128, 3);
        gemm_wmma<true,3><<<g, 256>>>(
            (const __nv_bfloat16*)phdh, (const __nv_bfloat16*)phdl,
            (const __nv_bfloat16*)pw2h, (const __nv_bfloat16*)pw2l,
            (float*)pp2, Hh, OH, OH, OH,
            0, 0, 0, (long)NROWS*Hh);
    }
    // 12: out reduce (bias, alpha)
    {
        long total = (long)NROWS*Hh;
        reduce_ns<3,2><<<(int)((total/4 + 255)/256), 256>>>(
            (const float*)pp2, (long)NROWS*Hh, out,
            nullptr, nullptr, vb2, alpha, Hh, total);
    }
    (void)in_sizes; (void)n_in; (void)out_size;
}

// round 14
// speedup vs baseline: 1.8420x; 1.0306x over previous
#include <cuda_runtime.h>
#include <cuda_bf16.h>
#include <mma.h>
#include <math.h>
#include <cstdint>

using namespace nvcuda;

#define Bb 4
#define Ss 512
#define Hh 768
#define Dd 24
#define Mm 96
#define OH 768
#define H3 2304
#define NROWS (Bb*Ss)   // 2048

typedef unsigned long long ull;

// ---- scratch ----
__device__ __align__(16) float g_Zj[NROWS*Dd];
__device__ __align__(16) float g_Zi[NROWS*Dd];
__device__ __align__(16) float g_Aj[NROWS*Mm];
__device__ __align__(16) __nv_bfloat16 g_Wph[96*88];
// bf16 hi/lo operands for tensor-core GEMMs
__device__ __align__(16) __nv_bfloat16 g_pbh[(long)Bb*Ss*Ss];
__device__ __align__(16) __nv_bfloat16 g_pbl[(long)Bb*Ss*Ss];
__device__ __align__(16) __nv_bfloat16 g_hih[(long)NROWS*Hh];
__device__ __align__(16) __nv_bfloat16 g_hil[(long)NROWS*Hh];
__device__ __align__(16) __nv_bfloat16 g_m1h[(long)NROWS*H3];
__device__ __align__(16) __nv_bfloat16 g_m1l[(long)NROWS*H3];
__device__ __align__(16) __nv_bfloat16 g_w1h[(long)OH*H3];
__device__ __align__(16) __nv_bfloat16 g_w1l[(long)OH*H3];
__device__ __align__(16) __nv_bfloat16 g_hidh[(long)NROWS*OH];
__device__ __align__(16) __nv_bfloat16 g_hidl[(long)NROWS*OH];
__device__ __align__(16) __nv_bfloat16 g_w2h[(long)Hh*OH];
__device__ __align__(16) __nv_bfloat16 g_w2l[(long)Hh*OH];
// split-K partial buffers (fp32)
__device__ __align__(16) float g_partc[4L*Bb*Ss*Hh];
__device__ __align__(16) float g_part1[3L*NROWS*OH];
__device__ __align__(16) float g_part2[3L*NROWS*Hh];

// bf16 hi/lo split
__device__ __forceinline__ void bsplit(float v, __nv_bfloat16& h, __nv_bfloat16& l){
    h = __float2bfloat16(v);
    l = __float2bfloat16(v - __bfloat162float(h));
}
__device__ __forceinline__ unsigned packh(float a, float b){
    __nv_bfloat162 p;
    p.x = __float2bfloat16(a);
    p.y = __float2bfloat16(b);
    return *(unsigned*)&p;
}

// ---- PTX mma helpers (base ISA, sm_80+) ----
__device__ __forceinline__ unsigned smem_cast(const void* p){
    return (unsigned)__cvta_generic_to_shared(p);
}
__device__ __forceinline__ void ldsm_x4(unsigned addr, unsigned& r0, unsigned& r1,
                                        unsigned& r2, unsigned& r3){
    asm volatile("ldmatrix.sync.aligned.m8n8.x4.shared.b16 {%0,%1,%2,%3}, [%4];"
        : "=r"(r0), "=r"(r1), "=r"(r2), "=r"(r3) : "r"(addr));
}
__device__ __forceinline__ void mma16816(float* d, const unsigned* a,
                                         unsigned b0, unsigned b1){
    asm volatile(
        "mma.sync.aligned.m16n8k16.row.col.f32.bf16.bf16.f32 "
        "{%0,%1,%2,%3}, {%4,%5,%6,%7}, {%8,%9}, {%0,%1,%2,%3};"
        : "+f"(d[0]), "+f"(d[1]), "+f"(d[2]), "+f"(d[3])
        : "r"(a[0]), "r"(a[1]), "r"(a[2]), "r"(a[3]), "r"(b0), "r"(b1));
}

// ============================================================
// K0: precompute W' = [Wc | Wd | Wb | 0] (96 x 88) bf16
// ============================================================
__global__ __launch_bounds__(256) void wsplit_pair(const float* __restrict__ sw1)
{
    int i = blockIdx.x*256 + threadIdx.x;
    if (i >= 96*88) return;
    int m = i / 88, k = i % 88;
    float wv = 0.f;
    if (k < 24)      wv = sw1[m*96 + 48 + k];
    else if (k < 48) wv = sw1[m*96 + 72 + (k-24)];
    else if (k < 72) wv = sw1[m*96 + 24 + (k-48)];
    g_Wph[i] = __float2bfloat16(wv);
}

// ============================================================
// K1: proj v2 — 8 rows per CTA
// ============================================================
#define PROJ_ROWS 8
#define PROJ_SMEM (PROJ_ROWS*Hh*2*4 + PROJ_ROWS*Dd*4 + 128)
__global__ __launch_bounds__(256) void proj_kernel(
    const float* __restrict__ Hj, const float* __restrict__ Hi,
    const float* __restrict__ pjw, const float* __restrict__ piw,
    const float* __restrict__ sw1)
{
    extern __shared__ float psm[];
    float* shj = psm;
    float* shi = psm + PROJ_ROWS*Hh;
    float* szj = psm + 2*PROJ_ROWS*Hh;
    long r0 = (long)blockIdx.x * PROJ_ROWS;
    int tid = threadIdx.x;

    const float4* Hj4 = (const float4*)(Hj + r0*Hh);
    const float4* Hi4 = (const float4*)(Hi + r0*Hh);
    float4* shj4 = (float4*)shj;
    float4* shi4 = (float4*)shi;
    #pragma unroll 4
    for (int i = tid; i < PROJ_ROWS*Hh/4; i += 256){
        shj4[i] = Hj4[i];
        shi4[i] = Hi4[i];
    }
    __syncthreads();

    int o = tid >> 3, g = tid & 7;
    if (o < Dd){
        const float4* wj4 = (const float4*)(pjw + o*Hh);
        const float4* wi4 = (const float4*)(piw + o*Hh);
        #pragma unroll 1
        for (int rr = 0; rr < PROJ_ROWS; rr++){
            const float4* hj4 = (const float4*)(shj + rr*Hh);
            const float4* hs4 = (const float4*)(shi + rr*Hh);
            float pj = 0.f, pi = 0.f;
            #pragma unroll 6
            for (int it = g; it < Hh/4; it += 8){
                float4 wj = __ldg(&wj4[it]);
                float4 wi = __ldg(&wi4[it]);
                float4 hj = hj4[it];
                float4 hs = hs4[it];
                pj += wj.x*hj.x + wj.y*hj.y + wj.z*hj.z + wj.w*hj.w;
                pi += wi.x*hs.x + wi.y*hs.y + wi.z*hs.z + wi.w*hs.w;
            }
            #pragma unroll
            for (int d = 4; d > 0; d >>= 1){
                pj += __shfl_down_sync(0xffffffffu, pj, d, 8);
                pi += __shfl_down_sync(0xffffffffu, pi, d, 8);
            }
            if (g == 0){
                szj[rr*Dd + o] = pj;
                g_Zj[(r0+rr)*Dd + o] = pj;
                g_Zi[(r0+rr)*Dd + o] = pi;
            }
        }
    }
    __syncthreads();
    if (tid < Mm){
        #pragma unroll 1
        for (int rr = 0; rr < PROJ_ROWS; rr++){
            float a = 0.f;
            #pragma unroll
            for (int d = 0; d < Dd; d++)
                a += sw1[tid*96 + d] * szj[rr*Dd + d];
            g_Aj[(r0+rr)*Mm + tid] = a;
        }
    }
}

// ============================================================
// K2: pair logits v8 — square warp tiles (32 rows x 48 cols),
//  PTX mma, in-register reduce, partial logits per col-half.
// ============================================================
#define POFF_WH   0                       // 16896
#define POFF_F    16896                   // 22528 -> 39424
#define POFF_SLOG 39424                   // 2*512*4 = 4096 -> 43520
#define POFF_SZJ  43520                   // 128 -> 43648
#define POFF_SCW  43648                   // 768 -> 44416
#define POFF_SRED 44416                   // 32 -> 44448
#define PAIR_SMEM 44544

#define FCOLV(c) ((c) < 24 ? szj[(c)]*za[(c)] : \
                  (c) < 48 ? fabsf(szj[(c)-24]-za[(c)-24]) : \
                  (c) < 72 ? za[(c)-48] : 0.f)

__global__ __launch_bounds__(256, 3) void pair_wmma(
    const float* __restrict__ sb1,
    const float* __restrict__ sw2v, const float* __restrict__ sb2,
    const float* __restrict__ mask)
{
    extern __shared__ char ps[];
    __nv_bfloat16* Wh = (__nv_bfloat16*)(ps + POFF_WH);
    __nv_bfloat16* Fh = (__nv_bfloat16*)(ps + POFF_F);
    float*  slog = (float*)(ps + POFF_SLOG);
    float*  szj  = (float*)(ps + POFF_SZJ);
    float2* scw  = (float2*)(ps + POFF_SCW);
    float*  sred = (float*)(ps + POFF_SRED);

    int r = blockIdx.x, b = r >> 9;
    int tid = threadIdx.x, wid = tid >> 5, lane = tid & 31;

    for (int i = tid; i < 1056; i += 256)
        ((uint4*)Wh)[i] = ((const uint4*)g_Wph)[i];
    if (tid < Dd) szj[tid] = g_Zj[r*Dd + tid];
    if (tid < Mm)
        scw[tid] = make_float2(g_Aj[r*Mm + tid] + sb1[tid], sw2v[tid]);
    if (tid < 128){
        uint4 z = make_uint4(0u,0u,0u,0u);
        uint4* zp = (uint4*)&Fh[tid*88 + 72];
        zp[0] = z; zp[1] = z;
    }
    __syncthreads();

    unsigned sF = smem_cast(Fh);
    unsigned sW = smem_cast(Wh);
    int bhalf = tid >> 7;
    int brow  = tid & 127;
    int l16   = lane & 15;
    int lhi8  = (lane >> 4) * 8;
    int c0    = (lane & 3) * 2;
    int R0 = (wid & 3) * 32;       // row group (4 x 32 rows)
    int CB = (wid >> 2) * 48;      // col half (2 x 48 cols)

    #pragma unroll 1
    for (int chunk = 0; chunk < 4; chunk++){
        // ---- build F cols 0..71 ----
        {
            int t = chunk*128 + brow;
            const float4* zi4 = (const float4*)&g_Zi[(long)(b*Ss + t)*Dd];
            float za[24];
            #pragma unroll
            for (int q = 0; q < 6; q++){
                float4 v4 = __ldg(&zi4[q]);
                za[q*4+0]=v4.x; za[q*4+1]=v4.y; za[q*4+2]=v4.z; za[q*4+3]=v4.w;
            }
            if (bhalf == 0){
                uint4* dh = (uint4*)&Fh[brow*88];
                #pragma unroll
                for (int q = 0; q < 5; q++){
                    unsigned h4[4];
                    #pragma unroll
                    for (int e = 0; e < 4; e++){
                        int c = q*8 + e*2;
                        h4[e] = packh(FCOLV(c), FCOLV(c+1));
                    }
                    dh[q] = make_uint4(h4[0],h4[1],h4[2],h4[3]);
                }
            } else {
                uint4* dh = (uint4*)&Fh[brow*88 + 40];
                #pragma unroll
                for (int q = 0; q < 4; q++){
                    unsigned h4[4];
                    #pragma unroll
                    for (int e = 0; e < 4; e++){
                        int c = 40 + q*8 + e*2;
                        h4[e] = packh(FCOLV(c), FCOLV(c+1));
                    }
                    dh[q] = make_uint4(h4[0],h4[1],h4[2],h4[3]);
                }
            }
        }
        __syncthreads();

        // ---- MMA: 2 row-tiles x 3 col-groups x 2 nfrags ----
        float acc[12][4];    // [t*6 + g*2 + h][e]
        #pragma unroll
        for (int f = 0; f < 12; f++)
            #pragma unroll
            for (int e = 0; e < 4; e++) acc[f][e] = 0.f;

        #pragma unroll
        for (int k = 0; k < 5; k++){
            unsigned a0[4], a1[4];
            unsigned aaddr0 = sF + (unsigned)(((R0      + l16)*88 + k*16 + lhi8) * 2);
            unsigned aaddr1 = sF + (unsigned)(((R0 + 16 + l16)*88 + k*16 + lhi8) * 2);
            ldsm_x4(aaddr0, a0[0], a0[1], a0[2], a0[3]);
            ldsm_x4(aaddr1, a1[0], a1[1], a1[2], a1[3]);
            #pragma unroll
            for (int g = 0; g < 3; g++){
                unsigned bq[4];
                unsigned baddr = sW + (unsigned)(((CB + g*16 + l16)*88 + k*16 + lhi8) * 2);
                ldsm_x4(baddr, bq[0], bq[1], bq[2], bq[3]);
                mma16816(acc[g*2],         a0, bq[0], bq[2]);
                mma16816(acc[g*2 + 1],     a0, bq[1], bq[3]);
                mma16816(acc[6 + g*2],     a1, bq[0], bq[2]);
                mma16816(acc[6 + g*2 + 1], a1, bq[1], bq[3]);
            }
        }

        // ---- in-register reduce to partial logits ----
        float s00 = 0.f, s01 = 0.f, s10 = 0.f, s11 = 0.f;
        #pragma unroll
        for (int g = 0; g < 3; g++)
            #pragma unroll
            for (int h = 0; h < 2; h++){
                float4 c = *(const float4*)&scw[CB + g*16 + h*8 + c0];
                int f = g*2 + h;
                s00 += c.y * fmaxf(acc[f][0] + c.x, 0.f)
                     + c.w * fmaxf(acc[f][1] + c.z, 0.f);
                s01 += c.y * fmaxf(acc[f][2] + c.x, 0.f)
                     + c.w * fmaxf(acc[f][3] + c.z, 0.f);
                s10 += c.y * fmaxf(acc[6+f][0] + c.x, 0.f)
                     + c.w * fmaxf(acc[6+f][1] + c.z, 0.f);
                s11 += c.y * fmaxf(acc[6+f][2] + c.x, 0.f)
                     + c.w * fmaxf(acc[6+f][3] + c.z, 0.f);
            }
        s00 += __shfl_xor_sync(0xffffffffu, s00, 1);
        s00 += __shfl_xor_sync(0xffffffffu, s00, 2);
        s01 += __shfl_xor_sync(0xffffffffu, s01, 1);
        s01 += __shfl_xor_sync(0xffffffffu, s01, 2);
        s10 += __shfl_xor_sync(0xffffffffu, s10, 1);
        s10 += __shfl_xor_sync(0xffffffffu, s10, 2);
        s11 += __shfl_xor_sync(0xffffffffu, s11, 1);
        s11 += __shfl_xor_sync(0xffffffffu, s11, 2);
        if ((lane & 3) == 0){
            int row = lane >> 2;
            int base = (wid >> 2)*512 + chunk*128 + R0;
            slog[base + row]          = s00;
            slog[base + 8 + row]      = s01;
            slog[base + 16 + row]     = s10;
            slog[base + 24 + row]     = s11;
        }
        __syncthreads();
    }

    // ---- masked softmax over combined partial logits ----
    int t0 = tid, t1 = tid + 256;
    float lt0 = slog[t0] + slog[512 + t0] + sb2[0]
              + (1.f - mask[b*Ss + t0]) * (-3.402823466e38f);
    float lt1 = slog[t1] + slog[512 + t1] + sb2[0]
              + (1.f - mask[b*Ss + t1]) * (-3.402823466e38f);

    float mx = fmaxf(lt0, lt1);
    #pragma unroll
    for (int d = 16; d > 0; d >>= 1)
        mx = fmaxf(mx, __shfl_xor_sync(0xffffffffu, mx, d));
    if (lane == 0) sred[wid] = mx;
    __syncthreads();
    float bmax = sred[0];
    #pragma unroll
    for (int i = 1; i < 8; i++) bmax = fmaxf(bmax, sred[i]);

    float e0 = expf(lt0 - bmax);
    float e1 = expf(lt1 - bmax);
    float sm = e0 + e1;
    #pragma unroll
    for (int d = 16; d > 0; d >>= 1)
        sm += __shfl_xor_sync(0xffffffffu, sm, d);
    __syncthreads();
    if (lane == 0) sred[wid] = sm;
    __syncthreads();
    float tot = 0.f;
    #pragma unroll
    for (int i = 0; i < 8; i++) tot += sred[i];
    float inv = 1.f / tot;

    __nv_bfloat16 h, l;
    bsplit(e0 * inv, h, l);
    g_pbh[(long)r*Ss + t0] = h; g_pbl[(long)r*Ss + t0] = l;
    bsplit(e1 * inv, h, l);
    g_pbh[(long)r*Ss + t1] = h; g_pbl[(long)r*Ss + t1] = l;
}

// ============================================================
// K3: fp32 -> bf16 hi/lo split (vectorized)
// ============================================================
__global__ __launch_bounds__(256) void conv_split(
    const float* __restrict__ x, __nv_bfloat16* __restrict__ hi,
    __nv_bfloat16* __restrict__ lo, int n4)
{
    int i = blockIdx.x*256 + threadIdx.x;
    if (i >= n4) return;
    float4 v = ((const float4*)x)[i];
    __nv_bfloat16 h0,h1,h2,h3,l0,l1,l2,l3;
    bsplit(v.x,h0,l0); bsplit(v.y,h1,l1); bsplit(v.z,h2,l2); bsplit(v.w,h3,l3);
    __nv_bfloat162 p0, p1;
    p0.x=h0; p0.y=h1; p1.x=h2; p1.y=h3;
    ((__nv_bfloat162*)hi)[2*i]   = p0;
    ((__nv_bfloat162*)hi)[2*i+1] = p1;
    p0.x=l0; p0.y=l1; p1.x=l2; p1.y=l3;
    ((__nv_bfloat162*)lo)[2*i]   = p0;
    ((__nv_bfloat162*)lo)[2*i+1] = p1;
}

// ============================================================
// K4: fused ctx split-K reduce + msg_in build (all 3 segments)
// ============================================================
__device__ __forceinline__ void store4(__nv_bfloat16* hp, __nv_bfloat16* lp,
                                       float a, float b, float c, float d)
{
    __nv_bfloat16 h0,h1,h2,h3,l0,l1,l2,l3;
    bsplit(a,h0,l0); bsplit(b,h1,l1); bsplit(c,h2,l2); bsplit(d,h3,l3);
    __nv_bfloat162 p0, p1;
    p0.x=h0; p0.y=h1; p1.x=h2; p1.y=h3;
    ((__nv_bfloat162*)hp)[0] = p0; ((__nv_bfloat162*)hp)[1] = p1;
    p0.x=l0; p0.y=l1; p1.x=l2; p1.y=l3;
    ((__nv_bfloat162*)lp)[0] = p0; ((__nv_bfloat162*)lp)[1] = p1;
}
__global__ __launch_bounds__(256) void ctx_msgin_fused(
    const float* __restrict__ p, const float* __restrict__ Hj)
{
    long i4 = ((long)blockIdx.x * 256 + threadIdx.x) * 4;
    if (i4 >= (long)NROWS*Hh) return;
    long stride = 4L*Ss*Hh;   // = Bb*Ss*Hh
    float4 s = *(const float4*)&p[i4];
    #pragma unroll
    for (int n = 1; n < 4; n++){
        float4 v = *(const float4*)&p[n*stride + i4];
        s.x += v.x; s.y += v.y; s.z += v.z; s.w += v.w;
    }
    int r = (int)(i4 / Hh);
    int c = (int)(i4 % Hh);
    float4 hv = *(const float4*)&Hj[i4];
    long base = (long)r*H3 + c;
    store4(&g_m1h[base],      &g_m1l[base],      s.x, s.y, s.z, s.w);
    store4(&g_m1h[base+Hh],   &g_m1l[base+Hh],   hv.x, hv.y, hv.z, hv.w);
    store4(&g_m1h[base+2*Hh], &g_m1l[base+2*Hh],
           s.x*hv.x, s.y*hv.y, s.z*hv.z, s.w*hv.w);
}

// ============================================================
// K5: WMMA GEMM, split-K, raw fp32 partial store.
// ============================================================
template<bool TRANSB, int KSPLIT>
__global__ __launch_bounds__(256) void gemm_wmma(
    const __nv_bfloat16* __restrict__ Ah, const __nv_bfloat16* __restrict__ Al,
    const __nv_bfloat16* __restrict__ Bh, const __nv_bfloat16* __restrict__ Bl,
    float* __restrict__ Cpart, int N, int K, int ldA, int ldB,
    long strideA, long strideB, long strideC, long partStride)
{
    __shared__ __nv_bfloat16 As[2][128][40];
    __shared__ __nv_bfloat16 Bs[2][5120];

    int tid = threadIdx.x;
    int wid = tid >> 5;
    int wr = wid & 3, wc = wid >> 2;
    long row0 = (long)blockIdx.y * 128;
    long col0 = (long)blockIdx.x * 128;

    int zb = blockIdx.z / KSPLIT, zk = blockIdx.z % KSPLIT;
    int kcnt = K / KSPLIT, k0 = zk * kcnt;

    const __nv_bfloat16* APh = Ah + (long)zb * strideA;
    const __nv_bfloat16* APl = Al + (long)zb * strideA;
    const __nv_bfloat16* BPh = Bh + (long)zb * strideB;
    const __nv_bfloat16* BPl = Bl + (long)zb * strideB;
    float* Cb = Cpart + (long)zk * partStride + (long)zb * strideC;

    wmma::fragment<wmma::accumulator,16,16,16,float> acc[2][4];
    #pragma unroll
    for (int i = 0; i < 2; i++)
        #pragma unroll
        for (int j = 0; j < 4; j++) wmma::fill_fragment(acc[i][j], 0.f);

    #pragma unroll 1
    for (int kc = k0; kc < k0 + kcnt; kc += 32){
        #pragma unroll
        for (int t = tid; t < 512; t += 256){
            int r = t >> 2, seg = t & 3;
            long off = (row0 + r)*(long)ldA + kc + seg*8;
            *(float4*)&As[0][r][seg*8] = *(const float4*)(APh + off);
            *(float4*)&As[1][r][seg*8] = *(const float4*)(APl + off);
        }
        if (TRANSB){
            #pragma unroll
            for (int t = tid; t < 512; t += 256){
                int r = t >> 2, seg = t & 3;
                long off = (col0 + r)*(long)ldB + kc + seg*8;
                *(float4*)&Bs[0][r*40 + seg*8] = *(const float4*)(BPh + off);
                *(float4*)&Bs[1][r*40 + seg*8] = *(const float4*)(BPl + off);
            }
        } else {
            #pragma unroll
            for (int t = tid; t < 512; t += 256){
                int r = t >> 4, seg = t & 15;
                long off = (long)(kc + r)*ldB + col0 + seg*8;
                *(float4*)&Bs[0][r*136 + seg*8] = *(const float4*)(BPh + off);
                *(float4*)&Bs[1][r*136 + seg*8] = *(const float4*)(BPl + off);
            }
        }
        __syncthreads();

        #pragma unroll
        for (int ks = 0; ks < 2; ks++){
            wmma::fragment<wmma::matrix_a,16,16,16,__nv_bfloat16,wmma::row_major> afh[2], afl[2];
            #pragma unroll
            for (int i = 0; i < 2; i++){
                wmma::load_matrix_sync(afh[i], &As[0][wr*32 + i*16][ks*16], 40);
                wmma::load_matrix_sync(afl[i], &As[1][wr*32 + i*16][ks*16], 40);
            }
            if (TRANSB){
                #pragma unroll
                for (int j = 0; j < 4; j++){
                    wmma::fragment<wmma::matrix_b,16,16,16,__nv_bfloat16,wmma::col_major> bfh, bfl;
                    int nb = wc*64 + j*16;
                    wmma::load_matrix_sync(bfh, &Bs[0][nb*40 + ks*16], 40);
                    wmma::load_matrix_sync(bfl, &Bs[1][nb*40 + ks*16], 40);
                    #pragma unroll
                    for (int i = 0; i < 2; i++){
                        wmma::mma_sync(acc[i][j], afh[i], bfh, acc[i][j]);
                        wmma::mma_sync(acc[i][j], afh[i], bfl, acc[i][j]);
                        wmma::mma_sync(acc[i][j], afl[i], bfh, acc[i][j]);
                    }
                }
            } else {
                #pragma unroll
                for (int j = 0; j < 4; j++){
                    wmma::fragment<wmma::matrix_b,16,16,16,__nv_bfloat16,wmma::row_major> bfh, bfl;
                    int nb = wc*64 + j*16;
                    wmma::load_matrix_sync(bfh, &Bs[0][(ks*16)*136 + nb], 136);
                    wmma::load_matrix_sync(bfl, &Bs[1][(ks*16)*136 + nb], 136);
                    #pragma unroll
                    for (int i = 0; i < 2; i++){
                        wmma::mma_sync(acc[i][j], afh[i], bfh, acc[i][j]);
                        wmma::mma_sync(acc[i][j], afh[i], bfl, acc[i][j]);
                        wmma::mma_sync(acc[i][j], afl[i], bfh, acc[i][j]);
                    }
                }
            }
        }
        __syncthreads();
    }

    #pragma unroll
    for (int i = 0; i < 2; i++)
        #pragma unroll
        for (int j = 0; j < 4; j++){
            float* cp = Cb + (row0 + wr*32 + i*16)*(long)N + col0 + wc*64 + j*16;
            wmma::store_matrix_sync(cp, acc[i][j], N, wmma::mem_row_major);
        }
}

// ============================================================
// K6: split-K reduce + epilogues
// ============================================================
template<int NS, int MODE>
__global__ __launch_bounds__(256) void reduce_ns(
    const float* __restrict__ p, long partStride,
    float* __restrict__ outf,
    __nv_bfloat16* __restrict__ oh, __nv_bfloat16* __restrict__ ol,
    const float* __restrict__ bias, const float* __restrict__ alpha_p,
    int N, long total)
{
    long i4 = ((long)blockIdx.x * 256 + threadIdx.x) * 4;
    if (i4 >= total) return;
    float4 s = *(const float4*)&p[i4];
    #pragma unroll
    for (int n = 1; n < NS; n++){
        float4 v = *(const float4*)&p[n*partStride + i4];
        s.x += v.x; s.y += v.y; s.z += v.z; s.w += v.w;
    }
    if (MODE >= 1){
        int col = (int)(i4 % N);
        float4 bi = *(const float4*)&bias[col];
        s.x += bi.x; s.y += bi.y; s.z += bi.z; s.w += bi.w;
    }
    if (MODE == 1){
        s.x = fmaxf(s.x, 0.f); s.y = fmaxf(s.y, 0.f);
        s.z = fmaxf(s.z, 0.f); s.w = fmaxf(s.w, 0.f);
        __nv_bfloat16 h0,h1,h2,h3,l0,l1,l2,l3;
        bsplit(s.x,h0,l0); bsplit(s.y,h1,l1); bsplit(s.z,h2,l2); bsplit(s.w,h3,l3);
        __nv_bfloat162 ph0, ph1, pl0, pl1;
        ph0.x=h0; ph0.y=h1; ph1.x=h2; ph1.y=h3;
        pl0.x=l0; pl0.y=l1; pl1.x=l2; pl1.y=l3;
        *(__nv_bfloat162*)&oh[i4]   = ph0;
        *(__nv_bfloat162*)&oh[i4+2] = ph1;
        *(__nv_bfloat162*)&ol[i4]   = pl0;
        *(__nv_bfloat162*)&ol[i4+2] = pl1;
    } else {
        if (MODE == 2){
            float a = __ldg(alpha_p);
            s.x *= a; s.y *= a; s.z *= a; s.w *= a;
        }
        *(float4*)&outf[i4] = s;
    }
}

// ============================================================
extern "C" void kernel_launch(void* const* d_in, const int* in_sizes, int n_in,
                              void* d_out, int out_size)
{
    const float* Hj   = (const float*)d_in[0];
    const float* Hi   = (const float*)d_in[1];
    const float* mask = (const float*)d_in[2];
    const float* pjw  = (const float*)d_in[3];
    const float* piw  = (const float*)d_in[4];
    const float* sw1  = (const float*)d_in[5];
    const float* sb1  = (const float*)d_in[6];
    const float* sw2  = (const float*)d_in[7];
    const float* sb2  = (const float*)d_in[8];
    const float* vw1  = (const float*)d_in[9];
    const float* vb1  = (const float*)d_in[10];
    const float* vw2  = (const float*)d_in[11];
    const float* vb2  = (const float*)d_in[12];
    const float* alpha= (const float*)d_in[13];
    float* out = (float*)d_out;

    void *ppbh, *ppbl, *phih, *phil, *pm1h, *pm1l;
    void *pw1h, *pw1l, *phdh, *phdl, *pw2h, *pw2l;
    void *ppc, *pp1, *pp2;
    cudaGetSymbolAddress(&ppbh, g_pbh);  cudaGetSymbolAddress(&ppbl, g_pbl);
    cudaGetSymbolAddress(&phih, g_hih);  cudaGetSymbolAddress(&phil, g_hil);
    cudaGetSymbolAddress(&pm1h, g_m1h);  cudaGetSymbolAddress(&pm1l, g_m1l);
    cudaGetSymbolAddress(&pw1h, g_w1h);  cudaGetSymbolAddress(&pw1l, g_w1l);
    cudaGetSymbolAddress(&phdh, g_hidh); cudaGetSymbolAddress(&phdl, g_hidl);
    cudaGetSymbolAddress(&pw2h, g_w2h);  cudaGetSymbolAddress(&pw2l, g_w2l);
    cudaGetSymbolAddress(&ppc, g_partc);
    cudaGetSymbolAddress(&pp1, g_part1);
    cudaGetSymbolAddress(&pp2, g_part2);

    cudaFuncSetAttribute(pair_wmma, cudaFuncAttributeMaxDynamicSharedMemorySize, PAIR_SMEM);
    cudaFuncSetAttribute(proj_kernel, cudaFuncAttributeMaxDynamicSharedMemorySize, PROJ_SMEM);

    // 0: proj (8 rows/CTA)
    proj_kernel<<<NROWS/PROJ_ROWS, 256, PROJ_SMEM>>>(Hj, Hi, pjw, piw, sw1);
    // 1: W' precompute
    wsplit_pair<<<(96*88 + 255)/256, 256>>>(sw1);
    // 2: Hi -> bf16 hi/lo
    conv_split<<<(NROWS*Hh/4 + 255)/256, 256>>>(Hi, (__nv_bfloat16*)phih,
                                                (__nv_bfloat16*)phil, NROWS*Hh/4);
    // 3: pair
    pair_wmma<<<NROWS, 256, PAIR_SMEM>>>(sb1, sw2, sb2, mask);
    // 4: ctx partials = probs @ Hi  [NN, batched, split-K=4]
    {
        dim3 g(Hh/128, Ss/128, Bb*4);
        gemm_wmma<false,4><<<g, 256>>>(
            (const __nv_bfloat16*)ppbh, (const __nv_bfloat16*)ppbl,
            (const __nv_bfloat16*)phih, (const __nv_bfloat16*)phil,
            (float*)ppc, Hh, Ss, Ss, Hh,
            (long)Ss*Ss, (long)Ss*Hh, (long)Ss*Hh, 4L*Ss*Hh);
    }
    // 5: fused ctx reduce + msg_in build
    {
        long total = (long)NROWS*Hh;
        ctx_msgin_fused<<<(int)((total/4 + 255)/256), 256>>>(
            (const float*)ppc, Hj);
    }
    // 6: vw1 -> bf16 hi/lo
    conv_split<<<(OH*H3/4 + 255)/256, 256>>>(vw1, (__nv_bfloat16*)pw1h,
                                             (__nv_bfloat16*)pw1l, OH*H3/4);
    // 7: gemm1 partials  [NT, split-K=3]
    {
        dim3 g(OH/128, NROWS/128, 3);
        gemm_wmma<true,3><<<g, 256>>>(
            (const __nv_bfloat16*)pm1h, (const __nv_bfloat16*)pm1l,
            (const __nv_bfloat16*)pw1h, (const __nv_bfloat16*)pw1l,
            (float*)pp1, OH, H3, H3, H3,
            0, 0, 0, (long)NROWS*OH);
    }
    // 8: hid reduce (bias+relu -> bf16 split)
    {
        long total = (long)NROWS*OH;
        reduce_ns<3,1><<<(int)((total/4 + 255)/256), 256>>>(
            (const float*)pp1, (long)NROWS*OH, nullptr,
            (__nv_bfloat16*)phdh, (__nv_bfloat16*)phdl, vb1, nullptr, OH, total);
    }
    // 9: vw2 -> bf16 hi/lo
    conv_split<<<(Hh*OH/4 + 255)/256, 256>>>(vw2, (__nv_bfloat16*)pw2h,
                                             (__nv_bfloat16*)pw2l, Hh*OH/4);
    // 10: gemm2 partials  [NT, split-K=3]
    {
        dim3 g(Hh/128, NROWS/128, 3);
        gemm_wmma<true,3><<<g, 256>>>(
            (const __nv_bfloat16*)phdh, (const __nv_bfloat16*)phdl,
            (const __nv_bfloat16*)pw2h, (const __nv_bfloat16*)pw2l,
            (float*)pp2, Hh, OH, OH, OH,
            0, 0, 0, (long)NROWS*Hh);
    }
    // 11: out reduce (bias, alpha)
    {
        long total = (long)NROWS*Hh;
        reduce_ns<3,2><<<(int)((total/4 + 255)/256), 256>>>(
            (const float*)pp2, (long)NROWS*Hh, out,
            nullptr, nullptr, vb2, alpha, Hh, total);
    }
    (void)in_sizes; (void)n_in; (void)out_size;
}

// round 15
// speedup vs baseline: 2.0297x; 1.1019x over previous
#include <cuda_runtime.h>
#include <cuda_bf16.h>
#include <mma.h>
#include <math.h>
#include <cstdint>

using namespace nvcuda;

#define Bb 4
#define Ss 512
#define Hh 768
#define Dd 24
#define Mm 96
#define OH 768
#define H3 2304
#define NROWS (Bb*Ss)   // 2048

typedef unsigned long long ull;

// ---- scratch ----
__device__ __align__(16) float g_Zj[NROWS*Dd];
__device__ __align__(16) float g_Zi[NROWS*Dd];
__device__ __align__(16) float g_Aj[NROWS*Mm];
__device__ __align__(16) __nv_bfloat16 g_Wph[96*88];
__device__ __align__(16) __nv_bfloat16 g_pbh[(long)Bb*Ss*Ss];
__device__ __align__(16) __nv_bfloat16 g_pbl[(long)Bb*Ss*Ss];
__device__ __align__(16) __nv_bfloat16 g_hih[(long)NROWS*Hh];
__device__ __align__(16) __nv_bfloat16 g_hil[(long)NROWS*Hh];
__device__ __align__(16) __nv_bfloat16 g_m1h[(long)NROWS*H3];
__device__ __align__(16) __nv_bfloat16 g_m1l[(long)NROWS*H3];
__device__ __align__(16) __nv_bfloat16 g_w1h[(long)OH*H3];
__device__ __align__(16) __nv_bfloat16 g_w1l[(long)OH*H3];
__device__ __align__(16) __nv_bfloat16 g_hidh[(long)NROWS*OH];
__device__ __align__(16) __nv_bfloat16 g_hidl[(long)NROWS*OH];
__device__ __align__(16) __nv_bfloat16 g_w2h[(long)Hh*OH];
__device__ __align__(16) __nv_bfloat16 g_w2l[(long)Hh*OH];
__device__ __align__(16) float g_partc[4L*Bb*Ss*Hh];
__device__ __align__(16) float g_part1[3L*NROWS*OH];
__device__ __align__(16) float g_part2[3L*NROWS*Hh];

// bf16 hi/lo split
__device__ __forceinline__ void bsplit(float v, __nv_bfloat16& h, __nv_bfloat16& l){
    h = __float2bfloat16(v);
    l = __float2bfloat16(v - __bfloat162float(h));
}
__device__ __forceinline__ unsigned packh(float a, float b){
    __nv_bfloat162 p;
    p.x = __float2bfloat16(a);
    p.y = __float2bfloat16(b);
    return *(unsigned*)&p;
}

// ---- PTX helpers (base ISA, sm_80+) ----
__device__ __forceinline__ unsigned smem_cast(const void* p){
    return (unsigned)__cvta_generic_to_shared(p);
}
__device__ __forceinline__ void ldsm_x4(unsigned addr, unsigned& r0, unsigned& r1,
                                        unsigned& r2, unsigned& r3){
    asm volatile("ldmatrix.sync.aligned.m8n8.x4.shared.b16 {%0,%1,%2,%3}, [%4];"
        : "=r"(r0), "=r"(r1), "=r"(r2), "=r"(r3) : "r"(addr));
}
__device__ __forceinline__ void mma16816(float* d, const unsigned* a,
                                         unsigned b0, unsigned b1){
    asm volatile(
        "mma.sync.aligned.m16n8k16.row.col.f32.bf16.bf16.f32 "
        "{%0,%1,%2,%3}, {%4,%5,%6,%7}, {%8,%9}, {%0,%1,%2,%3};"
        : "+f"(d[0]), "+f"(d[1]), "+f"(d[2]), "+f"(d[3])
        : "r"(a[0]), "r"(a[1]), "r"(a[2]), "r"(a[3]), "r"(b0), "r"(b1));
}
__device__ __forceinline__ void cpasync16(unsigned dst, const void* src){
    asm volatile("cp.async.cg.shared.global [%0], [%1], 16;"
        :: "r"(dst), "l"(src));
}
#define CP_COMMIT() asm volatile("cp.async.commit_group;" ::: "memory")
#define CP_WAIT1()  asm volatile("cp.async.wait_group 1;" ::: "memory")
#define CP_WAIT0()  asm volatile("cp.async.wait_group 0;" ::: "memory")

// ============================================================
// K0: precompute W' = [Wc | Wd | Wb | 0] (96 x 88) bf16
// ============================================================
__global__ __launch_bounds__(256) void wsplit_pair(const float* __restrict__ sw1)
{
    int i = blockIdx.x*256 + threadIdx.x;
    if (i >= 96*88) return;
    int m = i / 88, k = i % 88;
    float wv = 0.f;
    if (k < 24)      wv = sw1[m*96 + 48 + k];
    else if (k < 48) wv = sw1[m*96 + 72 + (k-24)];
    else if (k < 72) wv = sw1[m*96 + 24 + (k-48)];
    g_Wph[i] = __float2bfloat16(wv);
}

// ============================================================
// K1: proj v2 — 8 rows per CTA
// ============================================================
#define PROJ_ROWS 8
#define PROJ_SMEM (PROJ_ROWS*Hh*2*4 + PROJ_ROWS*Dd*4 + 128)
__global__ __launch_bounds__(256) void proj_kernel(
    const float* __restrict__ Hj, const float* __restrict__ Hi,
    const float* __restrict__ pjw, const float* __restrict__ piw,
    const float* __restrict__ sw1)
{
    extern __shared__ float psm[];
    float* shj = psm;
    float* shi = psm + PROJ_ROWS*Hh;
    float* szj = psm + 2*PROJ_ROWS*Hh;
    long r0 = (long)blockIdx.x * PROJ_ROWS;
    int tid = threadIdx.x;

    const float4* Hj4 = (const float4*)(Hj + r0*Hh);
    const float4* Hi4 = (const float4*)(Hi + r0*Hh);
    float4* shj4 = (float4*)shj;
    float4* shi4 = (float4*)shi;
    #pragma unroll 4
    for (int i = tid; i < PROJ_ROWS*Hh/4; i += 256){
        shj4[i] = Hj4[i];
        shi4[i] = Hi4[i];
    }
    __syncthreads();

    int o = tid >> 3, g = tid & 7;
    if (o < Dd){
        const float4* wj4 = (const float4*)(pjw + o*Hh);
        const float4* wi4 = (const float4*)(piw + o*Hh);
        #pragma unroll 1
        for (int rr = 0; rr < PROJ_ROWS; rr++){
            const float4* hj4 = (const float4*)(shj + rr*Hh);
            const float4* hs4 = (const float4*)(shi + rr*Hh);
            float pj = 0.f, pi = 0.f;
            #pragma unroll 6
            for (int it = g; it < Hh/4; it += 8){
                float4 wj = __ldg(&wj4[it]);
                float4 wi = __ldg(&wi4[it]);
                float4 hj = hj4[it];
                float4 hs = hs4[it];
                pj += wj.x*hj.x + wj.y*hj.y + wj.z*hj.z + wj.w*hj.w;
                pi += wi.x*hs.x + wi.y*hs.y + wi.z*hs.z + wi.w*hs.w;
            }
            #pragma unroll
            for (int d = 4; d > 0; d >>= 1){
                pj += __shfl_down_sync(0xffffffffu, pj, d, 8);
                pi += __shfl_down_sync(0xffffffffu, pi, d, 8);
            }
            if (g == 0){
                szj[rr*Dd + o] = pj;
                g_Zj[(r0+rr)*Dd + o] = pj;
                g_Zi[(r0+rr)*Dd + o] = pi;
            }
        }
    }
    __syncthreads();
    if (tid < Mm){
        #pragma unroll 1
        for (int rr = 0; rr < PROJ_ROWS; rr++){
            float a = 0.f;
            #pragma unroll
            for (int d = 0; d < Dd; d++)
                a += sw1[tid*96 + d] * szj[rr*Dd + d];
            g_Aj[(r0+rr)*Mm + tid] = a;
        }
    }
}

// ============================================================
// K2: pair logits v8 — square warp tiles, PTX mma, reg reduce.
// ============================================================
#define POFF_WH   0
#define POFF_F    16896
#define POFF_SLOG 39424
#define POFF_SZJ  43520
#define POFF_SCW  43648
#define POFF_SRED 44416
#define PAIR_SMEM 44544

#define FCOLV(c) ((c) < 24 ? szj[(c)]*za[(c)] : \
                  (c) < 48 ? fabsf(szj[(c)-24]-za[(c)-24]) : \
                  (c) < 72 ? za[(c)-48] : 0.f)

__global__ __launch_bounds__(256, 3) void pair_wmma(
    const float* __restrict__ sb1,
    const float* __restrict__ sw2v, const float* __restrict__ sb2,
    const float* __restrict__ mask)
{
    extern __shared__ char ps[];
    __nv_bfloat16* Wh = (__nv_bfloat16*)(ps + POFF_WH);
    __nv_bfloat16* Fh = (__nv_bfloat16*)(ps + POFF_F);
    float*  slog = (float*)(ps + POFF_SLOG);
    float*  szj  = (float*)(ps + POFF_SZJ);
    float2* scw  = (float2*)(ps + POFF_SCW);
    float*  sred = (float*)(ps + POFF_SRED);

    int r = blockIdx.x, b = r >> 9;
    int tid = threadIdx.x, wid = tid >> 5, lane = tid & 31;

    for (int i = tid; i < 1056; i += 256)
        ((uint4*)Wh)[i] = ((const uint4*)g_Wph)[i];
    if (tid < Dd) szj[tid] = g_Zj[r*Dd + tid];
    if (tid < Mm)
        scw[tid] = make_float2(g_Aj[r*Mm + tid] + sb1[tid], sw2v[tid]);
    if (tid < 128){
        uint4 z = make_uint4(0u,0u,0u,0u);
        uint4* zp = (uint4*)&Fh[tid*88 + 72];
        zp[0] = z; zp[1] = z;
    }
    __syncthreads();

    unsigned sF = smem_cast(Fh);
    unsigned sW = smem_cast(Wh);
    int bhalf = tid >> 7;
    int brow  = tid & 127;
    int l16   = lane & 15;
    int lhi8  = (lane >> 4) * 8;
    int c0    = (lane & 3) * 2;
    int R0 = (wid & 3) * 32;
    int CB = (wid >> 2) * 48;

    #pragma unroll 1
    for (int chunk = 0; chunk < 4; chunk++){
        {
            int t = chunk*128 + brow;
            const float4* zi4 = (const float4*)&g_Zi[(long)(b*Ss + t)*Dd];
            float za[24];
            #pragma unroll
            for (int q = 0; q < 6; q++){
                float4 v4 = __ldg(&zi4[q]);
                za[q*4+0]=v4.x; za[q*4+1]=v4.y; za[q*4+2]=v4.z; za[q*4+3]=v4.w;
            }
            if (bhalf == 0){
                uint4* dh = (uint4*)&Fh[brow*88];
                #pragma unroll
                for (int q = 0; q < 5; q++){
                    unsigned h4[4];
                    #pragma unroll
                    for (int e = 0; e < 4; e++){
                        int c = q*8 + e*2;
                        h4[e] = packh(FCOLV(c), FCOLV(c+1));
                    }
                    dh[q] = make_uint4(h4[0],h4[1],h4[2],h4[3]);
                }
            } else {
                uint4* dh = (uint4*)&Fh[brow*88 + 40];
                #pragma unroll
                for (int q = 0; q < 4; q++){
                    unsigned h4[4];
                    #pragma unroll
                    for (int e = 0; e < 4; e++){
                        int c = 40 + q*8 + e*2;
                        h4[e] = packh(FCOLV(c), FCOLV(c+1));
                    }
                    dh[q] = make_uint4(h4[0],h4[1],h4[2],h4[3]);
                }
            }
        }
        __syncthreads();

        float acc[12][4];
        #pragma unroll
        for (int f = 0; f < 12; f++)
            #pragma unroll
            for (int e = 0; e < 4; e++) acc[f][e] = 0.f;

        #pragma unroll
        for (int k = 0; k < 5; k++){
            unsigned a0[4], a1[4];
            unsigned aaddr0 = sF + (unsigned)(((R0      + l16)*88 + k*16 + lhi8) * 2);
            unsigned aaddr1 = sF + (unsigned)(((R0 + 16 + l16)*88 + k*16 + lhi8) * 2);
            ldsm_x4(aaddr0, a0[0], a0[1], a0[2], a0[3]);
            ldsm_x4(aaddr1, a1[0], a1[1], a1[2], a1[3]);
            #pragma unroll
            for (int g = 0; g < 3; g++){
                unsigned bq[4];
                unsigned baddr = sW + (unsigned)(((CB + g*16 + l16)*88 + k*16 + lhi8) * 2);
                ldsm_x4(baddr, bq[0], bq[1], bq[2], bq[3]);
                mma16816(acc[g*2],         a0, bq[0], bq[2]);
                mma16816(acc[g*2 + 1],     a0, bq[1], bq[3]);
                mma16816(acc[6 + g*2],     a1, bq[0], bq[2]);
                mma16816(acc[6 + g*2 + 1], a1, bq[1], bq[3]);
            }
        }

        float s00 = 0.f, s01 = 0.f, s10 = 0.f, s11 = 0.f;
        #pragma unroll
        for (int g = 0; g < 3; g++)
            #pragma unroll
            for (int h = 0; h < 2; h++){
                float4 c = *(const float4*)&scw[CB + g*16 + h*8 + c0];
                int f = g*2 + h;
                s00 += c.y * fmaxf(acc[f][0] + c.x, 0.f)
                     + c.w * fmaxf(acc[f][1] + c.z, 0.f);
                s01 += c.y * fmaxf(acc[f][2] + c.x, 0.f)
                     + c.w * fmaxf(acc[f][3] + c.z, 0.f);
                s10 += c.y * fmaxf(acc[6+f][0] + c.x, 0.f)
                     + c.w * fmaxf(acc[6+f][1] + c.z, 0.f);
                s11 += c.y * fmaxf(acc[6+f][2] + c.x, 0.f)
                     + c.w * fmaxf(acc[6+f][3] + c.z, 0.f);
            }
        s00 += __shfl_xor_sync(0xffffffffu, s00, 1);
        s00 += __shfl_xor_sync(0xffffffffu, s00, 2);
        s01 += __shfl_xor_sync(0xffffffffu, s01, 1);
        s01 += __shfl_xor_sync(0xffffffffu, s01, 2);
        s10 += __shfl_xor_sync(0xffffffffu, s10, 1);
        s10 += __shfl_xor_sync(0xffffffffu, s10, 2);
        s11 += __shfl_xor_sync(0xffffffffu, s11, 1);
        s11 += __shfl_xor_sync(0xffffffffu, s11, 2);
        if ((lane & 3) == 0){
            int row = lane >> 2;
            int base = (wid >> 2)*512 + chunk*128 + R0;
            slog[base + row]          = s00;
            slog[base + 8 + row]      = s01;
            slog[base + 16 + row]     = s10;
            slog[base + 24 + row]     = s11;
        }
        __syncthreads();
    }

    int t0 = tid, t1 = tid + 256;
    float lt0 = slog[t0] + slog[512 + t0] + sb2[0]
              + (1.f - mask[b*Ss + t0]) * (-3.402823466e38f);
    float lt1 = slog[t1] + slog[512 + t1] + sb2[0]
              + (1.f - mask[b*Ss + t1]) * (-3.402823466e38f);

    float mx = fmaxf(lt0, lt1);
    #pragma unroll
    for (int d = 16; d > 0; d >>= 1)
        mx = fmaxf(mx, __shfl_xor_sync(0xffffffffu, mx, d));
    if (lane == 0) sred[wid] = mx;
    __syncthreads();
    float bmax = sred[0];
    #pragma unroll
    for (int i = 1; i < 8; i++) bmax = fmaxf(bmax, sred[i]);

    float e0 = expf(lt0 - bmax);
    float e1 = expf(lt1 - bmax);
    float sm = e0 + e1;
    #pragma unroll
    for (int d = 16; d > 0; d >>= 1)
        sm += __shfl_xor_sync(0xffffffffu, sm, d);
    __syncthreads();
    if (lane == 0) sred[wid] = sm;
    __syncthreads();
    float tot = 0.f;
    #pragma unroll
    for (int i = 0; i < 8; i++) tot += sred[i];
    float inv = 1.f / tot;

    __nv_bfloat16 h, l;
    bsplit(e0 * inv, h, l);
    g_pbh[(long)r*Ss + t0] = h; g_pbl[(long)r*Ss + t0] = l;
    bsplit(e1 * inv, h, l);
    g_pbh[(long)r*Ss + t1] = h; g_pbl[(long)r*Ss + t1] = l;
}

// ============================================================
// K3: fp32 -> bf16 hi/lo split (vectorized)
// ============================================================
__global__ __launch_bounds__(256) void conv_split(
    const float* __restrict__ x, __nv_bfloat16* __restrict__ hi,
    __nv_bfloat16* __restrict__ lo, int n4)
{
    int i = blockIdx.x*256 + threadIdx.x;
    if (i >= n4) return;
    float4 v = ((const float4*)x)[i];
    __nv_bfloat16 h0,h1,h2,h3,l0,l1,l2,l3;
    bsplit(v.x,h0,l0); bsplit(v.y,h1,l1); bsplit(v.z,h2,l2); bsplit(v.w,h3,l3);
    __nv_bfloat162 p0, p1;
    p0.x=h0; p0.y=h1; p1.x=h2; p1.y=h3;
    ((__nv_bfloat162*)hi)[2*i]   = p0;
    ((__nv_bfloat162*)hi)[2*i+1] = p1;
    p0.x=l0; p0.y=l1; p1.x=l2; p1.y=l3;
    ((__nv_bfloat162*)lo)[2*i]   = p0;
    ((__nv_bfloat162*)lo)[2*i+1] = p1;
}

// ============================================================
// K4: fused ctx split-K reduce + msg_in build
// ============================================================
__device__ __forceinline__ void store4(__nv_bfloat16* hp, __nv_bfloat16* lp,
                                       float a, float b, float c, float d)
{
    __nv_bfloat16 h0,h1,h2,h3,l0,l1,l2,l3;
    bsplit(a,h0,l0); bsplit(b,h1,l1); bsplit(c,h2,l2); bsplit(d,h3,l3);
    __nv_bfloat162 p0, p1;
    p0.x=h0; p0.y=h1; p1.x=h2; p1.y=h3;
    ((__nv_bfloat162*)hp)[0] = p0; ((__nv_bfloat162*)hp)[1] = p1;
    p0.x=l0; p0.y=l1; p1.x=l2; p1.y=l3;
    ((__nv_bfloat162*)lp)[0] = p0; ((__nv_bfloat162*)lp)[1] = p1;
}
__global__ __launch_bounds__(256) void ctx_msgin_fused(
    const float* __restrict__ p, const float* __restrict__ Hj)
{
    long i4 = ((long)blockIdx.x * 256 + threadIdx.x) * 4;
    if (i4 >= (long)NROWS*Hh) return;
    long stride = 4L*Ss*Hh;
    float4 s = *(const float4*)&p[i4];
    #pragma unroll
    for (int n = 1; n < 4; n++){
        float4 v = *(const float4*)&p[n*stride + i4];
        s.x += v.x; s.y += v.y; s.z += v.z; s.w += v.w;
    }
    int r = (int)(i4 / Hh);
    int c = (int)(i4 % Hh);
    float4 hv = *(const float4*)&Hj[i4];
    long base = (long)r*H3 + c;
    store4(&g_m1h[base],      &g_m1l[base],      s.x, s.y, s.z, s.w);
    store4(&g_m1h[base+Hh],   &g_m1l[base+Hh],   hv.x, hv.y, hv.z, hv.w);
    store4(&g_m1h[base+2*Hh], &g_m1l[base+2*Hh],
           s.x*hv.x, s.y*hv.y, s.z*hv.z, s.w*hv.w);
}

// ============================================================
// K5: WMMA GEMM, split-K, cp.async double-buffered staging.
//  dynamic smem: A[buf][hl] 4x10240B, then B[buf][hl] 4x10240B.
// ============================================================
#define GEMM_SMEM 81920
#define HLSZ 10240   // bytes per (buf,hl) plane (5120 bf16)

template<bool TRANSB, int KSPLIT>
__global__ __launch_bounds__(256) void gemm_wmma(
    const __nv_bfloat16* __restrict__ Ah, const __nv_bfloat16* __restrict__ Al,
    const __nv_bfloat16* __restrict__ Bh, const __nv_bfloat16* __restrict__ Bl,
    float* __restrict__ Cpart, int N, int K, int ldA, int ldB,
    long strideA, long strideB, long strideC, long partStride)
{
    extern __shared__ char gsm[];
    unsigned sbase = smem_cast(gsm);

    int tid = threadIdx.x;
    int wid = tid >> 5;
    int wr = wid & 3, wc = wid >> 2;
    long row0 = (long)blockIdx.y * 128;
    long col0 = (long)blockIdx.x * 128;

    int zb = blockIdx.z / KSPLIT, zk = blockIdx.z % KSPLIT;
    int kcnt = K / KSPLIT, k0 = zk * kcnt;

    const __nv_bfloat16* APh = Ah + (long)zb * strideA;
    const __nv_bfloat16* APl = Al + (long)zb * strideA;
    const __nv_bfloat16* BPh = Bh + (long)zb * strideB;
    const __nv_bfloat16* BPl = Bl + (long)zb * strideB;
    float* Cb = Cpart + (long)zk * partStride + (long)zb * strideC;

    // staging thread roles
    int a_r = tid >> 2, a_seg = tid & 3;          // two passes: rows tid>>2 and +64
    int bn_r = tid >> 4, bn_seg = tid & 15;       // NN

    wmma::fragment<wmma::accumulator,16,16,16,float> acc[2][4];
    #pragma unroll
    for (int i = 0; i < 2; i++)
        #pragma unroll
        for (int j = 0; j < 4; j++) wmma::fill_fragment(acc[i][j], 0.f);

    int nch = kcnt >> 5;

    // ---- staging macro: chunk at kc into buffer bi ----
    #define STAGE_CHUNK(bi, kc) do {                                         \
        unsigned abase = sbase + (bi)*2*HLSZ;                                \
        _Pragma("unroll")                                                    \
        for (int t = 0; t < 2; t++){                                         \
            int rr = a_r + t*64;                                             \
            long off = (row0 + rr)*(long)ldA + (kc) + a_seg*8;               \
            unsigned d = abase + (unsigned)((rr*40 + a_seg*8)*2);            \
            cpasync16(d,        APh + off);                                  \
            cpasync16(d + HLSZ, APl + off);                                  \
        }                                                                    \
        unsigned bbase = sbase + 4*HLSZ + (bi)*2*HLSZ;                       \
        if (TRANSB){                                                         \
            _Pragma("unroll")                                                \
            for (int t = 0; t < 2; t++){                                     \
                int rr = a_r + t*64;                                         \
                long off = (col0 + rr)*(long)ldB + (kc) + a_seg*8;           \
                unsigned d = bbase + (unsigned)((rr*40 + a_seg*8)*2);        \
                cpasync16(d,        BPh + off);                              \
                cpasync16(d + HLSZ, BPl + off);                              \
            }                                                                \
        } else {                                                             \
            _Pragma("unroll")                                                \
            for (int t = 0; t < 2; t++){                                     \
                int rr = bn_r + t*16;                                        \
                long off = (long)((kc) + rr)*ldB + col0 + bn_seg*8;          \
                unsigned d = bbase + (unsigned)((rr*136 + bn_seg*8)*2);      \
                cpasync16(d,        BPh + off);                              \
                cpasync16(d + HLSZ, BPl + off);                              \
            }                                                                \
        }                                                                    \
        CP_COMMIT();                                                         \
    } while(0)

    STAGE_CHUNK(0, k0);

    #pragma unroll 1
    for (int s = 0; s < nch; s++){
        int cur = s & 1;
        if (s + 1 < nch){
            STAGE_CHUNK(cur ^ 1, k0 + (s+1)*32);
            CP_WAIT1();
        } else {
            CP_WAIT0();
        }
        __syncthreads();

        const __nv_bfloat16* Asb = (const __nv_bfloat16*)(gsm + cur*2*HLSZ);
        const __nv_bfloat16* Alb = Asb + 5120;
        const __nv_bfloat16* Bsb = (const __nv_bfloat16*)(gsm + 4*HLSZ + cur*2*HLSZ);
        const __nv_bfloat16* Blb = Bsb + 5120;

        #pragma unroll
        for (int ks = 0; ks < 2; ks++){
            wmma::fragment<wmma::matrix_a,16,16,16,__nv_bfloat16,wmma::row_major> afh[2], afl[2];
            #pragma unroll
            for (int i = 0; i < 2; i++){
                wmma::load_matrix_sync(afh[i], Asb + (wr*32 + i*16)*40 + ks*16, 40);
                wmma::load_matrix_sync(afl[i], Alb + (wr*32 + i*16)*40 + ks*16, 40);
            }
            if (TRANSB){
                #pragma unroll
                for (int j = 0; j < 4; j++){
                    wmma::fragment<wmma::matrix_b,16,16,16,__nv_bfloat16,wmma::col_major> bfh, bfl;
                    int nb = wc*64 + j*16;
                    wmma::load_matrix_sync(bfh, Bsb + nb*40 + ks*16, 40);
                    wmma::load_matrix_sync(bfl, Blb + nb*40 + ks*16, 40);
                    #pragma unroll
                    for (int i = 0; i < 2; i++){
                        wmma::mma_sync(acc[i][j], afh[i], bfh, acc[i][j]);
                        wmma::mma_sync(acc[i][j], afh[i], bfl, acc[i][j]);
                        wmma::mma_sync(acc[i][j], afl[i], bfh, acc[i][j]);
                    }
                }
            } else {
                #pragma unroll
                for (int j = 0; j < 4; j++){
                    wmma::fragment<wmma::matrix_b,16,16,16,__nv_bfloat16,wmma::row_major> bfh, bfl;
                    int nb = wc*64 + j*16;
                    wmma::load_matrix_sync(bfh, Bsb + (ks*16)*136 + nb, 136);
                    wmma::load_matrix_sync(bfl, Blb + (ks*16)*136 + nb, 136);
                    #pragma unroll
                    for (int i = 0; i < 2; i++){
                        wmma::mma_sync(acc[i][j], afh[i], bfh, acc[i][j]);
                        wmma::mma_sync(acc[i][j], afh[i], bfl, acc[i][j]);
                        wmma::mma_sync(acc[i][j], afl[i], bfh, acc[i][j]);
                    }
                }
            }
        }
        __syncthreads();
    }
    #undef STAGE_CHUNK

    #pragma unroll
    for (int i = 0; i < 2; i++)
        #pragma unroll
        for (int j = 0; j < 4; j++){
            float* cp = Cb + (row0 + wr*32 + i*16)*(long)N + col0 + wc*64 + j*16;
            wmma::store_matrix_sync(cp, acc[i][j], N, wmma::mem_row_major);
        }
}

// ============================================================
// K6: split-K reduce + epilogues
// ============================================================
template<int NS, int MODE>
__global__ __launch_bounds__(256) void reduce_ns(
    const float* __restrict__ p, long partStride,
    float* __restrict__ outf,
    __nv_bfloat16* __restrict__ oh, __nv_bfloat16* __restrict__ ol,
    const float* __restrict__ bias, const float* __restrict__ alpha_p,
    int N, long total)
{
    long i4 = ((long)blockIdx.x * 256 + threadIdx.x) * 4;
    if (i4 >= total) return;
    float4 s = *(const float4*)&p[i4];
    #pragma unroll
    for (int n = 1; n < NS; n++){
        float4 v = *(const float4*)&p[n*partStride + i4];
        s.x += v.x; s.y += v.y; s.z += v.z; s.w += v.w;
    }
    if (MODE >= 1){
        int col = (int)(i4 % N);
        float4 bi = *(const float4*)&bias[col];
        s.x += bi.x; s.y += bi.y; s.z += bi.z; s.w += bi.w;
    }
    if (MODE == 1){
        s.x = fmaxf(s.x, 0.f); s.y = fmaxf(s.y, 0.f);
        s.z = fmaxf(s.z, 0.f); s.w = fmaxf(s.w, 0.f);
        __nv_bfloat16 h0,h1,h2,h3,l0,l1,l2,l3;
        bsplit(s.x,h0,l0); bsplit(s.y,h1,l1); bsplit(s.z,h2,l2); bsplit(s.w,h3,l3);
        __nv_bfloat162 ph0, ph1, pl0, pl1;
        ph0.x=h0; ph0.y=h1; ph1.x=h2; ph1.y=h3;
        pl0.x=l0; pl0.y=l1; pl1.x=l2; pl1.y=l3;
        *(__nv_bfloat162*)&oh[i4]   = ph0;
        *(__nv_bfloat162*)&oh[i4+2] = ph1;
        *(__nv_bfloat162*)&ol[i4]   = pl0;
        *(__nv_bfloat162*)&ol[i4+2] = pl1;
    } else {
        if (MODE == 2){
            float a = __ldg(alpha_p);
            s.x *= a; s.y *= a; s.z *= a; s.w *= a;
        }
        *(float4*)&outf[i4] = s;
    }
}

// ============================================================
extern "C" void kernel_launch(void* const* d_in, const int* in_sizes, int n_in,
                              void* d_out, int out_size)
{
    const float* Hj   = (const float*)d_in[0];
    const float* Hi   = (const float*)d_in[1];
    const float* mask = (const float*)d_in[2];
    const float* pjw  = (const float*)d_in[3];
    const float* piw  = (const float*)d_in[4];
    const float* sw1  = (const float*)d_in[5];
    const float* sb1  = (const float*)d_in[6];
    const float* sw2  = (const float*)d_in[7];
    const float* sb2  = (const float*)d_in[8];
    const float* vw1  = (const float*)d_in[9];
    const float* vb1  = (const float*)d_in[10];
    const float* vw2  = (const float*)d_in[11];
    const float* vb2  = (const float*)d_in[12];
    const float* alpha= (const float*)d_in[13];
    float* out = (float*)d_out;

    void *ppbh, *ppbl, *phih, *phil, *pm1h, *pm1l;
    void *pw1h, *pw1l, *phdh, *phdl, *pw2h, *pw2l;
    void *ppc, *pp1, *pp2;
    cudaGetSymbolAddress(&ppbh, g_pbh);  cudaGetSymbolAddress(&ppbl, g_pbl);
    cudaGetSymbolAddress(&phih, g_hih);  cudaGetSymbolAddress(&phil, g_hil);
    cudaGetSymbolAddress(&pm1h, g_m1h);  cudaGetSymbolAddress(&pm1l, g_m1l);
    cudaGetSymbolAddress(&pw1h, g_w1h);  cudaGetSymbolAddress(&pw1l, g_w1l);
    cudaGetSymbolAddress(&phdh, g_hidh); cudaGetSymbolAddress(&phdl, g_hidl);
    cudaGetSymbolAddress(&pw2h, g_w2h);  cudaGetSymbolAddress(&pw2l, g_w2l);
    cudaGetSymbolAddress(&ppc, g_partc);
    cudaGetSymbolAddress(&pp1, g_part1);
    cudaGetSymbolAddress(&pp2, g_part2);

    cudaFuncSetAttribute(pair_wmma, cudaFuncAttributeMaxDynamicSharedMemorySize, PAIR_SMEM);
    cudaFuncSetAttribute(proj_kernel, cudaFuncAttributeMaxDynamicSharedMemorySize, PROJ_SMEM);
    cudaFuncSetAttribute(gemm_wmma<false,4>, cudaFuncAttributeMaxDynamicSharedMemorySize, GEMM_SMEM);
    cudaFuncSetAttribute(gemm_wmma<true,3>,  cudaFuncAttributeMaxDynamicSharedMemorySize, GEMM_SMEM);

    // 0: proj (8 rows/CTA)
    proj_kernel<<<NROWS/PROJ_ROWS, 256, PROJ_SMEM>>>(Hj, Hi, pjw, piw, sw1);
    // 1: W' precompute
    wsplit_pair<<<(96*88 + 255)/256, 256>>>(sw1);
    // 2: Hi -> bf16 hi/lo
    conv_split<<<(NROWS*Hh/4 + 255)/256, 256>>>(Hi, (__nv_bfloat16*)phih,
                                                (__nv_bfloat16*)phil, NROWS*Hh/4);
    // 3: pair
    pair_wmma<<<NROWS, 256, PAIR_SMEM>>>(sb1, sw2, sb2, mask);
    // 4: ctx partials = probs @ Hi  [NN, batched, split-K=4]
    {
        dim3 g(Hh/128, Ss/128, Bb*4);
        gemm_wmma<false,4><<<g, 256, GEMM_SMEM>>>(
            (const __nv_bfloat16*)ppbh, (const __nv_bfloat16*)ppbl,
            (const __nv_bfloat16*)phih, (const __nv_bfloat16*)phil,
            (float*)ppc, Hh, Ss, Ss, Hh,
            (long)Ss*Ss, (long)Ss*Hh, (long)Ss*Hh, 4L*Ss*Hh);
    }
    // 5: fused ctx reduce + msg_in build
    {
        long total = (long)NROWS*Hh;
        ctx_msgin_fused<<<(int)((total/4 + 255)/256), 256>>>(
            (const float*)ppc, Hj);
    }
    // 6: vw1 -> bf16 hi/lo
    conv_split<<<(OH*H3/4 + 255)/256, 256>>>(vw1, (__nv_bfloat16*)pw1h,
                                             (__nv_bfloat16*)pw1l, OH*H3/4);
    // 7: gemm1 partials  [NT, split-K=3]
    {
        dim3 g(OH/128, NROWS/128, 3);
        gemm_wmma<true,3><<<g, 256, GEMM_SMEM>>>(
            (const __nv_bfloat16*)pm1h, (const __nv_bfloat16*)pm1l,
            (const __nv_bfloat16*)pw1h, (const __nv_bfloat16*)pw1l,
            (float*)pp1, OH, H3, H3, H3,
            0, 0, 0, (long)NROWS*OH);
    }
    // 8: hid reduce (bias+relu -> bf16 split)
    {
        long total = (long)NROWS*OH;
        reduce_ns<3,1><<<(int)((total/4 + 255)/256), 256>>>(
            (const float*)pp1, (long)NROWS*OH, nullptr,
            (__nv_bfloat16*)phdh, (__nv_bfloat16*)phdl, vb1, nullptr, OH, total);
    }
    // 9: vw2 -> bf16 hi/lo
    conv_split<<<(Hh*OH/4 + 255)/256, 256>>>(vw2, (__nv_bfloat16*)pw2h,
                                             (__nv_bfloat16*)pw2l, Hh*OH/4);
    // 10: gemm2 partials  [NT, split-K=3]
    {
        dim3 g(Hh/128, NROWS/128, 3);
        gemm_wmma<true,3><<<g, 256, GEMM_SMEM>>>(
            (const __nv_bfloat16*)phdh, (const __nv_bfloat16*)phdl,
            (const __nv_bfloat16*)pw2h, (const __nv_bfloat16*)pw2l,
            (float*)pp2, Hh, OH, OH, OH,
            0, 0, 0, (long)NROWS*Hh);
    }
    // 11: out reduce (bias, alpha)
    {
        long total = (long)NROWS*Hh;
        reduce_ns<3,2><<<(int)((total/4 + 255)/256), 256>>>(
            (const float*)pp2, (long)NROWS*Hh, out,
            nullptr, nullptr, vb2, alpha, Hh, total);
    }
    (void)in_sizes; (void)n_in; (void)out_size;
}

// round 16
// speedup vs baseline: 2.4625x; 1.2133x over previous
#include <cuda_runtime.h>
#include <cuda_bf16.h>
#include <cuda_fp16.h>
#include <mma.h>
#include <math.h>
#include <cstdint>

using namespace nvcuda;

#define Bb 4
#define Ss 512
#define Hh 768
#define Dd 24
#define Mm 96
#define OH 768
#define H3 2304
#define NROWS (Bb*Ss)   // 2048

typedef unsigned long long ull;

// ---- scratch ----
__device__ __align__(16) float g_Zj[NROWS*Dd];
__device__ __align__(16) float g_Zi[NROWS*Dd];
__device__ __align__(16) float g_Aj[NROWS*Mm];
__device__ __align__(16) __nv_bfloat16 g_Wph[96*88];
// fp16 operands for tensor-core GEMMs (A single, B hi/lo)
__device__ __align__(16) __half g_pb[(long)Bb*Ss*Ss];
__device__ __align__(16) __half g_hih[(long)NROWS*Hh];
__device__ __align__(16) __half g_hil[(long)NROWS*Hh];
__device__ __align__(16) __half g_m1[(long)NROWS*H3];
__device__ __align__(16) __half g_w1h[(long)OH*H3];
__device__ __align__(16) __half g_w1l[(long)OH*H3];
__device__ __align__(16) __half g_hid[(long)NROWS*OH];
__device__ __align__(16) __half g_w2h[(long)Hh*OH];
__device__ __align__(16) __half g_w2l[(long)Hh*OH];
__device__ __align__(16) float g_partc[4L*Bb*Ss*Hh];
__device__ __align__(16) float g_part1[3L*NROWS*OH];
__device__ __align__(16) float g_part2[3L*NROWS*Hh];

// bf16 split helpers (pair kernel)
__device__ __forceinline__ void bsplit(float v, __nv_bfloat16& h, __nv_bfloat16& l){
    h = __float2bfloat16(v);
    l = __float2bfloat16(v - __bfloat162float(h));
}
__device__ __forceinline__ unsigned packh(float a, float b){
    __nv_bfloat162 p;
    p.x = __float2bfloat16(a);
    p.y = __float2bfloat16(b);
    return *(unsigned*)&p;
}
// fp16 split
__device__ __forceinline__ void hsplit(float v, __half& h, __half& l){
    h = __float2half(v);
    l = __float2half(v - __half2float(h));
}

// ---- PTX helpers (base ISA, sm_80+) ----
__device__ __forceinline__ unsigned smem_cast(const void* p){
    return (unsigned)__cvta_generic_to_shared(p);
}
__device__ __forceinline__ void ldsm_x4(unsigned addr, unsigned& r0, unsigned& r1,
                                        unsigned& r2, unsigned& r3){
    asm volatile("ldmatrix.sync.aligned.m8n8.x4.shared.b16 {%0,%1,%2,%3}, [%4];"
        : "=r"(r0), "=r"(r1), "=r"(r2), "=r"(r3) : "r"(addr));
}
__device__ __forceinline__ void mma16816(float* d, const unsigned* a,
                                         unsigned b0, unsigned b1){
    asm volatile(
        "mma.sync.aligned.m16n8k16.row.col.f32.bf16.bf16.f32 "
        "{%0,%1,%2,%3}, {%4,%5,%6,%7}, {%8,%9}, {%0,%1,%2,%3};"
        : "+f"(d[0]), "+f"(d[1]), "+f"(d[2]), "+f"(d[3])
        : "r"(a[0]), "r"(a[1]), "r"(a[2]), "r"(a[3]), "r"(b0), "r"(b1));
}
__device__ __forceinline__ void cpasync16(unsigned dst, const void* src){
    asm volatile("cp.async.cg.shared.global [%0], [%1], 16;"
        :: "r"(dst), "l"(src));
}
#define CP_COMMIT() asm volatile("cp.async.commit_group;" ::: "memory")
#define CP_WAIT1()  asm volatile("cp.async.wait_group 1;" ::: "memory")
#define CP_WAIT0()  asm volatile("cp.async.wait_group 0;" ::: "memory")

// ============================================================
// K0: precompute W' = [Wc | Wd | Wb | 0] (96 x 88) bf16
// ============================================================
__global__ __launch_bounds__(256) void wsplit_pair(const float* __restrict__ sw1)
{
    int i = blockIdx.x*256 + threadIdx.x;
    if (i >= 96*88) return;
    int m = i / 88, k = i % 88;
    float wv = 0.f;
    if (k < 24)      wv = sw1[m*96 + 48 + k];
    else if (k < 48) wv = sw1[m*96 + 72 + (k-24)];
    else if (k < 72) wv = sw1[m*96 + 24 + (k-48)];
    g_Wph[i] = __float2bfloat16(wv);
}

// ============================================================
// K1: proj v2 — 8 rows per CTA
// ============================================================
#define PROJ_ROWS 8
#define PROJ_SMEM (PROJ_ROWS*Hh*2*4 + PROJ_ROWS*Dd*4 + 128)
__global__ __launch_bounds__(256) void proj_kernel(
    const float* __restrict__ Hj, const float* __restrict__ Hi,
    const float* __restrict__ pjw, const float* __restrict__ piw,
    const float* __restrict__ sw1)
{
    extern __shared__ float psm[];
    float* shj = psm;
    float* shi = psm + PROJ_ROWS*Hh;
    float* szj = psm + 2*PROJ_ROWS*Hh;
    long r0 = (long)blockIdx.x * PROJ_ROWS;
    int tid = threadIdx.x;

    const float4* Hj4 = (const float4*)(Hj + r0*Hh);
    const float4* Hi4 = (const float4*)(Hi + r0*Hh);
    float4* shj4 = (float4*)shj;
    float4* shi4 = (float4*)shi;
    #pragma unroll 4
    for (int i = tid; i < PROJ_ROWS*Hh/4; i += 256){
        shj4[i] = Hj4[i];
        shi4[i] = Hi4[i];
    }
    __syncthreads();

    int o = tid >> 3, g = tid & 7;
    if (o < Dd){
        const float4* wj4 = (const float4*)(pjw + o*Hh);
        const float4* wi4 = (const float4*)(piw + o*Hh);
        #pragma unroll 1
        for (int rr = 0; rr < PROJ_ROWS; rr++){
            const float4* hj4 = (const float4*)(shj + rr*Hh);
            const float4* hs4 = (const float4*)(shi + rr*Hh);
            float pj = 0.f, pi = 0.f;
            #pragma unroll 6
            for (int it = g; it < Hh/4; it += 8){
                float4 wj = __ldg(&wj4[it]);
                float4 wi = __ldg(&wi4[it]);
                float4 hj = hj4[it];
                float4 hs = hs4[it];
                pj += wj.x*hj.x + wj.y*hj.y + wj.z*hj.z + wj.w*hj.w;
                pi += wi.x*hs.x + wi.y*hs.y + wi.z*hs.z + wi.w*hs.w;
            }
            #pragma unroll
            for (int d = 4; d > 0; d >>= 1){
                pj += __shfl_down_sync(0xffffffffu, pj, d, 8);
                pi += __shfl_down_sync(0xffffffffu, pi, d, 8);
            }
            if (g == 0){
                szj[rr*Dd + o] = pj;
                g_Zj[(r0+rr)*Dd + o] = pj;
                g_Zi[(r0+rr)*Dd + o] = pi;
            }
        }
    }
    __syncthreads();
    if (tid < Mm){
        #pragma unroll 1
        for (int rr = 0; rr < PROJ_ROWS; rr++){
            float a = 0.f;
            #pragma unroll
            for (int d = 0; d < Dd; d++)
                a += sw1[tid*96 + d] * szj[rr*Dd + d];
            g_Aj[(r0+rr)*Mm + tid] = a;
        }
    }
}

// ============================================================
// K2: pair logits v8 — square warp tiles, PTX mma, reg reduce.
//  Output probs as fp16 single.
// ============================================================
#define POFF_WH   0
#define POFF_F    16896
#define POFF_SLOG 39424
#define POFF_SZJ  43520
#define POFF_SCW  43648
#define POFF_SRED 44416
#define PAIR_SMEM 44544

#define FCOLV(c) ((c) < 24 ? szj[(c)]*za[(c)] : \
                  (c) < 48 ? fabsf(szj[(c)-24]-za[(c)-24]) : \
                  (c) < 72 ? za[(c)-48] : 0.f)

__global__ __launch_bounds__(256, 3) void pair_wmma(
    const float* __restrict__ sb1,
    const float* __restrict__ sw2v, const float* __restrict__ sb2,
    const float* __restrict__ mask)
{
    extern __shared__ char ps[];
    __nv_bfloat16* Wh = (__nv_bfloat16*)(ps + POFF_WH);
    __nv_bfloat16* Fh = (__nv_bfloat16*)(ps + POFF_F);
    float*  slog = (float*)(ps + POFF_SLOG);
    float*  szj  = (float*)(ps + POFF_SZJ);
    float2* scw  = (float2*)(ps + POFF_SCW);
    float*  sred = (float*)(ps + POFF_SRED);

    int r = blockIdx.x, b = r >> 9;
    int tid = threadIdx.x, wid = tid >> 5, lane = tid & 31;

    for (int i = tid; i < 1056; i += 256)
        ((uint4*)Wh)[i] = ((const uint4*)g_Wph)[i];
    if (tid < Dd) szj[tid] = g_Zj[r*Dd + tid];
    if (tid < Mm)
        scw[tid] = make_float2(g_Aj[r*Mm + tid] + sb1[tid], sw2v[tid]);
    if (tid < 128){
        uint4 z = make_uint4(0u,0u,0u,0u);
        uint4* zp = (uint4*)&Fh[tid*88 + 72];
        zp[0] = z; zp[1] = z;
    }
    __syncthreads();

    unsigned sF = smem_cast(Fh);
    unsigned sW = smem_cast(Wh);
    int bhalf = tid >> 7;
    int brow  = tid & 127;
    int l16   = lane & 15;
    int lhi8  = (lane >> 4) * 8;
    int c0    = (lane & 3) * 2;
    int R0 = (wid & 3) * 32;
    int CB = (wid >> 2) * 48;

    #pragma unroll 1
    for (int chunk = 0; chunk < 4; chunk++){
        {
            int t = chunk*128 + brow;
            const float4* zi4 = (const float4*)&g_Zi[(long)(b*Ss + t)*Dd];
            float za[24];
            #pragma unroll
            for (int q = 0; q < 6; q++){
                float4 v4 = __ldg(&zi4[q]);
                za[q*4+0]=v4.x; za[q*4+1]=v4.y; za[q*4+2]=v4.z; za[q*4+3]=v4.w;
            }
            if (bhalf == 0){
                uint4* dh = (uint4*)&Fh[brow*88];
                #pragma unroll
                for (int q = 0; q < 5; q++){
                    unsigned h4[4];
                    #pragma unroll
                    for (int e = 0; e < 4; e++){
                        int c = q*8 + e*2;
                        h4[e] = packh(FCOLV(c), FCOLV(c+1));
                    }
                    dh[q] = make_uint4(h4[0],h4[1],h4[2],h4[3]);
                }
            } else {
                uint4* dh = (uint4*)&Fh[brow*88 + 40];
                #pragma unroll
                for (int q = 0; q < 4; q++){
                    unsigned h4[4];
                    #pragma unroll
                    for (int e = 0; e < 4; e++){
                        int c = 40 + q*8 + e*2;
                        h4[e] = packh(FCOLV(c), FCOLV(c+1));
                    }
                    dh[q] = make_uint4(h4[0],h4[1],h4[2],h4[3]);
                }
            }
        }
        __syncthreads();

        float acc[12][4];
        #pragma unroll
        for (int f = 0; f < 12; f++)
            #pragma unroll
            for (int e = 0; e < 4; e++) acc[f][e] = 0.f;

        #pragma unroll
        for (int k = 0; k < 5; k++){
            unsigned a0[4], a1[4];
            unsigned aaddr0 = sF + (unsigned)(((R0      + l16)*88 + k*16 + lhi8) * 2);
            unsigned aaddr1 = sF + (unsigned)(((R0 + 16 + l16)*88 + k*16 + lhi8) * 2);
            ldsm_x4(aaddr0, a0[0], a0[1], a0[2], a0[3]);
            ldsm_x4(aaddr1, a1[0], a1[1], a1[2], a1[3]);
            #pragma unroll
            for (int g = 0; g < 3; g++){
                unsigned bq[4];
                unsigned baddr = sW + (unsigned)(((CB + g*16 + l16)*88 + k*16 + lhi8) * 2);
                ldsm_x4(baddr, bq[0], bq[1], bq[2], bq[3]);
                mma16816(acc[g*2],         a0, bq[0], bq[2]);
                mma16816(acc[g*2 + 1],     a0, bq[1], bq[3]);
                mma16816(acc[6 + g*2],     a1, bq[0], bq[2]);
                mma16816(acc[6 + g*2 + 1], a1, bq[1], bq[3]);
            }
        }

        float s00 = 0.f, s01 = 0.f, s10 = 0.f, s11 = 0.f;
        #pragma unroll
        for (int g = 0; g < 3; g++)
            #pragma unroll
            for (int h = 0; h < 2; h++){
                float4 c = *(const float4*)&scw[CB + g*16 + h*8 + c0];
                int f = g*2 + h;
                s00 += c.y * fmaxf(acc[f][0] + c.x, 0.f)
                     + c.w * fmaxf(acc[f][1] + c.z, 0.f);
                s01 += c.y * fmaxf(acc[f][2] + c.x, 0.f)
                     + c.w * fmaxf(acc[f][3] + c.z, 0.f);
                s10 += c.y * fmaxf(acc[6+f][0] + c.x, 0.f)
                     + c.w * fmaxf(acc[6+f][1] + c.z, 0.f);
                s11 += c.y * fmaxf(acc[6+f][2] + c.x, 0.f)
                     + c.w * fmaxf(acc[6+f][3] + c.z, 0.f);
            }
        s00 += __shfl_xor_sync(0xffffffffu, s00, 1);
        s00 += __shfl_xor_sync(0xffffffffu, s00, 2);
        s01 += __shfl_xor_sync(0xffffffffu, s01, 1);
        s01 += __shfl_xor_sync(0xffffffffu, s01, 2);
        s10 += __shfl_xor_sync(0xffffffffu, s10, 1);
        s10 += __shfl_xor_sync(0xffffffffu, s10, 2);
        s11 += __shfl_xor_sync(0xffffffffu, s11, 1);
        s11 += __shfl_xor_sync(0xffffffffu, s11, 2);
        if ((lane & 3) == 0){
            int row = lane >> 2;
            int base = (wid >> 2)*512 + chunk*128 + R0;
            slog[base + row]          = s00;
            slog[base + 8 + row]      = s01;
            slog[base + 16 + row]     = s10;
            slog[base + 24 + row]     = s11;
        }
        __syncthreads();
    }

    int t0 = tid, t1 = tid + 256;
    float lt0 = slog[t0] + slog[512 + t0] + sb2[0]
              + (1.f - mask[b*Ss + t0]) * (-3.402823466e38f);
    float lt1 = slog[t1] + slog[512 + t1] + sb2[0]
              + (1.f - mask[b*Ss + t1]) * (-3.402823466e38f);

    float mx = fmaxf(lt0, lt1);
    #pragma unroll
    for (int d = 16; d > 0; d >>= 1)
        mx = fmaxf(mx, __shfl_xor_sync(0xffffffffu, mx, d));
    if (lane == 0) sred[wid] = mx;
    __syncthreads();
    float bmax = sred[0];
    #pragma unroll
    for (int i = 1; i < 8; i++) bmax = fmaxf(bmax, sred[i]);

    float e0 = expf(lt0 - bmax);
    float e1 = expf(lt1 - bmax);
    float sm = e0 + e1;
    #pragma unroll
    for (int d = 16; d > 0; d >>= 1)
        sm += __shfl_xor_sync(0xffffffffu, sm, d);
    __syncthreads();
    if (lane == 0) sred[wid] = sm;
    __syncthreads();
    float tot = 0.f;
    #pragma unroll
    for (int i = 0; i < 8; i++) tot += sred[i];
    float inv = 1.f / tot;

    g_pb[(long)r*Ss + t0] = __float2half(e0 * inv);
    g_pb[(long)r*Ss + t1] = __float2half(e1 * inv);
}

// ============================================================
// K3: fp32 -> fp16 hi/lo split (vectorized)
// ============================================================
__global__ __launch_bounds__(256) void conv_split_h(
    const float* __restrict__ x, __half* __restrict__ hi,
    __half* __restrict__ lo, int n4)
{
    int i = blockIdx.x*256 + threadIdx.x;
    if (i >= n4) return;
    float4 v = ((const float4*)x)[i];
    __half h0,h1,h2,h3,l0,l1,l2,l3;
    hsplit(v.x,h0,l0); hsplit(v.y,h1,l1); hsplit(v.z,h2,l2); hsplit(v.w,h3,l3);
    __half2 p0 = __halves2half2(h0,h1);
    __half2 p1 = __halves2half2(h2,h3);
    ((__half2*)hi)[2*i]   = p0;
    ((__half2*)hi)[2*i+1] = p1;
    p0 = __halves2half2(l0,l1);
    p1 = __halves2half2(l2,l3);
    ((__half2*)lo)[2*i]   = p0;
    ((__half2*)lo)[2*i+1] = p1;
}

// ============================================================
// K4: fused ctx split-K reduce + msg_in build (fp16 single)
// ============================================================
__device__ __forceinline__ void store4h(__half* p, float a, float b, float c, float d){
    __half2 p0 = __floats2half2_rn(a, b);
    __half2 p1 = __floats2half2_rn(c, d);
    ((__half2*)p)[0] = p0;
    ((__half2*)p)[1] = p1;
}
__global__ __launch_bounds__(256) void ctx_msgin_fused(
    const float* __restrict__ p, const float* __restrict__ Hj)
{
    long i4 = ((long)blockIdx.x * 256 + threadIdx.x) * 4;
    if (i4 >= (long)NROWS*Hh) return;
    long stride = 4L*Ss*Hh;
    float4 s = *(const float4*)&p[i4];
    #pragma unroll
    for (int n = 1; n < 4; n++){
        float4 v = *(const float4*)&p[n*stride + i4];
        s.x += v.x; s.y += v.y; s.z += v.z; s.w += v.w;
    }
    int r = (int)(i4 / Hh);
    int c = (int)(i4 % Hh);
    float4 hv = *(const float4*)&Hj[i4];
    long base = (long)r*H3 + c;
    store4h(&g_m1[base],      s.x, s.y, s.z, s.w);
    store4h(&g_m1[base+Hh],   hv.x, hv.y, hv.z, hv.w);
    store4h(&g_m1[base+2*Hh], s.x*hv.x, s.y*hv.y, s.z*hv.z, s.w*hv.w);
}

// ============================================================
// K5: WMMA fp16 GEMM, split-K, cp.async double-buffered,
//  A single-plane fp16, B hi/lo fp16, 2-pass.
//  smem: A[2] 2x10240, B[2][hl] 4x10240 = 61440 B
// ============================================================
#define GEMM_SMEM 61440
#define HLSZ 10240

template<bool TRANSB, int KSPLIT>
__global__ __launch_bounds__(256) void gemm_wmma(
    const __half* __restrict__ Aop,
    const __half* __restrict__ Bh, const __half* __restrict__ Bl,
    float* __restrict__ Cpart, int N, int K, int ldA, int ldB,
    long strideA, long strideB, long strideC, long partStride)
{
    extern __shared__ char gsm[];
    unsigned sbase = smem_cast(gsm);

    int tid = threadIdx.x;
    int wid = tid >> 5;
    int wr = wid & 3, wc = wid >> 2;
    long row0 = (long)blockIdx.y * 128;
    long col0 = (long)blockIdx.x * 128;

    int zb = blockIdx.z / KSPLIT, zk = blockIdx.z % KSPLIT;
    int kcnt = K / KSPLIT, k0 = zk * kcnt;

    const __half* AP  = Aop + (long)zb * strideA;
    const __half* BPh = Bh  + (long)zb * strideB;
    const __half* BPl = Bl  + (long)zb * strideB;
    float* Cb = Cpart + (long)zk * partStride + (long)zb * strideC;

    int a_r = tid >> 2, a_seg = tid & 3;
    int bn_r = tid >> 4, bn_seg = tid & 15;

    wmma::fragment<wmma::accumulator,16,16,16,float> acc[2][4];
    #pragma unroll
    for (int i = 0; i < 2; i++)
        #pragma unroll
        for (int j = 0; j < 4; j++) wmma::fill_fragment(acc[i][j], 0.f);

    int nch = kcnt >> 5;

    #define STAGE_CHUNK(bi, kc) do {                                         \
        unsigned abase = sbase + (bi)*HLSZ;                                  \
        _Pragma("unroll")                                                    \
        for (int t = 0; t < 2; t++){                                         \
            int rr = a_r + t*64;                                             \
            long off = (row0 + rr)*(long)ldA + (kc) + a_seg*8;               \
            cpasync16(abase + (unsigned)((rr*40 + a_seg*8)*2), AP + off);    \
        }                                                                    \
        unsigned bbase = sbase + 2*HLSZ + (bi)*2*HLSZ;                       \
        if (TRANSB){                                                         \
            _Pragma("unroll")                                                \
            for (int t = 0; t < 2; t++){                                     \
                int rr = a_r + t*64;                                         \
                long off = (col0 + rr)*(long)ldB + (kc) + a_seg*8;           \
                unsigned d = bbase + (unsigned)((rr*40 + a_seg*8)*2);        \
                cpasync16(d,        BPh + off);                              \
                cpasync16(d + HLSZ, BPl + off);                              \
            }                                                                \
        } else {                                                             \
            _Pragma("unroll")                                                \
            for (int t = 0; t < 2; t++){                                     \
                int rr = bn_r + t*16;                                        \
                long off = (long)((kc) + rr)*ldB + col0 + bn_seg*8;          \
                unsigned d = bbase + (unsigned)((rr*136 + bn_seg*8)*2);      \
                cpasync16(d,        BPh + off);                              \
                cpasync16(d + HLSZ, BPl + off);                              \
            }                                                                \
        }                                                                    \
        CP_COMMIT();                                                         \
    } while(0)

    STAGE_CHUNK(0, k0);

    #pragma unroll 1
    for (int s = 0; s < nch; s++){
        int cur = s & 1;
        if (s + 1 < nch){
            STAGE_CHUNK(cur ^ 1, k0 + (s+1)*32);
            CP_WAIT1();
        } else {
            CP_WAIT0();
        }
        __syncthreads();

        const __half* Asb = (const __half*)(gsm + cur*HLSZ);
        const __half* Bsb = (const __half*)(gsm + 2*HLSZ + cur*2*HLSZ);
        const __half* Blb = Bsb + 5120;

        #pragma unroll
        for (int ks = 0; ks < 2; ks++){
            wmma::fragment<wmma::matrix_a,16,16,16,__half,wmma::row_major> af[2];
            #pragma unroll
            for (int i = 0; i < 2; i++)
                wmma::load_matrix_sync(af[i], Asb + (wr*32 + i*16)*40 + ks*16, 40);
            if (TRANSB){
                #pragma unroll
                for (int j = 0; j < 4; j++){
                    wmma::fragment<wmma::matrix_b,16,16,16,__half,wmma::col_major> bfh, bfl;
                    int nb = wc*64 + j*16;
                    wmma::load_matrix_sync(bfh, Bsb + nb*40 + ks*16, 40);
                    wmma::load_matrix_sync(bfl, Blb + nb*40 + ks*16, 40);
                    #pragma unroll
                    for (int i = 0; i < 2; i++){
                        wmma::mma_sync(acc[i][j], af[i], bfh, acc[i][j]);
                        wmma::mma_sync(acc[i][j], af[i], bfl, acc[i][j]);
                    }
                }
            } else {
                #pragma unroll
                for (int j = 0; j < 4; j++){
                    wmma::fragment<wmma::matrix_b,16,16,16,__half,wmma::row_major> bfh, bfl;
                    int nb = wc*64 + j*16;
                    wmma::load_matrix_sync(bfh, Bsb + (ks*16)*136 + nb, 136);
                    wmma::load_matrix_sync(bfl, Blb + (ks*16)*136 + nb, 136);
                    #pragma unroll
                    for (int i = 0; i < 2; i++){
                        wmma::mma_sync(acc[i][j], af[i], bfh, acc[i][j]);
                        wmma::mma_sync(acc[i][j], af[i], bfl, acc[i][j]);
                    }
                }
            }
        }
        __syncthreads();
    }
    #undef STAGE_CHUNK

    #pragma unroll
    for (int i = 0; i < 2; i++)
        #pragma unroll
        for (int j = 0; j < 4; j++){
            float* cp = Cb + (row0 + wr*32 + i*16)*(long)N + col0 + wc*64 + j*16;
            wmma::store_matrix_sync(cp, acc[i][j], N, wmma::mem_row_major);
        }
}

// ============================================================
// K6: split-K reduce + epilogues
//  MODE 1: relu(sum+bias) -> fp16 single (hid)
//  MODE 2: (sum+bias)*alpha -> fp32 (out)
// ============================================================
template<int NS, int MODE>
__global__ __launch_bounds__(256) void reduce_ns(
    const float* __restrict__ p, long partStride,
    float* __restrict__ outf, __half* __restrict__ oh,
    const float* __restrict__ bias, const float* __restrict__ alpha_p,
    int N, long total)
{
    long i4 = ((long)blockIdx.x * 256 + threadIdx.x) * 4;
    if (i4 >= total) return;
    float4 s = *(const float4*)&p[i4];
    #pragma unroll
    for (int n = 1; n < NS; n++){
        float4 v = *(const float4*)&p[n*partStride + i4];
        s.x += v.x; s.y += v.y; s.z += v.z; s.w += v.w;
    }
    int col = (int)(i4 % N);
    float4 bi = *(const float4*)&bias[col];
    s.x += bi.x; s.y += bi.y; s.z += bi.z; s.w += bi.w;
    if (MODE == 1){
        s.x = fmaxf(s.x, 0.f); s.y = fmaxf(s.y, 0.f);
        s.z = fmaxf(s.z, 0.f); s.w = fmaxf(s.w, 0.f);
        store4h(&oh[i4], s.x, s.y, s.z, s.w);
    } else {
        float a = __ldg(alpha_p);
        s.x *= a; s.y *= a; s.z *= a; s.w *= a;
        *(float4*)&outf[i4] = s;
    }
}

// ============================================================
extern "C" void kernel_launch(void* const* d_in, const int* in_sizes, int n_in,
                              void* d_out, int out_size)
{
    const float* Hj   = (const float*)d_in[0];
    const float* Hi   = (const float*)d_in[1];
    const float* mask = (const float*)d_in[2];
    const float* pjw  = (const float*)d_in[3];
    const float* piw  = (const float*)d_in[4];
    const float* sw1  = (const float*)d_in[5];
    const float* sb1  = (const float*)d_in[6];
    const float* sw2  = (const float*)d_in[7];
    const float* sb2  = (const float*)d_in[8];
    const float* vw1  = (const float*)d_in[9];
    const float* vb1  = (const float*)d_in[10];
    const float* vw2  = (const float*)d_in[11];
    const float* vb2  = (const float*)d_in[12];
    const float* alpha= (const float*)d_in[13];
    float* out = (float*)d_out;

    void *ppb, *phih, *phil, *pm1, *pw1h, *pw1l, *phd, *pw2h, *pw2l;
    void *ppc, *pp1, *pp2;
    cudaGetSymbolAddress(&ppb,  g_pb);
    cudaGetSymbolAddress(&phih, g_hih);  cudaGetSymbolAddress(&phil, g_hil);
    cudaGetSymbolAddress(&pm1,  g_m1);
    cudaGetSymbolAddress(&pw1h, g_w1h);  cudaGetSymbolAddress(&pw1l, g_w1l);
    cudaGetSymbolAddress(&phd,  g_hid);
    cudaGetSymbolAddress(&pw2h, g_w2h);  cudaGetSymbolAddress(&pw2l, g_w2l);
    cudaGetSymbolAddress(&ppc, g_partc);
    cudaGetSymbolAddress(&pp1, g_part1);
    cudaGetSymbolAddress(&pp2, g_part2);

    cudaFuncSetAttribute(pair_wmma, cudaFuncAttributeMaxDynamicSharedMemorySize, PAIR_SMEM);
    cudaFuncSetAttribute(proj_kernel, cudaFuncAttributeMaxDynamicSharedMemorySize, PROJ_SMEM);
    cudaFuncSetAttribute(gemm_wmma<false,4>, cudaFuncAttributeMaxDynamicSharedMemorySize, GEMM_SMEM);
    cudaFuncSetAttribute(gemm_wmma<true,3>,  cudaFuncAttributeMaxDynamicSharedMemorySize, GEMM_SMEM);

    // 0: proj (8 rows/CTA)
    proj_kernel<<<NROWS/PROJ_ROWS, 256, PROJ_SMEM>>>(Hj, Hi, pjw, piw, sw1);
    // 1: W' precompute
    wsplit_pair<<<(96*88 + 255)/256, 256>>>(sw1);
    // 2: Hi -> fp16 hi/lo
    conv_split_h<<<(NROWS*Hh/4 + 255)/256, 256>>>(Hi, (__half*)phih,
                                                  (__half*)phil, NROWS*Hh/4);
    // 3: pair
    pair_wmma<<<NROWS, 256, PAIR_SMEM>>>(sb1, sw2, sb2, mask);
    // 4: ctx partials = probs @ Hi  [NN, batched, split-K=4]
    {
        dim3 g(Hh/128, Ss/128, Bb*4);
        gemm_wmma<false,4><<<g, 256, GEMM_SMEM>>>(
            (const __half*)ppb,
            (const __half*)phih, (const __half*)phil,
            (float*)ppc, Hh, Ss, Ss, Hh,
            (long)Ss*Ss, (long)Ss*Hh, (long)Ss*Hh, 4L*Ss*Hh);
    }
    // 5: fused ctx reduce + msg_in build (fp16 single)
    {
        long total = (long)NROWS*Hh;
        ctx_msgin_fused<<<(int)((total/4 + 255)/256), 256>>>(
            (const float*)ppc, Hj);
    }
    // 6: vw1 -> fp16 hi/lo
    conv_split_h<<<(OH*H3/4 + 255)/256, 256>>>(vw1, (__half*)pw1h,
                                               (__half*)pw1l, OH*H3/4);
    // 7: gemm1 partials  [NT, split-K=3]
    {
        dim3 g(OH/128, NROWS/128, 3);
        gemm_wmma<true,3><<<g, 256, GEMM_SMEM>>>(
            (const __half*)pm1,
            (const __half*)pw1h, (const __half*)pw1l,
            (float*)pp1, OH, H3, H3, H3,
            0, 0, 0, (long)NROWS*OH);
    }
    // 8: hid reduce (bias+relu -> fp16 single)
    {
        long total = (long)NROWS*OH;
        reduce_ns<3,1><<<(int)((total/4 + 255)/256), 256>>>(
            (const float*)pp1, (long)NROWS*OH, nullptr,
            (__half*)phd, vb1, nullptr, OH, total);
    }
    // 9: vw2 -> fp16 hi/lo
    conv_split_h<<<(Hh*OH/4 + 255)/256, 256>>>(vw2, (__half*)pw2h,
                                               (__half*)pw2l, Hh*OH/4);
    // 10: gemm2 partials  [NT, split-K=3]
    {
        dim3 g(Hh/128, NROWS/128, 3);
        gemm_wmma<true,3><<<g, 256, GEMM_SMEM>>>(
            (const __half*)phd,
            (const __half*)pw2h, (const __half*)pw2l,
            (float*)pp2, Hh, OH, OH, OH,
            0, 0, 0, (long)NROWS*Hh);
    }
    // 11: out reduce (bias, alpha)
    {
        long total = (long)NROWS*Hh;
        reduce_ns<3,2><<<(int)((total/4 + 255)/256), 256>>>(
            (const float*)pp2, (long)NROWS*Hh, out,
            nullptr, vb2, alpha, Hh, total);
    }
    (void)in_sizes; (void)n_in; (void)out_size;
}

// round 17
// speedup vs baseline: 2.7590x; 1.1204x over previous
#include <cuda_runtime.h>
#include <cuda_bf16.h>
#include <cuda_fp16.h>
#include <mma.h>
#include <math.h>
#include <cstdint>

using namespace nvcuda;

#define Bb 4
#define Ss 512
#define Hh 768
#define Dd 24
#define Mm 96
#define OH 768
#define H3 2304
#define NROWS (Bb*Ss)   // 2048

typedef unsigned long long ull;

// ---- scratch ----
__device__ __align__(16) float g_Zj[NROWS*Dd];
__device__ __align__(16) float g_Zi[NROWS*Dd];
__device__ __align__(16) float g_Aj[NROWS*Mm];
__device__ __align__(16) __nv_bfloat16 g_Wph[96*88];
// fp16 operands
__device__ __align__(16) __half g_pb[(long)Bb*Ss*Ss];      // probs (A of ctx)
__device__ __align__(16) __half g_hi[(long)NROWS*Hh];      // Hi single (B of ctx)
__device__ __align__(16) __half g_m1[(long)NROWS*H3];      // msg_in single
__device__ __align__(16) __half g_w1[(long)OH*H3];         // w1 single
__device__ __align__(16) __half g_hid[(long)NROWS*OH];     // hid single
__device__ __align__(16) __half g_w2h[(long)Hh*OH];        // w2 hi/lo (2-pass)
__device__ __align__(16) __half g_w2l[(long)Hh*OH];
__device__ __align__(16) float g_partc[4L*Bb*Ss*Hh];
__device__ __align__(16) float g_part1[3L*NROWS*OH];
__device__ __align__(16) float g_part2[3L*NROWS*Hh];

// bf16 helpers (pair kernel)
__device__ __forceinline__ unsigned packh(float a, float b){
    __nv_bfloat162 p;
    p.x = __float2bfloat16(a);
    p.y = __float2bfloat16(b);
    return *(unsigned*)&p;
}
// fp16 split
__device__ __forceinline__ void hsplit(float v, __half& h, __half& l){
    h = __float2half(v);
    l = __float2half(v - __half2float(h));
}
__device__ __forceinline__ void store4h(__half* p, float a, float b, float c, float d){
    __half2 p0 = __floats2half2_rn(a, b);
    __half2 p1 = __floats2half2_rn(c, d);
    ((__half2*)p)[0] = p0;
    ((__half2*)p)[1] = p1;
}

// ---- PTX helpers (base ISA, sm_80+) ----
__device__ __forceinline__ unsigned smem_cast(const void* p){
    return (unsigned)__cvta_generic_to_shared(p);
}
__device__ __forceinline__ void ldsm_x4(unsigned addr, unsigned& r0, unsigned& r1,
                                        unsigned& r2, unsigned& r3){
    asm volatile("ldmatrix.sync.aligned.m8n8.x4.shared.b16 {%0,%1,%2,%3}, [%4];"
        : "=r"(r0), "=r"(r1), "=r"(r2), "=r"(r3) : "r"(addr));
}
__device__ __forceinline__ void mma16816(float* d, const unsigned* a,
                                         unsigned b0, unsigned b1){
    asm volatile(
        "mma.sync.aligned.m16n8k16.row.col.f32.bf16.bf16.f32 "
        "{%0,%1,%2,%3}, {%4,%5,%6,%7}, {%8,%9}, {%0,%1,%2,%3};"
        : "+f"(d[0]), "+f"(d[1]), "+f"(d[2]), "+f"(d[3])
        : "r"(a[0]), "r"(a[1]), "r"(a[2]), "r"(a[3]), "r"(b0), "r"(b1));
}
__device__ __forceinline__ void cpasync16(unsigned dst, const void* src){
    asm volatile("cp.async.cg.shared.global [%0], [%1], 16;"
        :: "r"(dst), "l"(src));
}
#define CP_COMMIT() asm volatile("cp.async.commit_group;" ::: "memory")
#define CP_WAIT1()  asm volatile("cp.async.wait_group 1;" ::: "memory")
#define CP_WAIT0()  asm volatile("cp.async.wait_group 0;" ::: "memory")

// ============================================================
// K0: precompute W' = [Wc | Wd | Wb | 0] (96 x 88) bf16
// ============================================================
__global__ __launch_bounds__(256) void wsplit_pair(const float* __restrict__ sw1)
{
    int i = blockIdx.x*256 + threadIdx.x;
    if (i >= 96*88) return;
    int m = i / 88, k = i % 88;
    float wv = 0.f;
    if (k < 24)      wv = sw1[m*96 + 48 + k];
    else if (k < 48) wv = sw1[m*96 + 72 + (k-24)];
    else if (k < 72) wv = sw1[m*96 + 24 + (k-48)];
    g_Wph[i] = __float2bfloat16(wv);
}

// ============================================================
// K1: proj v3 — 8 rows per CTA; also emits Hi as fp16 single.
// ============================================================
#define PROJ_ROWS 8
#define PROJ_SMEM (PROJ_ROWS*Hh*2*4 + PROJ_ROWS*Dd*4 + 128)
__global__ __launch_bounds__(256) void proj_kernel(
    const float* __restrict__ Hj, const float* __restrict__ Hi,
    const float* __restrict__ pjw, const float* __restrict__ piw,
    const float* __restrict__ sw1)
{
    extern __shared__ float psm[];
    float* shj = psm;
    float* shi = psm + PROJ_ROWS*Hh;
    float* szj = psm + 2*PROJ_ROWS*Hh;
    long r0 = (long)blockIdx.x * PROJ_ROWS;
    int tid = threadIdx.x;

    const float4* Hj4 = (const float4*)(Hj + r0*Hh);
    const float4* Hi4 = (const float4*)(Hi + r0*Hh);
    float4* shj4 = (float4*)shj;
    float4* shi4 = (float4*)shi;
    #pragma unroll 4
    for (int i = tid; i < PROJ_ROWS*Hh/4; i += 256){
        float4 hj = Hj4[i];
        float4 hs = Hi4[i];
        shj4[i] = hj;
        shi4[i] = hs;
        store4h(&g_hi[r0*Hh + i*4], hs.x, hs.y, hs.z, hs.w);
    }
    __syncthreads();

    int o = tid >> 3, g = tid & 7;
    if (o < Dd){
        const float4* wj4 = (const float4*)(pjw + o*Hh);
        const float4* wi4 = (const float4*)(piw + o*Hh);
        #pragma unroll 1
        for (int rr = 0; rr < PROJ_ROWS; rr++){
            const float4* hj4 = (const float4*)(shj + rr*Hh);
            const float4* hs4 = (const float4*)(shi + rr*Hh);
            float pj = 0.f, pi = 0.f;
            #pragma unroll 6
            for (int it = g; it < Hh/4; it += 8){
                float4 wj = __ldg(&wj4[it]);
                float4 wi = __ldg(&wi4[it]);
                float4 hj = hj4[it];
                float4 hs = hs4[it];
                pj += wj.x*hj.x + wj.y*hj.y + wj.z*hj.z + wj.w*hj.w;
                pi += wi.x*hs.x + wi.y*hs.y + wi.z*hs.z + wi.w*hs.w;
            }
            #pragma unroll
            for (int d = 4; d > 0; d >>= 1){
                pj += __shfl_down_sync(0xffffffffu, pj, d, 8);
                pi += __shfl_down_sync(0xffffffffu, pi, d, 8);
            }
            if (g == 0){
                szj[rr*Dd + o] = pj;
                g_Zj[(r0+rr)*Dd + o] = pj;
                g_Zi[(r0+rr)*Dd + o] = pi;
            }
        }
    }
    __syncthreads();
    if (tid < Mm){
        #pragma unroll 1
        for (int rr = 0; rr < PROJ_ROWS; rr++){
            float a = 0.f;
            #pragma unroll
            for (int d = 0; d < Dd; d++)
                a += sw1[tid*96 + d] * szj[rr*Dd + d];
            g_Aj[(r0+rr)*Mm + tid] = a;
        }
    }
}

// ============================================================
// K2: pair logits v8 — square warp tiles, PTX mma, reg reduce.
// ============================================================
#define POFF_WH   0
#define POFF_F    16896
#define POFF_SLOG 39424
#define POFF_SZJ  43520
#define POFF_SCW  43648
#define POFF_SRED 44416
#define PAIR_SMEM 44544

#define FCOLV(c) ((c) < 24 ? szj[(c)]*za[(c)] : \
                  (c) < 48 ? fabsf(szj[(c)-24]-za[(c)-24]) : \
                  (c) < 72 ? za[(c)-48] : 0.f)

__global__ __launch_bounds__(256, 3) void pair_wmma(
    const float* __restrict__ sb1,
    const float* __restrict__ sw2v, const float* __restrict__ sb2,
    const float* __restrict__ mask)
{
    extern __shared__ char ps[];
    __nv_bfloat16* Wh = (__nv_bfloat16*)(ps + POFF_WH);
    __nv_bfloat16* Fh = (__nv_bfloat16*)(ps + POFF_F);
    float*  slog = (float*)(ps + POFF_SLOG);
    float*  szj  = (float*)(ps + POFF_SZJ);
    float2* scw  = (float2*)(ps + POFF_SCW);
    float*  sred = (float*)(ps + POFF_SRED);

    int r = blockIdx.x, b = r >> 9;
    int tid = threadIdx.x, wid = tid >> 5, lane = tid & 31;

    for (int i = tid; i < 1056; i += 256)
        ((uint4*)Wh)[i] = ((const uint4*)g_Wph)[i];
    if (tid < Dd) szj[tid] = g_Zj[r*Dd + tid];
    if (tid < Mm)
        scw[tid] = make_float2(g_Aj[r*Mm + tid] + sb1[tid], sw2v[tid]);
    if (tid < 128){
        uint4 z = make_uint4(0u,0u,0u,0u);
        uint4* zp = (uint4*)&Fh[tid*88 + 72];
        zp[0] = z; zp[1] = z;
    }
    __syncthreads();

    unsigned sF = smem_cast(Fh);
    unsigned sW = smem_cast(Wh);
    int bhalf = tid >> 7;
    int brow  = tid & 127;
    int l16   = lane & 15;
    int lhi8  = (lane >> 4) * 8;
    int c0    = (lane & 3) * 2;
    int R0 = (wid & 3) * 32;
    int CB = (wid >> 2) * 48;

    #pragma unroll 1
    for (int chunk = 0; chunk < 4; chunk++){
        {
            int t = chunk*128 + brow;
            const float4* zi4 = (const float4*)&g_Zi[(long)(b*Ss + t)*Dd];
            float za[24];
            #pragma unroll
            for (int q = 0; q < 6; q++){
                float4 v4 = __ldg(&zi4[q]);
                za[q*4+0]=v4.x; za[q*4+1]=v4.y; za[q*4+2]=v4.z; za[q*4+3]=v4.w;
            }
            if (bhalf == 0){
                uint4* dh = (uint4*)&Fh[brow*88];
                #pragma unroll
                for (int q = 0; q < 5; q++){
                    unsigned h4[4];
                    #pragma unroll
                    for (int e = 0; e < 4; e++){
                        int c = q*8 + e*2;
                        h4[e] = packh(FCOLV(c), FCOLV(c+1));
                    }
                    dh[q] = make_uint4(h4[0],h4[1],h4[2],h4[3]);
                }
            } else {
                uint4* dh = (uint4*)&Fh[brow*88 + 40];
                #pragma unroll
                for (int q = 0; q < 4; q++){
                    unsigned h4[4];
                    #pragma unroll
                    for (int e = 0; e < 4; e++){
                        int c = 40 + q*8 + e*2;
                        h4[e] = packh(FCOLV(c), FCOLV(c+1));
                    }
                    dh[q] = make_uint4(h4[0],h4[1],h4[2],h4[3]);
                }
            }
        }
        __syncthreads();

        float acc[12][4];
        #pragma unroll
        for (int f = 0; f < 12; f++)
            #pragma unroll
            for (int e = 0; e < 4; e++) acc[f][e] = 0.f;

        #pragma unroll
        for (int k = 0; k < 5; k++){
            unsigned a0[4], a1[4];
            unsigned aaddr0 = sF + (unsigned)(((R0      + l16)*88 + k*16 + lhi8) * 2);
            unsigned aaddr1 = sF + (unsigned)(((R0 + 16 + l16)*88 + k*16 + lhi8) * 2);
            ldsm_x4(aaddr0, a0[0], a0[1], a0[2], a0[3]);
            ldsm_x4(aaddr1, a1[0], a1[1], a1[2], a1[3]);
            #pragma unroll
            for (int g = 0; g < 3; g++){
                unsigned bq[4];
                unsigned baddr = sW + (unsigned)(((CB + g*16 + l16)*88 + k*16 + lhi8) * 2);
                ldsm_x4(baddr, bq[0], bq[1], bq[2], bq[3]);
                mma16816(acc[g*2],         a0, bq[0], bq[2]);
                mma16816(acc[g*2 + 1],     a0, bq[1], bq[3]);
                mma16816(acc[6 + g*2],     a1, bq[0], bq[2]);
                mma16816(acc[6 + g*2 + 1], a1, bq[1], bq[3]);
            }
        }

        float s00 = 0.f, s01 = 0.f, s10 = 0.f, s11 = 0.f;
        #pragma unroll
        for (int g = 0; g < 3; g++)
            #pragma unroll
            for (int h = 0; h < 2; h++){
                float4 c = *(const float4*)&scw[CB + g*16 + h*8 + c0];
                int f = g*2 + h;
                s00 += c.y * fmaxf(acc[f][0] + c.x, 0.f)
                     + c.w * fmaxf(acc[f][1] + c.z, 0.f);
                s01 += c.y * fmaxf(acc[f][2] + c.x, 0.f)
                     + c.w * fmaxf(acc[f][3] + c.z, 0.f);
                s10 += c.y * fmaxf(acc[6+f][0] + c.x, 0.f)
                     + c.w * fmaxf(acc[6+f][1] + c.z, 0.f);
                s11 += c.y * fmaxf(acc[6+f][2] + c.x, 0.f)
                     + c.w * fmaxf(acc[6+f][3] + c.z, 0.f);
            }
        s00 += __shfl_xor_sync(0xffffffffu, s00, 1);
        s00 += __shfl_xor_sync(0xffffffffu, s00, 2);
        s01 += __shfl_xor_sync(0xffffffffu, s01, 1);
        s01 += __shfl_xor_sync(0xffffffffu, s01, 2);
        s10 += __shfl_xor_sync(0xffffffffu, s10, 1);
        s10 += __shfl_xor_sync(0xffffffffu, s10, 2);
        s11 += __shfl_xor_sync(0xffffffffu, s11, 1);
        s11 += __shfl_xor_sync(0xffffffffu, s11, 2);
        if ((lane & 3) == 0){
            int row = lane >> 2;
            int base = (wid >> 2)*512 + chunk*128 + R0;
            slog[base + row]          = s00;
            slog[base + 8 + row]      = s01;
            slog[base + 16 + row]     = s10;
            slog[base + 24 + row]     = s11;
        }
        __syncthreads();
    }

    int t0 = tid, t1 = tid + 256;
    float lt0 = slog[t0] + slog[512 + t0] + sb2[0]
              + (1.f - mask[b*Ss + t0]) * (-3.402823466e38f);
    float lt1 = slog[t1] + slog[512 + t1] + sb2[0]
              + (1.f - mask[b*Ss + t1]) * (-3.402823466e38f);

    float mx = fmaxf(lt0, lt1);
    #pragma unroll
    for (int d = 16; d > 0; d >>= 1)
        mx = fmaxf(mx, __shfl_xor_sync(0xffffffffu, mx, d));
    if (lane == 0) sred[wid] = mx;
    __syncthreads();
    float bmax = sred[0];
    #pragma unroll
    for (int i = 1; i < 8; i++) bmax = fmaxf(bmax, sred[i]);

    float e0 = expf(lt0 - bmax);
    float e1 = expf(lt1 - bmax);
    float sm = e0 + e1;
    #pragma unroll
    for (int d = 16; d > 0; d >>= 1)
        sm += __shfl_xor_sync(0xffffffffu, sm, d);
    __syncthreads();
    if (lane == 0) sred[wid] = sm;
    __syncthreads();
    float tot = 0.f;
    #pragma unroll
    for (int i = 0; i < 8; i++) tot += sred[i];
    float inv = 1.f / tot;

    g_pb[(long)r*Ss + t0] = __float2half(e0 * inv);
    g_pb[(long)r*Ss + t1] = __float2half(e1 * inv);
}

// ============================================================
// K3a: fp32 -> fp16 single (vectorized)
// ============================================================
__global__ __launch_bounds__(256) void conv_single_h(
    const float* __restrict__ x, __half* __restrict__ o, int n4)
{
    int i = blockIdx.x*256 + threadIdx.x;
    if (i >= n4) return;
    float4 v = ((const float4*)x)[i];
    store4h(&o[(long)i*4], v.x, v.y, v.z, v.w);
}
// K3b: fp32 -> fp16 hi/lo split
__global__ __launch_bounds__(256) void conv_split_h(
    const float* __restrict__ x, __half* __restrict__ hi,
    __half* __restrict__ lo, int n4)
{
    int i = blockIdx.x*256 + threadIdx.x;
    if (i >= n4) return;
    float4 v = ((const float4*)x)[i];
    __half h0,h1,h2,h3,l0,l1,l2,l3;
    hsplit(v.x,h0,l0); hsplit(v.y,h1,l1); hsplit(v.z,h2,l2); hsplit(v.w,h3,l3);
    ((__half2*)hi)[2*i]   = __halves2half2(h0,h1);
    ((__half2*)hi)[2*i+1] = __halves2half2(h2,h3);
    ((__half2*)lo)[2*i]   = __halves2half2(l0,l1);
    ((__half2*)lo)[2*i+1] = __halves2half2(l2,l3);
}

// ============================================================
// K4: fused ctx split-K reduce + msg_in build (fp16 single)
// ============================================================
__global__ __launch_bounds__(256) void ctx_msgin_fused(
    const float* __restrict__ p, const float* __restrict__ Hj)
{
    long i4 = ((long)blockIdx.x * 256 + threadIdx.x) * 4;
    if (i4 >= (long)NROWS*Hh) return;
    long stride = 4L*Ss*Hh;
    float4 s = *(const float4*)&p[i4];
    #pragma unroll
    for (int n = 1; n < 4; n++){
        float4 v = *(const float4*)&p[n*stride + i4];
        s.x += v.x; s.y += v.y; s.z += v.z; s.w += v.w;
    }
    int r = (int)(i4 / Hh);
    int c = (int)(i4 % Hh);
    float4 hv = *(const float4*)&Hj[i4];
    long base = (long)r*H3 + c;
    store4h(&g_m1[base],      s.x, s.y, s.z, s.w);
    store4h(&g_m1[base+Hh],   hv.x, hv.y, hv.z, hv.w);
    store4h(&g_m1[base+2*Hh], s.x*hv.x, s.y*hv.y, s.z*hv.z, s.w*hv.w);
}

// ============================================================
// K5: WMMA fp16 GEMM, split-K, cp.async double-buffered.
//  A single fp16; B single (BHL=0) or hi/lo (BHL=1).
// ============================================================
#define HLSZ 10240
#define GEMM_SMEM_1 40960
#define GEMM_SMEM_2 61440

template<bool TRANSB, int KSPLIT, int BHL>
__global__ __launch_bounds__(256) void gemm_wmma(
    const __half* __restrict__ Aop,
    const __half* __restrict__ Bh, const __half* __restrict__ Bl,
    float* __restrict__ Cpart, int N, int K, int ldA, int ldB,
    long strideA, long strideB, long strideC, long partStride)
{
    extern __shared__ char gsm[];
    unsigned sbase = smem_cast(gsm);

    int tid = threadIdx.x;
    int wid = tid >> 5;
    int wr = wid & 3, wc = wid >> 2;
    long row0 = (long)blockIdx.y * 128;
    long col0 = (long)blockIdx.x * 128;

    int zb = blockIdx.z / KSPLIT, zk = blockIdx.z % KSPLIT;
    int kcnt = K / KSPLIT, k0 = zk * kcnt;

    const __half* AP  = Aop + (long)zb * strideA;
    const __half* BPh = Bh  + (long)zb * strideB;
    const __half* BPl = BHL ? (Bl + (long)zb * strideB) : nullptr;
    float* Cb = Cpart + (long)zk * partStride + (long)zb * strideC;

    int a_r = tid >> 2, a_seg = tid & 3;
    int bn_r = tid >> 4, bn_seg = tid & 15;

    wmma::fragment<wmma::accumulator,16,16,16,float> acc[2][4];
    #pragma unroll
    for (int i = 0; i < 2; i++)
        #pragma unroll
        for (int j = 0; j < 4; j++) wmma::fill_fragment(acc[i][j], 0.f);

    int nch = kcnt >> 5;

    #define STAGE_CHUNK(bi, kc) do {                                         \
        unsigned abase = sbase + (bi)*HLSZ;                                  \
        _Pragma("unroll")                                                    \
        for (int t = 0; t < 2; t++){                                         \
            int rr = a_r + t*64;                                             \
            long off = (row0 + rr)*(long)ldA + (kc) + a_seg*8;               \
            cpasync16(abase + (unsigned)((rr*40 + a_seg*8)*2), AP + off);    \
        }                                                                    \
        unsigned bbase = sbase + 2*HLSZ + (bi)*(1+BHL)*HLSZ;                 \
        if (TRANSB){                                                         \
            _Pragma("unroll")                                                \
            for (int t = 0; t < 2; t++){                                     \
                int rr = a_r + t*64;                                         \
                long off = (col0 + rr)*(long)ldB + (kc) + a_seg*8;           \
                unsigned d = bbase + (unsigned)((rr*40 + a_seg*8)*2);        \
                cpasync16(d, BPh + off);                                     \
                if (BHL) cpasync16(d + HLSZ, BPl + off);                     \
            }                                                                \
        } else {                                                             \
            _Pragma("unroll")                                                \
            for (int t = 0; t < 2; t++){                                     \
                int rr = bn_r + t*16;                                        \
                long off = (long)((kc) + rr)*ldB + col0 + bn_seg*8;          \
                unsigned d = bbase + (unsigned)((rr*136 + bn_seg*8)*2);      \
                cpasync16(d, BPh + off);                                     \
                if (BHL) cpasync16(d + HLSZ, BPl + off);                     \
            }                                                                \
        }                                                                    \
        CP_COMMIT();                                                         \
    } while(0)

    STAGE_CHUNK(0, k0);

    #pragma unroll 1
    for (int s = 0; s < nch; s++){
        int cur = s & 1;
        if (s + 1 < nch){
            STAGE_CHUNK(cur ^ 1, k0 + (s+1)*32);
            CP_WAIT1();
        } else {
            CP_WAIT0();
        }
        __syncthreads();

        const __half* Asb = (const __half*)(gsm + cur*HLSZ);
        const __half* Bsb = (const __half*)(gsm + 2*HLSZ + cur*(1+BHL)*HLSZ);
        const __half* Blb = Bsb + 5120;

        #pragma unroll
        for (int ks = 0; ks < 2; ks++){
            wmma::fragment<wmma::matrix_a,16,16,16,__half,wmma::row_major> af[2];
            #pragma unroll
            for (int i = 0; i < 2; i++)
                wmma::load_matrix_sync(af[i], Asb + (wr*32 + i*16)*40 + ks*16, 40);
            if (TRANSB){
                #pragma unroll
                for (int j = 0; j < 4; j++){
                    wmma::fragment<wmma::matrix_b,16,16,16,__half,wmma::col_major> bfh, bfl;
                    int nb = wc*64 + j*16;
                    wmma::load_matrix_sync(bfh, Bsb + nb*40 + ks*16, 40);
                    if (BHL) wmma::load_matrix_sync(bfl, Blb + nb*40 + ks*16, 40);
                    #pragma unroll
                    for (int i = 0; i < 2; i++){
                        wmma::mma_sync(acc[i][j], af[i], bfh, acc[i][j]);
                        if (BHL) wmma::mma_sync(acc[i][j], af[i], bfl, acc[i][j]);
                    }
                }
            } else {
                #pragma unroll
                for (int j = 0; j < 4; j++){
                    wmma::fragment<wmma::matrix_b,16,16,16,__half,wmma::row_major> bfh, bfl;
                    int nb = wc*64 + j*16;
                    wmma::load_matrix_sync(bfh, Bsb + (ks*16)*136 + nb, 136);
                    if (BHL) wmma::load_matrix_sync(bfl, Blb + (ks*16)*136 + nb, 136);
                    #pragma unroll
                    for (int i = 0; i < 2; i++){
                        wmma::mma_sync(acc[i][j], af[i], bfh, acc[i][j]);
                        if (BHL) wmma::mma_sync(acc[i][j], af[i], bfl, acc[i][j]);
                    }
                }
            }
        }
        __syncthreads();
    }
    #undef STAGE_CHUNK

    #pragma unroll
    for (int i = 0; i < 2; i++)
        #pragma unroll
        for (int j = 0; j < 4; j++){
            float* cp = Cb + (row0 + wr*32 + i*16)*(long)N + col0 + wc*64 + j*16;
            wmma::store_matrix_sync(cp, acc[i][j], N, wmma::mem_row_major);
        }
}

// ============================================================
// K6: split-K reduce + epilogues
// ============================================================
template<int NS, int MODE>
__global__ __launch_bounds__(256) void reduce_ns(
    const float* __restrict__ p, long partStride,
    float* __restrict__ outf, __half* __restrict__ oh,
    const float* __restrict__ bias, const float* __restrict__ alpha_p,
    int N, long total)
{
    long i4 = ((long)blockIdx.x * 256 + threadIdx.x) * 4;
    if (i4 >= total) return;
    float4 s = *(const float4*)&p[i4];
    #pragma unroll
    for (int n = 1; n < NS; n++){
        float4 v = *(const float4*)&p[n*partStride + i4];
        s.x += v.x; s.y += v.y; s.z += v.z; s.w += v.w;
    }
    int col = (int)(i4 % N);
    float4 bi = *(const float4*)&bias[col];
    s.x += bi.x; s.y += bi.y; s.z += bi.z; s.w += bi.w;
    if (MODE == 1){
        s.x = fmaxf(s.x, 0.f); s.y = fmaxf(s.y, 0.f);
        s.z = fmaxf(s.z, 0.f); s.w = fmaxf(s.w, 0.f);
        store4h(&oh[i4], s.x, s.y, s.z, s.w);
    } else {
        float a = __ldg(alpha_p);
        s.x *= a; s.y *= a; s.z *= a; s.w *= a;
        *(float4*)&outf[i4] = s;
    }
}

// ============================================================
extern "C" void kernel_launch(void* const* d_in, const int* in_sizes, int n_in,
                              void* d_out, int out_size)
{
    const float* Hj   = (const float*)d_in[0];
    const float* Hi   = (const float*)d_in[1];
    const float* mask = (const float*)d_in[2];
    const float* pjw  = (const float*)d_in[3];
    const float* piw  = (const float*)d_in[4];
    const float* sw1  = (const float*)d_in[5];
    const float* sb1  = (const float*)d_in[6];
    const float* sw2  = (const float*)d_in[7];
    const float* sb2  = (const float*)d_in[8];
    const float* vw1  = (const float*)d_in[9];
    const float* vb1  = (const float*)d_in[10];
    const float* vw2  = (const float*)d_in[11];
    const float* vb2  = (const float*)d_in[12];
    const float* alpha= (const float*)d_in[13];
    float* out = (float*)d_out;

    void *ppb, *phi, *pm1, *pw1, *phd, *pw2h, *pw2l;
    void *ppc, *pp1, *pp2;
    cudaGetSymbolAddress(&ppb,  g_pb);
    cudaGetSymbolAddress(&phi,  g_hi);
    cudaGetSymbolAddress(&pm1,  g_m1);
    cudaGetSymbolAddress(&pw1,  g_w1);
    cudaGetSymbolAddress(&phd,  g_hid);
    cudaGetSymbolAddress(&pw2h, g_w2h);  cudaGetSymbolAddress(&pw2l, g_w2l);
    cudaGetSymbolAddress(&ppc, g_partc);
    cudaGetSymbolAddress(&pp1, g_part1);
    cudaGetSymbolAddress(&pp2, g_part2);

    cudaFuncSetAttribute(pair_wmma, cudaFuncAttributeMaxDynamicSharedMemorySize, PAIR_SMEM);
    cudaFuncSetAttribute(proj_kernel, cudaFuncAttributeMaxDynamicSharedMemorySize, PROJ_SMEM);
    cudaFuncSetAttribute(gemm_wmma<false,4,0>, cudaFuncAttributeMaxDynamicSharedMemorySize, GEMM_SMEM_1);
    cudaFuncSetAttribute(gemm_wmma<true,3,0>,  cudaFuncAttributeMaxDynamicSharedMemorySize, GEMM_SMEM_1);
    cudaFuncSetAttribute(gemm_wmma<true,3,1>,  cudaFuncAttributeMaxDynamicSharedMemorySize, GEMM_SMEM_2);

    // 0: proj (8 rows/CTA; emits g_hi fp16)
    proj_kernel<<<NROWS/PROJ_ROWS, 256, PROJ_SMEM>>>(Hj, Hi, pjw, piw, sw1);
    // 1: W' precompute
    wsplit_pair<<<(96*88 + 255)/256, 256>>>(sw1);
    // 2: vw1 -> fp16 single
    conv_single_h<<<(OH*H3/4 + 255)/256, 256>>>(vw1, (__half*)pw1, OH*H3/4);
    // 3: pair
    pair_wmma<<<NROWS, 256, PAIR_SMEM>>>(sb1, sw2, sb2, mask);
    // 4: ctx partials = probs @ Hi  [NN, batched, split-K=4, 1-pass]
    {
        dim3 g(Hh/128, Ss/128, Bb*4);
        gemm_wmma<false,4,0><<<g, 256, GEMM_SMEM_1>>>(
            (const __half*)ppb,
            (const __half*)phi, nullptr,
            (float*)ppc, Hh, Ss, Ss, Hh,
            (long)Ss*Ss, (long)Ss*Hh, (long)Ss*Hh, 4L*Ss*Hh);
    }
    // 5: fused ctx reduce + msg_in build
    {
        long total = (long)NROWS*Hh;
        ctx_msgin_fused<<<(int)((total/4 + 255)/256), 256>>>(
            (const float*)ppc, Hj);
    }
    // 6: vw2 -> fp16 hi/lo
    conv_split_h<<<(Hh*OH/4 + 255)/256, 256>>>(vw2, (__half*)pw2h,
                                               (__half*)pw2l, Hh*OH/4);
    // 7: gemm1 partials  [NT, split-K=3, 1-pass]
    {
        dim3 g(OH/128, NROWS/128, 3);
        gemm_wmma<true,3,0><<<g, 256, GEMM_SMEM_1>>>(
            (const __half*)pm1,
            (const __half*)pw1, nullptr,
            (float*)pp1, OH, H3, H3, H3,
            0, 0, 0, (long)NROWS*OH);
    }
    // 8: hid reduce (bias+relu -> fp16 single)
    {
        long total = (long)NROWS*OH;
        reduce_ns<3,1><<<(int)((total/4 + 255)/256), 256>>>(
            (const float*)pp1, (long)NROWS*OH, nullptr,
            (__half*)phd, vb1, nullptr, OH, total);
    }
    // 9: gemm2 partials  [NT, split-K=3, 2-pass]
    {
        dim3 g(Hh/128, NROWS/128, 3);
        gemm_wmma<true,3,1><<<g, 256, GEMM_SMEM_2>>>(
            (const __half*)phd,
            (const __half*)pw2h, (const __half*)pw2l,
            (float*)pp2, Hh, OH, OH, OH,
            0, 0, 0, (long)NROWS*Hh);
    }
    // 10: out reduce (bias, alpha)
    {
        long total = (long)NROWS*Hh;
        reduce_ns<3,2><<<(int)((total/4 + 255)/256), 256>>>(
            (const float*)pp2, (long)NROWS*Hh, out,
            nullptr, vb2, alpha, Hh, total);
    }
    (void)in_sizes; (void)n_in; (void)out_size;
}